// round 9
// baseline (speedup 1.0000x reference)
#include <cuda_runtime.h>

#define Dm 128
#define Hm 256
#define ROWS 16384   /* 16 * 1024 chunks */
#define NTOK 131072  /* 16 * 8192 tokens */
#define EPSf 1e-5f

typedef unsigned long long u64;
typedef unsigned int u32;

// ---- scratch (device globals; no allocation) ----
__device__ float g_local[NTOK * Dm];   // 64 MB
__device__ float g_hA[ROWS * Dm];      // 8 MB
__device__ float g_hB[ROWS * Dm];      // 8 MB
__device__ float g_bcb[ROWS * Dm];     // 8 MB
// packed tf32 weight fragments
__device__ float2 g_w1p[16 * 32 * 32]; // lw1 128x256
__device__ float2 g_w2p[32 * 16 * 32]; // lw2 256x128
__device__ float2 g_hwp[16 * 32 * 32]; // head_w 128x256
// 128x128 mats: [0]=w1self [1]=w1nbr [2]=mw2 [3]=uw1a [4]=uw1b [5]=uw2 [6]=bc_w
__device__ float2 g_mwp[7 * 8192];

// ---- packed f32x2 helpers (scalar path) ----
__device__ __forceinline__ u64 pk2(float x, float y) {
    u64 r; asm("mov.b64 %0, {%1, %2};" : "=l"(r) : "f"(x), "f"(y)); return r;
}
__device__ __forceinline__ u64 dup_f(float a) {
    u64 r; asm("mov.b64 %0, {%1, %1};" : "=l"(r) : "f"(a)); return r;
}
__device__ __forceinline__ void fma2(u64& d, u64 a, u64 b) {
    asm("fma.rn.f32x2 %0, %1, %2, %0;" : "+l"(d) : "l"(a), "l"(b));
}
__device__ __forceinline__ float2 u2f(u64 v) {
    float2 r; asm("mov.b64 {%0, %1}, %2;" : "=f"(r.x), "=f"(r.y) : "l"(v)); return r;
}

// ---- tf32 helpers ----
__device__ __forceinline__ u32 f2tf(float f) {
    u32 r; asm("cvt.rna.tf32.f32 %0, %1;" : "=r"(r) : "f"(f)); return r;
}
__device__ __forceinline__ float f2tff(float f) { return __uint_as_float(f2tf(f)); }

// mma.sync m16n8k8 tf32
__device__ __forceinline__ void mma8(float4& c, const u32 a[4], u32 b0, u32 b1) {
    asm volatile(
        "mma.sync.aligned.m16n8k8.row.col.f32.tf32.tf32.f32 "
        "{%0,%1,%2,%3}, {%4,%5,%6,%7}, {%8,%9}, {%0,%1,%2,%3};"
        : "+f"(c.x), "+f"(c.y), "+f"(c.z), "+f"(c.w)
        : "r"(a[0]), "r"(a[1]), "r"(a[2]), "r"(a[3]), "r"(b0), "r"(b1));
}

template<int STRIDE>
__device__ __forceinline__ void ldA_raw(const float* ap, u32 a[4]) {
    a[0] = __float_as_uint(ap[0]);
    a[1] = __float_as_uint(ap[8 * STRIDE]);
    a[2] = __float_as_uint(ap[4]);
    a[3] = __float_as_uint(ap[8 * STRIDE + 4]);
}

__device__ __forceinline__ float wsum(float v) {
#pragma unroll
    for (int o = 16; o; o >>= 1) v += __shfl_xor_sync(0xffffffffu, v, o);
    return v;
}
__device__ __forceinline__ float gelu_f(float x) {
    return 0.5f * x * (1.0f + erff(x * 0.70710678118f));
}

__device__ __forceinline__ float4 ln_f4(float4 h, const float* __restrict__ g,
                                        const float* __restrict__ b, int lane) {
    const float mu = wsum(h.x + h.y + h.z + h.w) * (1.0f / 128.0f);
    const float a0 = h.x - mu, a1 = h.y - mu, a2 = h.z - mu, a3 = h.w - mu;
    const float var = wsum(a0 * a0 + a1 * a1 + a2 * a2 + a3 * a3) * (1.0f / 128.0f);
    const float rs = rsqrtf(var + EPSf);
    const int dd = lane * 4;
    const float4 gg = *(const float4*)(g + dd);
    const float4 bb = *(const float4*)(b + dd);
    return make_float4(a0 * rs * gg.x + bb.x, a1 * rs * gg.y + bb.y,
                       a2 * rs * gg.z + bb.z, a3 * rs * gg.w + bb.w);
}

// ---- scalar register-tiled GEMM accumulate (pool only) ----
template<int KDIM, int RPT, int NCP>
__device__ __forceinline__ void mm_acc(const float* __restrict__ s,
                                       const float* __restrict__ W, const int ldw,
                                       u64 acc[RPT][NCP]) {
#pragma unroll 2
    for (int d = 0; d < KDIM; d += 2) {
        u64 w0[NCP], w1[NCP];
        if constexpr (NCP >= 2) {
#pragma unroll
            for (int c = 0; c < NCP; c += 2) {
                const ulonglong2 t0 = *(const ulonglong2*)(W + d * ldw + c * 2);
                const ulonglong2 t1 = *(const ulonglong2*)(W + (d + 1) * ldw + c * 2);
                w0[c] = t0.x; w0[c + 1] = t0.y;
                w1[c] = t1.x; w1[c + 1] = t1.y;
            }
        } else {
            w0[0] = *(const u64*)(W + d * ldw);
            w1[0] = *(const u64*)(W + (d + 1) * ldw);
        }
#pragma unroll
        for (int r = 0; r < RPT; ++r) {
            const float2 a = *(const float2*)(s + r * KDIM + d);
            const u64 a0 = dup_f(a.x), a1 = dup_f(a.y);
#pragma unroll
            for (int c = 0; c < NCP; ++c) {
                fma2(acc[r][c], a0, w0[c]);
                fma2(acc[r][c], a1, w1[c]);
            }
        }
    }
}

// ============================================================
// K0: fused pack of all weights into tf32 B-fragment order
// ============================================================
__device__ __forceinline__ void pack_one(const float* __restrict__ W,
                                         float2* __restrict__ P,
                                         int N, int idx) {
    const int lane = idx & 31;
    const int t = idx >> 5;
    const int nt = t % (N / 8);
    const int ks = t / (N / 8);
    const int k = ks * 8 + (lane & 3);
    const int n = nt * 8 + (lane >> 2);
    P[idx] = make_float2(f2tff(W[k * N + n]), f2tff(W[(k + 4) * N + n]));
}

__global__ __launch_bounds__(256) void k_pack_all(
    const float* __restrict__ lw1, const float* __restrict__ lw2,
    const float* __restrict__ hw,  const float* __restrict__ mw1,
    const float* __restrict__ mw2, const float* __restrict__ uw1,
    const float* __restrict__ uw2, const float* __restrict__ bcw)
{
    const int b = blockIdx.x, tid = threadIdx.x;
    if      (b < 64)  pack_one(lw1, g_w1p, 256, b * 256 + tid);
    else if (b < 128) pack_one(lw2, g_w2p, 128, (b - 64) * 256 + tid);
    else if (b < 192) pack_one(hw,  g_hwp, 256, (b - 128) * 256 + tid);
    else if (b < 224) pack_one(mw1,           g_mwp + 0 * 8192, 128, (b - 192) * 256 + tid);
    else if (b < 256) pack_one(mw1 + 16384,   g_mwp + 1 * 8192, 128, (b - 224) * 256 + tid);
    else if (b < 288) pack_one(mw2,           g_mwp + 2 * 8192, 128, (b - 256) * 256 + tid);
    else if (b < 320) pack_one(uw1,           g_mwp + 3 * 8192, 128, (b - 288) * 256 + tid);
    else if (b < 352) pack_one(uw1 + 16384,   g_mwp + 4 * 8192, 128, (b - 320) * 256 + tid);
    else if (b < 384) pack_one(uw2,           g_mwp + 5 * 8192, 128, (b - 352) * 256 + tid);
    else              pack_one(bcw,           g_mwp + 6 * 8192, 128, (b - 384) * 256 + tid);
}

// ============================================================
// K1: local = h + MLP2(LN(h)) + fused pool/summ (tensor-core)
// 64 tokens (=8 chunks)/block, 256 threads, ~98KB dyn smem
// ============================================================
#define SXL 132
#define SHL 260
__global__ __launch_bounds__(256, 2) void k_local(
    const int* __restrict__ x, const float* __restrict__ emb, const float* __restrict__ pos,
    const float* __restrict__ lb1, const float* __restrict__ lb2,
    const float* __restrict__ lng, const float* __restrict__ lnb,
    const float* __restrict__ pw, const float* __restrict__ pb)
{
    extern __shared__ float sm[];
    float* s_x = sm;                // 64 x 132
    float* s_h = sm + 64 * SXL;     // 64 x 260
    const int tid = threadIdx.x, wid = tid >> 5, lane = tid & 31;
    const int gt0 = blockIdx.x * 64;
    const int frow = lane >> 2, fcol = lane & 3;

    // phase 1: LN per token -> tf32 in s_x
#pragma unroll
    for (int tt = 0; tt < 8; ++tt) {
        const int tl = wid * 8 + tt, gt = gt0 + tl;
        const int xt = __ldg(x + gt);
        const float4 e = *(const float4*)(emb + xt * Dm + lane * 4);
        const float4 p = *(const float4*)(pos + (gt & 7) * Dm + lane * 4);
        const float4 h = make_float4(e.x + p.x, e.y + p.y, e.z + p.z, e.w + p.w);
        const float4 v = ln_f4(h, lng, lnb, lane);
        float* dst = s_x + tl * SXL + lane * 4;
        dst[0] = f2tff(v.x); dst[1] = f2tff(v.y); dst[2] = f2tff(v.z); dst[3] = f2tff(v.w);
    }
    __syncthreads();

    const int mg = (wid >> 2) * 32;   // 2 m-groups of 32 rows
    const int ng = (wid & 3);         // 4 n-groups

    // phase 2: hid = gelu(xln @ lw1 + b1) -> tf32 in s_h (cols ng*64..+63)
    {
        float4 acc[2][8];
#pragma unroll
        for (int nt = 0; nt < 8; ++nt) {
            const int gc = ng * 64 + nt * 8 + 2 * fcol;
            const float b0 = lb1[gc], b1v = lb1[gc + 1];
#pragma unroll
            for (int mt = 0; mt < 2; ++mt) acc[mt][nt] = make_float4(b0, b1v, b0, b1v);
        }
#pragma unroll 4
        for (int ks = 0; ks < 16; ++ks) {
            u32 a[2][4];
#pragma unroll
            for (int mt = 0; mt < 2; ++mt)
                ldA_raw<SXL>(s_x + (mg + mt * 16 + frow) * SXL + ks * 8 + fcol, a[mt]);
#pragma unroll
            for (int nt = 0; nt < 8; ++nt) {
                const float2 b = g_w1p[(ks * 32 + ng * 8 + nt) * 32 + lane];
#pragma unroll
                for (int mt = 0; mt < 2; ++mt)
                    mma8(acc[mt][nt], a[mt], __float_as_uint(b.x), __float_as_uint(b.y));
            }
        }
#pragma unroll
        for (int mt = 0; mt < 2; ++mt) {
            const int rg = mg + mt * 16 + frow;
#pragma unroll
            for (int nt = 0; nt < 8; ++nt) {
                const int gc = ng * 64 + nt * 8 + 2 * fcol;
                *(float2*)(s_h + rg * SHL + gc) =
                    make_float2(f2tff(gelu_f(acc[mt][nt].x)), f2tff(gelu_f(acc[mt][nt].y)));
                *(float2*)(s_h + (rg + 8) * SHL + gc) =
                    make_float2(f2tff(gelu_f(acc[mt][nt].z)), f2tff(gelu_f(acc[mt][nt].w)));
            }
        }
    }
    __syncthreads();

    // phase 3: local = h + hid @ lw2 + b2 -> g_local and s_x (fp32)
    {
        float4 acc[2][4];
#pragma unroll
        for (int nt = 0; nt < 4; ++nt) {
            const int gc = ng * 32 + nt * 8 + 2 * fcol;
            const float b0 = lb2[gc], b1v = lb2[gc + 1];
#pragma unroll
            for (int mt = 0; mt < 2; ++mt) acc[mt][nt] = make_float4(b0, b1v, b0, b1v);
        }
#pragma unroll 4
        for (int ks = 0; ks < 32; ++ks) {
            u32 a[2][4];
#pragma unroll
            for (int mt = 0; mt < 2; ++mt)
                ldA_raw<SHL>(s_h + (mg + mt * 16 + frow) * SHL + ks * 8 + fcol, a[mt]);
#pragma unroll
            for (int nt = 0; nt < 4; ++nt) {
                const float2 b = g_w2p[(ks * 16 + ng * 4 + nt) * 32 + lane];
#pragma unroll
                for (int mt = 0; mt < 2; ++mt)
                    mma8(acc[mt][nt], a[mt], __float_as_uint(b.x), __float_as_uint(b.y));
            }
        }
#pragma unroll
        for (int mt = 0; mt < 2; ++mt) {
#pragma unroll
            for (int rr = 0; rr < 2; ++rr) {
                const int tl = mg + mt * 16 + frow + rr * 8;
                const int gt = gt0 + tl;
                const int xt = __ldg(x + gt);
#pragma unroll
                for (int nt = 0; nt < 4; ++nt) {
                    const int gc = ng * 32 + nt * 8 + 2 * fcol;
                    const float2 e = *(const float2*)(emb + xt * Dm + gc);
                    const float2 p = *(const float2*)(pos + (gt & 7) * Dm + gc);
                    const float cx = rr ? acc[mt][nt].z : acc[mt][nt].x;
                    const float cy = rr ? acc[mt][nt].w : acc[mt][nt].y;
                    const float2 o = make_float2(e.x + p.x + cx, e.y + p.y + cy);
                    *(float2*)(g_local + gt * Dm + gc) = o;
                    *(float2*)(s_x + tl * SXL + gc) = o;
                }
            }
        }
    }
    __syncthreads();

    // phase 4: chunk means (8 chunks) -> s_h[0:1024]
#pragma unroll
    for (int it = 0; it < 4; ++it) {
        const int idx = tid + it * 256;
        const int c = idx >> 7, dd = idx & 127;
        float s = 0.f;
#pragma unroll
        for (int t = 0; t < 8; ++t) s += s_x[(c * 8 + t) * SXL + dd];
        s_h[c * 128 + dd] = s * 0.125f;
    }
    __syncthreads();

    // phase 5: summ = mean @ pool_w + pool_b -> g_hA (warp per chunk)
    {
        const int j0 = lane * 4;
        u64 acc1[1][2];
        acc1[0][0] = pk2(pb[j0], pb[j0 + 1]);
        acc1[0][1] = pk2(pb[j0 + 2], pb[j0 + 3]);
        mm_acc<128, 1, 2>(s_h + wid * 128, pw + j0, 128, acc1);
        const float2 v0 = u2f(acc1[0][0]), v1 = u2f(acc1[0][1]);
        *(float4*)(g_hA + (blockIdx.x * 8 + wid) * Dm + j0) =
            make_float4(v0.x, v0.y, v1.x, v1.y);
    }
}

// ============================================================
// K2: FUSED proj + gelu-sum + agg + upd + LN (+ bc last round)
// 32 rows/block (+4 halo), grid 512, 128 threads, 84.5KB smem
// smem layout (floats, stride SXL):
//   s_hmt [0,6336)      : 48 rows tf32 hmsg, v = row-(r0-4)
//   s_pn  [6336,12672)  : 48 rows nbr-proj; rows 0..31 later = agg
//   s_ps  [12672,16896) : 32 rows self-proj; later uh
//   s_hs  [16896,21120) : 32 rows gelu-sum; later pre-LN fp32
// ============================================================
__global__ __launch_bounds__(128) void k_msgf(
    int useA, int last,
    const float* __restrict__ mb1, const float* __restrict__ mb2,
    const float* __restrict__ ub1, const float* __restrict__ ub2,
    const float* __restrict__ lg, const float* __restrict__ lb,
    const float* __restrict__ bcb)
{
    const float* __restrict__ hin = useA ? g_hA : g_hB;
    float* __restrict__ hout = useA ? g_hB : g_hA;
    extern __shared__ float sm[];
    float* s_hmt = sm;
    float* s_pn  = sm + 48 * SXL;
    float* s_ps  = sm + 96 * SXL;
    float* s_hs  = sm + 128 * SXL;
    float* s_ag  = s_pn;   // alias (pn dead after gelu-sum)
    float* s_uh  = s_ps;   // alias (ps dead after gelu-sum)
    float* s_pl  = s_hs;   // alias (hs dead after agg)
    const int tid = threadIdx.x, wid = tid >> 5, lane = tid & 31;
    const int r0 = blockIdx.x * 32;
    const int frow = lane >> 2, fcol = lane & 3;
    const int ng = wid;            // 4 n-groups of 32 cols

    // P0: load 48 halo rows of hmsg as tf32 (clamped)
#pragma unroll
    for (int it = 0; it < 48; ++it) {
        const int idx = tid + it * 128;
        const int v = idx >> 7, j = idx & 127;
        int row = r0 - 4 + v;
        row = row < 0 ? 0 : (row > ROWS - 1 ? ROWS - 1 : row);
        s_hmt[v * SXL + j] = f2tff(hin[row * Dm + j]);
    }
    __syncthreads();

    // P1: self-proj (2 m-tiles at v=4,20) and nbr-proj (3 m-tiles at v=0,16,32)
    {
        float4 accS[2][4], accN[3][4];
#pragma unroll
        for (int nt = 0; nt < 4; ++nt) {
#pragma unroll
            for (int mt = 0; mt < 2; ++mt) accS[mt][nt] = make_float4(0.f, 0.f, 0.f, 0.f);
#pragma unroll
            for (int mt = 0; mt < 3; ++mt) accN[mt][nt] = make_float4(0.f, 0.f, 0.f, 0.f);
        }
#pragma unroll 4
        for (int ks = 0; ks < 16; ++ks) {
            u32 aS[2][4], aN[3][4];
#pragma unroll
            for (int mt = 0; mt < 2; ++mt)
                ldA_raw<SXL>(s_hmt + (4 + mt * 16 + frow) * SXL + ks * 8 + fcol, aS[mt]);
#pragma unroll
            for (int mt = 0; mt < 3; ++mt)
                ldA_raw<SXL>(s_hmt + (mt * 16 + frow) * SXL + ks * 8 + fcol, aN[mt]);
#pragma unroll
            for (int nt = 0; nt < 4; ++nt) {
                const float2 bS = g_mwp[0 * 8192 + (ks * 16 + ng * 4 + nt) * 32 + lane];
                const float2 bN = g_mwp[1 * 8192 + (ks * 16 + ng * 4 + nt) * 32 + lane];
#pragma unroll
                for (int mt = 0; mt < 2; ++mt)
                    mma8(accS[mt][nt], aS[mt], __float_as_uint(bS.x), __float_as_uint(bS.y));
#pragma unroll
                for (int mt = 0; mt < 3; ++mt)
                    mma8(accN[mt][nt], aN[mt], __float_as_uint(bN.x), __float_as_uint(bN.y));
            }
        }
#pragma unroll
        for (int mt = 0; mt < 2; ++mt) {
            const int r = mt * 16 + frow;
#pragma unroll
            for (int nt = 0; nt < 4; ++nt) {
                const int gc = ng * 32 + nt * 8 + 2 * fcol;
                *(float2*)(s_ps + r * SXL + gc)       = make_float2(accS[mt][nt].x, accS[mt][nt].y);
                *(float2*)(s_ps + (r + 8) * SXL + gc) = make_float2(accS[mt][nt].z, accS[mt][nt].w);
            }
        }
#pragma unroll
        for (int mt = 0; mt < 3; ++mt) {
            const int v = mt * 16 + frow;
#pragma unroll
            for (int nt = 0; nt < 4; ++nt) {
                const int gc = ng * 32 + nt * 8 + 2 * fcol;
                *(float2*)(s_pn + v * SXL + gc)       = make_float2(accN[mt][nt].x, accN[mt][nt].y);
                *(float2*)(s_pn + (v + 8) * SXL + gc) = make_float2(accN[mt][nt].z, accN[mt][nt].w);
            }
        }
    }
    __syncthreads();

    // P2: gelu-sum -> s_hs (tf32).  hs[r][j] = sum_d gelu(ps[r][j]+pn[r+4-d][j]+b1)
#pragma unroll
    for (int it = 0; it < 32; ++it) {
        const int idx = tid + it * 128;
        const int r = idx >> 7, j = idx & 127;
        const int i = (r0 + r) & 1023;
        const float ps_b = s_ps[r * SXL + j] + mb1[j];
        float a = 0.f;
#pragma unroll
        for (int dd = 0; dd < 5; ++dd) {
            if (i >= dd) a += gelu_f(ps_b + s_pn[(r + 4 - dd) * SXL + j]);
        }
        s_hs[r * SXL + j] = f2tff(a);
    }
    __syncthreads();

    // P3: agg = (HS @ mw2)/count + b2 -> s_ag (tf32; alias s_pn rows 0..31)
    {
        float4 acc[2][4];
#pragma unroll
        for (int mt = 0; mt < 2; ++mt)
#pragma unroll
            for (int nt = 0; nt < 4; ++nt) acc[mt][nt] = make_float4(0.f, 0.f, 0.f, 0.f);
#pragma unroll 4
        for (int ks = 0; ks < 16; ++ks) {
            u32 a[2][4];
#pragma unroll
            for (int mt = 0; mt < 2; ++mt)
                ldA_raw<SXL>(s_hs + (mt * 16 + frow) * SXL + ks * 8 + fcol, a[mt]);
#pragma unroll
            for (int nt = 0; nt < 4; ++nt) {
                const float2 b = g_mwp[2 * 8192 + (ks * 16 + ng * 4 + nt) * 32 + lane];
#pragma unroll
                for (int mt = 0; mt < 2; ++mt)
                    mma8(acc[mt][nt], a[mt], __float_as_uint(b.x), __float_as_uint(b.y));
            }
        }
        __syncthreads();   // pn reads done (P2 had sync; this orders ag writes after P3 hs reads for aliasing safety of later phases)
#pragma unroll
        for (int mt = 0; mt < 2; ++mt) {
            const int rA = mt * 16 + frow;
            const int iA = (r0 + rA) & 1023, iB = (r0 + rA + 8) & 1023;
            const float invA = 1.0f / ((iA + 1) < 5 ? (float)(iA + 1) : 5.0f);
            const float invB = 1.0f / ((iB + 1) < 5 ? (float)(iB + 1) : 5.0f);
#pragma unroll
            for (int nt = 0; nt < 4; ++nt) {
                const int gc = ng * 32 + nt * 8 + 2 * fcol;
                const float b20 = mb2[gc], b21 = mb2[gc + 1];
                *(float2*)(s_ag + rA * SXL + gc) =
                    make_float2(f2tff(acc[mt][nt].x * invA + b20),
                                f2tff(acc[mt][nt].y * invA + b21));
                *(float2*)(s_ag + (rA + 8) * SXL + gc) =
                    make_float2(f2tff(acc[mt][nt].z * invB + b20),
                                f2tff(acc[mt][nt].w * invB + b21));
            }
        }
    }
    __syncthreads();

    // P4: uh = gelu(HMT @ uw1a + AG @ uw1b + ub1) -> s_uh (tf32; alias s_ps)
    {
        float4 acc[2][4];
#pragma unroll
        for (int nt = 0; nt < 4; ++nt) {
            const int gc = ng * 32 + nt * 8 + 2 * fcol;
            const float b0 = ub1[gc], b1v = ub1[gc + 1];
#pragma unroll
            for (int mt = 0; mt < 2; ++mt) acc[mt][nt] = make_float4(b0, b1v, b0, b1v);
        }
#pragma unroll 4
        for (int ks = 0; ks < 16; ++ks) {
            u32 a[2][4];
#pragma unroll
            for (int mt = 0; mt < 2; ++mt)
                ldA_raw<SXL>(s_hmt + (4 + mt * 16 + frow) * SXL + ks * 8 + fcol, a[mt]);
#pragma unroll
            for (int nt = 0; nt < 4; ++nt) {
                const float2 b = g_mwp[3 * 8192 + (ks * 16 + ng * 4 + nt) * 32 + lane];
#pragma unroll
                for (int mt = 0; mt < 2; ++mt)
                    mma8(acc[mt][nt], a[mt], __float_as_uint(b.x), __float_as_uint(b.y));
            }
        }
#pragma unroll 4
        for (int ks = 0; ks < 16; ++ks) {
            u32 a[2][4];
#pragma unroll
            for (int mt = 0; mt < 2; ++mt)
                ldA_raw<SXL>(s_ag + (mt * 16 + frow) * SXL + ks * 8 + fcol, a[mt]);
#pragma unroll
            for (int nt = 0; nt < 4; ++nt) {
                const float2 b = g_mwp[4 * 8192 + (ks * 16 + ng * 4 + nt) * 32 + lane];
#pragma unroll
                for (int mt = 0; mt < 2; ++mt)
                    mma8(acc[mt][nt], a[mt], __float_as_uint(b.x), __float_as_uint(b.y));
            }
        }
        __syncthreads();   // s_ps reads in P2 long done; order uh writes after everyone passed P3
#pragma unroll
        for (int mt = 0; mt < 2; ++mt) {
            const int rA = mt * 16 + frow;
#pragma unroll
            for (int nt = 0; nt < 4; ++nt) {
                const int gc = ng * 32 + nt * 8 + 2 * fcol;
                *(float2*)(s_uh + rA * SXL + gc) =
                    make_float2(f2tff(gelu_f(acc[mt][nt].x)), f2tff(gelu_f(acc[mt][nt].y)));
                *(float2*)(s_uh + (rA + 8) * SXL + gc) =
                    make_float2(f2tff(gelu_f(acc[mt][nt].z)), f2tff(gelu_f(acc[mt][nt].w)));
            }
        }
    }
    __syncthreads();

    // P5: pre-LN = hmsg + UH @ uw2 + ub2 -> s_pl (fp32; alias s_hs)
    {
        float4 acc[2][4];
#pragma unroll
        for (int nt = 0; nt < 4; ++nt) {
            const int gc = ng * 32 + nt * 8 + 2 * fcol;
            const float b0 = ub2[gc], b1v = ub2[gc + 1];
#pragma unroll
            for (int mt = 0; mt < 2; ++mt) acc[mt][nt] = make_float4(b0, b1v, b0, b1v);
        }
#pragma unroll 4
        for (int ks = 0; ks < 16; ++ks) {
            u32 a[2][4];
#pragma unroll
            for (int mt = 0; mt < 2; ++mt)
                ldA_raw<SXL>(s_uh + (mt * 16 + frow) * SXL + ks * 8 + fcol, a[mt]);
#pragma unroll
            for (int nt = 0; nt < 4; ++nt) {
                const float2 b = g_mwp[5 * 8192 + (ks * 16 + ng * 4 + nt) * 32 + lane];
#pragma unroll
                for (int mt = 0; mt < 2; ++mt)
                    mma8(acc[mt][nt], a[mt], __float_as_uint(b.x), __float_as_uint(b.y));
            }
        }
        __syncthreads();
#pragma unroll
        for (int mt = 0; mt < 2; ++mt) {
            const int rA = mt * 16 + frow;
#pragma unroll
            for (int nt = 0; nt < 4; ++nt) {
                const int gc = ng * 32 + nt * 8 + 2 * fcol;
                const float2 h0 = *(const float2*)(s_hmt + (4 + rA) * SXL + gc);
                const float2 h1 = *(const float2*)(s_hmt + (12 + rA) * SXL + gc);
                *(float2*)(s_pl + rA * SXL + gc) =
                    make_float2(h0.x + acc[mt][nt].x, h0.y + acc[mt][nt].y);
                *(float2*)(s_pl + (rA + 8) * SXL + gc) =
                    make_float2(h1.x + acc[mt][nt].z, h1.y + acc[mt][nt].w);
            }
        }
    }
    __syncthreads();

    // P6: LN per row (8 rows/warp). Non-final: -> hout. Final: tf32 -> s_hmt[4+r]
#pragma unroll
    for (int rr = 0; rr < 8; ++rr) {
        const int r = wid * 8 + rr;
        const float4 v0 = *(const float4*)(s_pl + r * SXL + lane * 4);
        const float4 v = ln_f4(v0, lg, lb, lane);
        if (!last) {
            *(float4*)(hout + (r0 + r) * Dm + lane * 4) = v;
        } else {
            float* dst = s_hmt + (4 + r) * SXL + lane * 4;
            dst[0] = f2tff(v.x); dst[1] = f2tff(v.y);
            dst[2] = f2tff(v.z); dst[3] = f2tff(v.w);
        }
    }

    // P7 (final round only): bc = hmsg_final @ bc_w + bc_b -> g_bcb
    if (last) {
        __syncthreads();
        float4 acc[2][4];
#pragma unroll
        for (int nt = 0; nt < 4; ++nt) {
            const int gc = ng * 32 + nt * 8 + 2 * fcol;
            const float b0 = bcb[gc], b1v = bcb[gc + 1];
#pragma unroll
            for (int mt = 0; mt < 2; ++mt) acc[mt][nt] = make_float4(b0, b1v, b0, b1v);
        }
#pragma unroll 4
        for (int ks = 0; ks < 16; ++ks) {
            u32 a[2][4];
#pragma unroll
            for (int mt = 0; mt < 2; ++mt)
                ldA_raw<SXL>(s_hmt + (4 + mt * 16 + frow) * SXL + ks * 8 + fcol, a[mt]);
#pragma unroll
            for (int nt = 0; nt < 4; ++nt) {
                const float2 b = g_mwp[6 * 8192 + (ks * 16 + ng * 4 + nt) * 32 + lane];
#pragma unroll
                for (int mt = 0; mt < 2; ++mt)
                    mma8(acc[mt][nt], a[mt], __float_as_uint(b.x), __float_as_uint(b.y));
            }
        }
#pragma unroll
        for (int mt = 0; mt < 2; ++mt) {
            const int rA = r0 + mt * 16 + frow;
#pragma unroll
            for (int nt = 0; nt < 4; ++nt) {
                const int gc = ng * 32 + nt * 8 + 2 * fcol;
                *(float2*)(g_bcb + rA * Dm + gc)       = make_float2(acc[mt][nt].x, acc[mt][nt].y);
                *(float2*)(g_bcb + (rA + 8) * Dm + gc) = make_float2(acc[mt][nt].z, acc[mt][nt].w);
            }
        }
    }
}

// ============================================================
// K5: logits = LN(local + bc) @ head_w (tensor), 64 tok/block
// ============================================================
__global__ __launch_bounds__(256) void k_head(
    const float* __restrict__ lg, const float* __restrict__ lb,
    float* __restrict__ out)
{
    __shared__ float s_x[64 * SXL];
    const int tid = threadIdx.x, wid = tid >> 5, lane = tid & 31;
    const int gt0 = blockIdx.x * 64;
    const int frow = lane >> 2, fcol = lane & 3;

#pragma unroll
    for (int tt = 0; tt < 8; ++tt) {
        const int tl = wid * 8 + tt, gt = gt0 + tl;
        const float4 lv = *(const float4*)(g_local + gt * Dm + lane * 4);
        const float4 bv = *(const float4*)(g_bcb + (gt >> 3) * Dm + lane * 4);
        const float4 h = make_float4(lv.x + bv.x, lv.y + bv.y, lv.z + bv.z, lv.w + bv.w);
        const float4 v = ln_f4(h, lg, lb, lane);
        float* dst = s_x + tl * SXL + lane * 4;
        dst[0] = f2tff(v.x); dst[1] = f2tff(v.y); dst[2] = f2tff(v.z); dst[3] = f2tff(v.w);
    }
    __syncthreads();

    const int mg = (wid >> 2) * 32;
    const int ng = (wid & 3);
    float4 acc[2][8];
#pragma unroll
    for (int mt = 0; mt < 2; ++mt)
#pragma unroll
        for (int nt = 0; nt < 8; ++nt) acc[mt][nt] = make_float4(0.f, 0.f, 0.f, 0.f);

#pragma unroll 4
    for (int ks = 0; ks < 16; ++ks) {
        u32 a[2][4];
#pragma unroll
        for (int mt = 0; mt < 2; ++mt)
            ldA_raw<SXL>(s_x + (mg + mt * 16 + frow) * SXL + ks * 8 + fcol, a[mt]);
#pragma unroll
        for (int nt = 0; nt < 8; ++nt) {
            const float2 b = g_hwp[(ks * 32 + ng * 8 + nt) * 32 + lane];
#pragma unroll
            for (int mt = 0; mt < 2; ++mt)
                mma8(acc[mt][nt], a[mt], __float_as_uint(b.x), __float_as_uint(b.y));
        }
    }

#pragma unroll
    for (int mt = 0; mt < 2; ++mt) {
        const int rg = gt0 + mg + mt * 16 + frow;
#pragma unroll
        for (int nt = 0; nt < 8; ++nt) {
            const int gc = ng * 64 + nt * 8 + 2 * fcol;
            *(float2*)(out + rg * Hm + gc)       = make_float2(acc[mt][nt].x, acc[mt][nt].y);
            *(float2*)(out + (rg + 8) * Hm + gc) = make_float2(acc[mt][nt].z, acc[mt][nt].w);
        }
    }
}

// ============================================================
extern "C" void kernel_launch(void* const* d_in, const int* in_sizes, int n_in,
                              void* d_out, int out_size) {
    const int*   x      = (const int*)  d_in[0];
    const float* emb    = (const float*)d_in[1];
    const float* pos    = (const float*)d_in[2];
    const float* lw1    = (const float*)d_in[3];
    const float* lb1    = (const float*)d_in[4];
    const float* lw2    = (const float*)d_in[5];
    const float* lb2    = (const float*)d_in[6];
    const float* lln_g  = (const float*)d_in[7];
    const float* lln_b  = (const float*)d_in[8];
    const float* pool_w = (const float*)d_in[9];
    const float* pool_b = (const float*)d_in[10];
    const float* msg_w1 = (const float*)d_in[11];
    const float* msg_b1 = (const float*)d_in[12];
    const float* msg_w2 = (const float*)d_in[13];
    const float* msg_b2 = (const float*)d_in[14];
    const float* upd_w1 = (const float*)d_in[15];
    const float* upd_b1 = (const float*)d_in[16];
    const float* upd_w2 = (const float*)d_in[17];
    const float* upd_b2 = (const float*)d_in[18];
    const float* mln_g  = (const float*)d_in[19];
    const float* mln_b  = (const float*)d_in[20];
    const float* bc_w   = (const float*)d_in[21];
    const float* bc_b   = (const float*)d_in[22];
    const float* fln_g  = (const float*)d_in[23];
    const float* fln_b  = (const float*)d_in[24];
    const float* head_w = (const float*)d_in[25];
    float* out = (float*)d_out;

    const int SMEM_LOCAL = (64 * SXL + 64 * SHL) * 4;   // 100352 B
    const int SMEM_MSG   = (160 * SXL) * 4;             // 84480 B
    cudaFuncSetAttribute(k_local, cudaFuncAttributeMaxDynamicSharedMemorySize, SMEM_LOCAL);
    cudaFuncSetAttribute(k_msgf,  cudaFuncAttributeMaxDynamicSharedMemorySize, SMEM_MSG);

    k_pack_all<<<416, 256>>>(lw1, lw2, head_w, msg_w1, msg_w2, upd_w1, upd_w2, bc_w);

    k_local<<<NTOK / 64, 256, SMEM_LOCAL>>>(x, emb, pos, lb1, lb2,
                                            lln_g, lln_b, pool_w, pool_b);

    // rounds: A->B, B->A, A->(bc)  (last round writes g_bcb, skips hout)
    for (int r = 0; r < 3; ++r) {
        const int useA = (r % 2 == 0) ? 1 : 0;
        const int last = (r == 2) ? 1 : 0;
        k_msgf<<<ROWS / 32, 128, SMEM_MSG>>>(useA, last, msg_b1, msg_b2,
                                             upd_b1, upd_b2, mln_g, mln_b, bc_b);
    }

    k_head<<<NTOK / 64, 256>>>(fln_g, fln_b, out);
}

// round 10
// speedup vs baseline: 1.0199x; 1.0199x over previous
#include <cuda_runtime.h>

#define Dm 128
#define Hm 256
#define ROWS 16384   /* 16 * 1024 chunks */
#define NTOK 131072  /* 16 * 8192 tokens */
#define EPSf 1e-5f

typedef unsigned long long u64;
typedef unsigned int u32;

// ---- scratch (device globals; no allocation) ----
__device__ float g_local[NTOK * Dm];   // 64 MB
__device__ float g_hA[ROWS * Dm];      // 8 MB
__device__ float g_hB[ROWS * Dm];      // 8 MB
__device__ float g_bcb[ROWS * Dm];     // 8 MB
// packed tf32 weight fragments
__device__ float2 g_w1p[16 * 32 * 32]; // lw1 128x256
__device__ float2 g_w2p[32 * 16 * 32]; // lw2 256x128
__device__ float2 g_hwp[16 * 32 * 32]; // head_w 128x256
// 128x128 mats: [0]=w1self [1]=w1nbr [2]=mw2 [3]=uw1a [4]=uw1b [5]=uw2 [6]=bc_w
__device__ float2 g_mwp[7 * 8192];

// ---- packed f32x2 helpers (scalar path) ----
__device__ __forceinline__ u64 pk2(float x, float y) {
    u64 r; asm("mov.b64 %0, {%1, %2};" : "=l"(r) : "f"(x), "f"(y)); return r;
}
__device__ __forceinline__ u64 dup_f(float a) {
    u64 r; asm("mov.b64 %0, {%1, %1};" : "=l"(r) : "f"(a)); return r;
}
__device__ __forceinline__ void fma2(u64& d, u64 a, u64 b) {
    asm("fma.rn.f32x2 %0, %1, %2, %0;" : "+l"(d) : "l"(a), "l"(b));
}
__device__ __forceinline__ float2 u2f(u64 v) {
    float2 r; asm("mov.b64 {%0, %1}, %2;" : "=f"(r.x), "=f"(r.y) : "l"(v)); return r;
}

// ---- tf32 helpers ----
__device__ __forceinline__ u32 f2tf(float f) {
    u32 r; asm("cvt.rna.tf32.f32 %0, %1;" : "=r"(r) : "f"(f)); return r;
}
__device__ __forceinline__ float f2tff(float f) { return __uint_as_float(f2tf(f)); }

// mma.sync m16n8k8 tf32
__device__ __forceinline__ void mma8(float4& c, const u32 a[4], u32 b0, u32 b1) {
    asm volatile(
        "mma.sync.aligned.m16n8k8.row.col.f32.tf32.tf32.f32 "
        "{%0,%1,%2,%3}, {%4,%5,%6,%7}, {%8,%9}, {%0,%1,%2,%3};"
        : "+f"(c.x), "+f"(c.y), "+f"(c.z), "+f"(c.w)
        : "r"(a[0]), "r"(a[1]), "r"(a[2]), "r"(a[3]), "r"(b0), "r"(b1));
}

template<int STRIDE>
__device__ __forceinline__ void ldA_raw(const float* ap, u32 a[4]) {
    a[0] = __float_as_uint(ap[0]);
    a[1] = __float_as_uint(ap[8 * STRIDE]);
    a[2] = __float_as_uint(ap[4]);
    a[3] = __float_as_uint(ap[8 * STRIDE + 4]);
}

__device__ __forceinline__ float wsum(float v) {
#pragma unroll
    for (int o = 16; o; o >>= 1) v += __shfl_xor_sync(0xffffffffu, v, o);
    return v;
}
__device__ __forceinline__ float gelu_f(float x) {
    return 0.5f * x * (1.0f + erff(x * 0.70710678118f));
}

__device__ __forceinline__ float4 ln_f4(float4 h, const float* __restrict__ g,
                                        const float* __restrict__ b, int lane) {
    const float mu = wsum(h.x + h.y + h.z + h.w) * (1.0f / 128.0f);
    const float a0 = h.x - mu, a1 = h.y - mu, a2 = h.z - mu, a3 = h.w - mu;
    const float var = wsum(a0 * a0 + a1 * a1 + a2 * a2 + a3 * a3) * (1.0f / 128.0f);
    const float rs = rsqrtf(var + EPSf);
    const int dd = lane * 4;
    const float4 gg = *(const float4*)(g + dd);
    const float4 bb = *(const float4*)(b + dd);
    return make_float4(a0 * rs * gg.x + bb.x, a1 * rs * gg.y + bb.y,
                       a2 * rs * gg.z + bb.z, a3 * rs * gg.w + bb.w);
}

// ---- scalar register-tiled GEMM accumulate (pool only) ----
template<int KDIM, int RPT, int NCP>
__device__ __forceinline__ void mm_acc(const float* __restrict__ s,
                                       const float* __restrict__ W, const int ldw,
                                       u64 acc[RPT][NCP]) {
#pragma unroll 2
    for (int d = 0; d < KDIM; d += 2) {
        u64 w0[NCP], w1[NCP];
        if constexpr (NCP >= 2) {
#pragma unroll
            for (int c = 0; c < NCP; c += 2) {
                const ulonglong2 t0 = *(const ulonglong2*)(W + d * ldw + c * 2);
                const ulonglong2 t1 = *(const ulonglong2*)(W + (d + 1) * ldw + c * 2);
                w0[c] = t0.x; w0[c + 1] = t0.y;
                w1[c] = t1.x; w1[c + 1] = t1.y;
            }
        } else {
            w0[0] = *(const u64*)(W + d * ldw);
            w1[0] = *(const u64*)(W + (d + 1) * ldw);
        }
#pragma unroll
        for (int r = 0; r < RPT; ++r) {
            const float2 a = *(const float2*)(s + r * KDIM + d);
            const u64 a0 = dup_f(a.x), a1 = dup_f(a.y);
#pragma unroll
            for (int c = 0; c < NCP; ++c) {
                fma2(acc[r][c], a0, w0[c]);
                fma2(acc[r][c], a1, w1[c]);
            }
        }
    }
}

// ============================================================
// K0: fused pack of all weights into tf32 B-fragment order
// ============================================================
__device__ __forceinline__ void pack_one(const float* __restrict__ W,
                                         float2* __restrict__ P,
                                         int N, int idx) {
    const int lane = idx & 31;
    const int t = idx >> 5;
    const int nt = t % (N / 8);
    const int ks = t / (N / 8);
    const int k = ks * 8 + (lane & 3);
    const int n = nt * 8 + (lane >> 2);
    P[idx] = make_float2(f2tff(W[k * N + n]), f2tff(W[(k + 4) * N + n]));
}

__global__ __launch_bounds__(256) void k_pack_all(
    const float* __restrict__ lw1, const float* __restrict__ lw2,
    const float* __restrict__ hw,  const float* __restrict__ mw1,
    const float* __restrict__ mw2, const float* __restrict__ uw1,
    const float* __restrict__ uw2, const float* __restrict__ bcw)
{
    const int b = blockIdx.x, tid = threadIdx.x;
    if      (b < 64)  pack_one(lw1, g_w1p, 256, b * 256 + tid);
    else if (b < 128) pack_one(lw2, g_w2p, 128, (b - 64) * 256 + tid);
    else if (b < 192) pack_one(hw,  g_hwp, 256, (b - 128) * 256 + tid);
    else if (b < 224) pack_one(mw1,           g_mwp + 0 * 8192, 128, (b - 192) * 256 + tid);
    else if (b < 256) pack_one(mw1 + 16384,   g_mwp + 1 * 8192, 128, (b - 224) * 256 + tid);
    else if (b < 288) pack_one(mw2,           g_mwp + 2 * 8192, 128, (b - 256) * 256 + tid);
    else if (b < 320) pack_one(uw1,           g_mwp + 3 * 8192, 128, (b - 288) * 256 + tid);
    else if (b < 352) pack_one(uw1 + 16384,   g_mwp + 4 * 8192, 128, (b - 320) * 256 + tid);
    else if (b < 384) pack_one(uw2,           g_mwp + 5 * 8192, 128, (b - 352) * 256 + tid);
    else              pack_one(bcw,           g_mwp + 6 * 8192, 128, (b - 384) * 256 + tid);
}

// ============================================================
// K1: local = h + MLP2(LN(h)) + fused pool/summ (tensor-core)
// 64 tokens/block, 256 threads, split-N MLP, 67.6KB smem, 3 CTAs/SM
// ============================================================
#define SXL 132
__global__ __launch_bounds__(256, 3) void k_local(
    const int* __restrict__ x, const float* __restrict__ emb, const float* __restrict__ pos,
    const float* __restrict__ lb1, const float* __restrict__ lb2,
    const float* __restrict__ lng, const float* __restrict__ lnb,
    const float* __restrict__ pw, const float* __restrict__ pb)
{
    extern __shared__ float sm[];
    float* s_x = sm;                // 64 x 132 : tf32 LN; later fp32 local
    float* s_h = sm + 64 * SXL;     // 64 x 132 : tf32 hidden half
    const int tid = threadIdx.x, wid = tid >> 5, lane = tid & 31;
    const int gt0 = blockIdx.x * 64;
    const int frow = lane >> 2, fcol = lane & 3;

    // phase 1: LN per token -> tf32 in s_x
#pragma unroll
    for (int tt = 0; tt < 8; ++tt) {
        const int tl = wid * 8 + tt, gt = gt0 + tl;
        const int xt = __ldg(x + gt);
        const float4 e = *(const float4*)(emb + xt * Dm + lane * 4);
        const float4 p = *(const float4*)(pos + (gt & 7) * Dm + lane * 4);
        const float4 h = make_float4(e.x + p.x, e.y + p.y, e.z + p.z, e.w + p.w);
        const float4 v = ln_f4(h, lng, lnb, lane);
        float* dst = s_x + tl * SXL + lane * 4;
        dst[0] = f2tff(v.x); dst[1] = f2tff(v.y); dst[2] = f2tff(v.z); dst[3] = f2tff(v.w);
    }
    __syncthreads();

    const int mg = (wid >> 2) * 32;   // 2 m-groups of 32 rows
    const int ng = (wid & 3);         // 4 n-groups

    // phase 2+3 over two 128-col halves of the hidden dim;
    // phase-3 accumulators persist in registers across halves.
    float4 acc3[2][4];
#pragma unroll
    for (int nt = 0; nt < 4; ++nt) {
        const int gc = ng * 32 + nt * 8 + 2 * fcol;
        const float b0 = lb2[gc], b1v = lb2[gc + 1];
#pragma unroll
        for (int mt = 0; mt < 2; ++mt) acc3[mt][nt] = make_float4(b0, b1v, b0, b1v);
    }

#pragma unroll
    for (int half = 0; half < 2; ++half) {
        // phase 2: hid half = gelu(xln @ lw1[:, half*128 + ...] + b1)
        {
            float4 acc2[2][4];
#pragma unroll
            for (int nt = 0; nt < 4; ++nt) {
                const int gcH = half * 128 + ng * 32 + nt * 8 + 2 * fcol;
                const float b0 = lb1[gcH], b1v = lb1[gcH + 1];
#pragma unroll
                for (int mt = 0; mt < 2; ++mt) acc2[mt][nt] = make_float4(b0, b1v, b0, b1v);
            }
#pragma unroll 4
            for (int ks = 0; ks < 16; ++ks) {
                u32 a[2][4];
#pragma unroll
                for (int mt = 0; mt < 2; ++mt)
                    ldA_raw<SXL>(s_x + (mg + mt * 16 + frow) * SXL + ks * 8 + fcol, a[mt]);
#pragma unroll
                for (int nt = 0; nt < 4; ++nt) {
                    const float2 b = g_w1p[(ks * 32 + half * 16 + ng * 4 + nt) * 32 + lane];
#pragma unroll
                    for (int mt = 0; mt < 2; ++mt)
                        mma8(acc2[mt][nt], a[mt], __float_as_uint(b.x), __float_as_uint(b.y));
                }
            }
#pragma unroll
            for (int mt = 0; mt < 2; ++mt) {
                const int rg = mg + mt * 16 + frow;
#pragma unroll
                for (int nt = 0; nt < 4; ++nt) {
                    const int gc = ng * 32 + nt * 8 + 2 * fcol;
                    *(float2*)(s_h + rg * SXL + gc) =
                        make_float2(f2tff(gelu_f(acc2[mt][nt].x)), f2tff(gelu_f(acc2[mt][nt].y)));
                    *(float2*)(s_h + (rg + 8) * SXL + gc) =
                        make_float2(f2tff(gelu_f(acc2[mt][nt].z)), f2tff(gelu_f(acc2[mt][nt].w)));
                }
            }
        }
        __syncthreads();

        // phase 3 partial: acc3 += hid_half @ lw2[half*128.. , :]
#pragma unroll 4
        for (int ks = 0; ks < 16; ++ks) {
            u32 a[2][4];
#pragma unroll
            for (int mt = 0; mt < 2; ++mt)
                ldA_raw<SXL>(s_h + (mg + mt * 16 + frow) * SXL + ks * 8 + fcol, a[mt]);
#pragma unroll
            for (int nt = 0; nt < 4; ++nt) {
                const float2 b = g_w2p[((half * 16 + ks) * 16 + ng * 4 + nt) * 32 + lane];
#pragma unroll
                for (int mt = 0; mt < 2; ++mt)
                    mma8(acc3[mt][nt], a[mt], __float_as_uint(b.x), __float_as_uint(b.y));
            }
        }
        __syncthreads();
    }

    // write local out = h + acc3 -> g_local and s_x (fp32)
#pragma unroll
    for (int mt = 0; mt < 2; ++mt) {
#pragma unroll
        for (int rr = 0; rr < 2; ++rr) {
            const int tl = mg + mt * 16 + frow + rr * 8;
            const int gt = gt0 + tl;
            const int xt = __ldg(x + gt);
#pragma unroll
            for (int nt = 0; nt < 4; ++nt) {
                const int gc = ng * 32 + nt * 8 + 2 * fcol;
                const float2 e = *(const float2*)(emb + xt * Dm + gc);
                const float2 p = *(const float2*)(pos + (gt & 7) * Dm + gc);
                const float cx = rr ? acc3[mt][nt].z : acc3[mt][nt].x;
                const float cy = rr ? acc3[mt][nt].w : acc3[mt][nt].y;
                const float2 o = make_float2(e.x + p.x + cx, e.y + p.y + cy);
                *(float2*)(g_local + gt * Dm + gc) = o;
                *(float2*)(s_x + tl * SXL + gc) = o;
            }
        }
    }
    __syncthreads();

    // phase 4: chunk means (8 chunks) -> s_h[0:1024]
#pragma unroll
    for (int it = 0; it < 4; ++it) {
        const int idx = tid + it * 256;
        const int c = idx >> 7, dd = idx & 127;
        float s = 0.f;
#pragma unroll
        for (int t = 0; t < 8; ++t) s += s_x[(c * 8 + t) * SXL + dd];
        s_h[c * 128 + dd] = s * 0.125f;
    }
    __syncthreads();

    // phase 5: summ = mean @ pool_w + pool_b -> g_hA (warp per chunk)
    {
        const int j0 = lane * 4;
        u64 acc1[1][2];
        acc1[0][0] = pk2(pb[j0], pb[j0 + 1]);
        acc1[0][1] = pk2(pb[j0 + 2], pb[j0 + 3]);
        mm_acc<128, 1, 2>(s_h + wid * 128, pw + j0, 128, acc1);
        const float2 v0 = u2f(acc1[0][0]), v1 = u2f(acc1[0][1]);
        *(float4*)(g_hA + (blockIdx.x * 8 + wid) * Dm + j0) =
            make_float4(v0.x, v0.y, v1.x, v1.y);
    }
}

// ============================================================
// K2: FUSED msg round, 256 threads / 8 warps, 32 rows (+4 halo)
// smem 84.5KB -> 2 CTAs/SM. grid 512.
//   s_hmt 48 rows tf32 hmsg (v = row-(r0-4))
//   s_pn  48 rows nbr-proj; rows 0..31 alias agg
//   s_ps  32 rows self-proj; alias uh
//   s_hs  32 rows gelu-sum; alias pre-LN fp32
// ============================================================
__global__ __launch_bounds__(256) void k_msgf(
    int useA, int last,
    const float* __restrict__ mb1, const float* __restrict__ mb2,
    const float* __restrict__ ub1, const float* __restrict__ ub2,
    const float* __restrict__ lg, const float* __restrict__ lb,
    const float* __restrict__ bcb)
{
    const float* __restrict__ hin = useA ? g_hA : g_hB;
    float* __restrict__ hout = useA ? g_hB : g_hA;
    extern __shared__ float sm[];
    float* s_hmt = sm;
    float* s_pn  = sm + 48 * SXL;
    float* s_ps  = sm + 96 * SXL;
    float* s_hs  = sm + 128 * SXL;
    float* s_ag  = s_pn;
    float* s_uh  = s_ps;
    float* s_pl  = s_hs;
    const int tid = threadIdx.x, wid = tid >> 5, lane = tid & 31;
    const int r0 = blockIdx.x * 32;
    const int frow = lane >> 2, fcol = lane & 3;
    const int ng = wid & 3;            // 4 n-groups of 32 cols
    const int mgrp = wid >> 2;         // 2 m-groups of 16 rows (phases P3+)
    const int mrow = mgrp * 16;

    // P0: load 48 halo rows of hmsg as tf32 (clamped)
#pragma unroll
    for (int it = 0; it < 24; ++it) {
        const int idx = tid + it * 256;
        const int v = idx >> 7, j = idx & 127;
        int row = r0 - 4 + v;
        row = row < 0 ? 0 : (row > ROWS - 1 ? ROWS - 1 : row);
        s_hmt[v * SXL + j] = f2tff(hin[row * Dm + j]);
    }
    __syncthreads();

    // P1: warps 0-3: self-proj (2 m-tiles, rows v=4..35); warps 4-7: nbr-proj (3 m-tiles, v=0..47)
    if (mgrp == 0) {
        float4 acc[2][4];
#pragma unroll
        for (int mt = 0; mt < 2; ++mt)
#pragma unroll
            for (int nt = 0; nt < 4; ++nt) acc[mt][nt] = make_float4(0.f, 0.f, 0.f, 0.f);
#pragma unroll 4
        for (int ks = 0; ks < 16; ++ks) {
            u32 a[2][4];
#pragma unroll
            for (int mt = 0; mt < 2; ++mt)
                ldA_raw<SXL>(s_hmt + (4 + mt * 16 + frow) * SXL + ks * 8 + fcol, a[mt]);
#pragma unroll
            for (int nt = 0; nt < 4; ++nt) {
                const float2 b = g_mwp[0 * 8192 + (ks * 16 + ng * 4 + nt) * 32 + lane];
#pragma unroll
                for (int mt = 0; mt < 2; ++mt)
                    mma8(acc[mt][nt], a[mt], __float_as_uint(b.x), __float_as_uint(b.y));
            }
        }
#pragma unroll
        for (int mt = 0; mt < 2; ++mt) {
            const int r = mt * 16 + frow;
#pragma unroll
            for (int nt = 0; nt < 4; ++nt) {
                const int gc = ng * 32 + nt * 8 + 2 * fcol;
                *(float2*)(s_ps + r * SXL + gc)       = make_float2(acc[mt][nt].x, acc[mt][nt].y);
                *(float2*)(s_ps + (r + 8) * SXL + gc) = make_float2(acc[mt][nt].z, acc[mt][nt].w);
            }
        }
    } else {
        float4 acc[3][4];
#pragma unroll
        for (int mt = 0; mt < 3; ++mt)
#pragma unroll
            for (int nt = 0; nt < 4; ++nt) acc[mt][nt] = make_float4(0.f, 0.f, 0.f, 0.f);
#pragma unroll 4
        for (int ks = 0; ks < 16; ++ks) {
            u32 a[3][4];
#pragma unroll
            for (int mt = 0; mt < 3; ++mt)
                ldA_raw<SXL>(s_hmt + (mt * 16 + frow) * SXL + ks * 8 + fcol, a[mt]);
#pragma unroll
            for (int nt = 0; nt < 4; ++nt) {
                const float2 b = g_mwp[1 * 8192 + (ks * 16 + ng * 4 + nt) * 32 + lane];
#pragma unroll
                for (int mt = 0; mt < 3; ++mt)
                    mma8(acc[mt][nt], a[mt], __float_as_uint(b.x), __float_as_uint(b.y));
            }
        }
#pragma unroll
        for (int mt = 0; mt < 3; ++mt) {
            const int v = mt * 16 + frow;
#pragma unroll
            for (int nt = 0; nt < 4; ++nt) {
                const int gc = ng * 32 + nt * 8 + 2 * fcol;
                *(float2*)(s_pn + v * SXL + gc)       = make_float2(acc[mt][nt].x, acc[mt][nt].y);
                *(float2*)(s_pn + (v + 8) * SXL + gc) = make_float2(acc[mt][nt].z, acc[mt][nt].w);
            }
        }
    }
    __syncthreads();

    // P2: gelu-sum -> s_hs (tf32)
#pragma unroll
    for (int it = 0; it < 16; ++it) {
        const int idx = tid + it * 256;
        const int r = idx >> 7, j = idx & 127;
        const int i = (r0 + r) & 1023;
        const float ps_b = s_ps[r * SXL + j] + mb1[j];
        float a = 0.f;
#pragma unroll
        for (int dd = 0; dd < 5; ++dd) {
            if (i >= dd) a += gelu_f(ps_b + s_pn[(r + 4 - dd) * SXL + j]);
        }
        s_hs[r * SXL + j] = f2tff(a);
    }
    __syncthreads();

    // P3: agg = (HS @ mw2)/count + b2 -> s_ag (tf32; alias s_pn rows 0..31)
    {
        float4 acc[4];
#pragma unroll
        for (int nt = 0; nt < 4; ++nt) acc[nt] = make_float4(0.f, 0.f, 0.f, 0.f);
#pragma unroll 4
        for (int ks = 0; ks < 16; ++ks) {
            u32 a[4];
            ldA_raw<SXL>(s_hs + (mrow + frow) * SXL + ks * 8 + fcol, a);
#pragma unroll
            for (int nt = 0; nt < 4; ++nt) {
                const float2 b = g_mwp[2 * 8192 + (ks * 16 + ng * 4 + nt) * 32 + lane];
                mma8(acc[nt], a, __float_as_uint(b.x), __float_as_uint(b.y));
            }
        }
        __syncthreads();
        const int rA = mrow + frow;
        const int iA = (r0 + rA) & 1023, iB = (r0 + rA + 8) & 1023;
        const float invA = 1.0f / ((iA + 1) < 5 ? (float)(iA + 1) : 5.0f);
        const float invB = 1.0f / ((iB + 1) < 5 ? (float)(iB + 1) : 5.0f);
#pragma unroll
        for (int nt = 0; nt < 4; ++nt) {
            const int gc = ng * 32 + nt * 8 + 2 * fcol;
            const float b20 = mb2[gc], b21 = mb2[gc + 1];
            *(float2*)(s_ag + rA * SXL + gc) =
                make_float2(f2tff(acc[nt].x * invA + b20), f2tff(acc[nt].y * invA + b21));
            *(float2*)(s_ag + (rA + 8) * SXL + gc) =
                make_float2(f2tff(acc[nt].z * invB + b20), f2tff(acc[nt].w * invB + b21));
        }
    }
    __syncthreads();

    // P4: uh = gelu(HMT @ uw1a + AG @ uw1b + ub1) -> s_uh (tf32; alias s_ps)
    {
        float4 acc[4];
#pragma unroll
        for (int nt = 0; nt < 4; ++nt) {
            const int gc = ng * 32 + nt * 8 + 2 * fcol;
            acc[nt] = make_float4(ub1[gc], ub1[gc + 1], ub1[gc], ub1[gc + 1]);
        }
#pragma unroll 4
        for (int ks = 0; ks < 16; ++ks) {
            u32 a[4];
            ldA_raw<SXL>(s_hmt + (4 + mrow + frow) * SXL + ks * 8 + fcol, a);
#pragma unroll
            for (int nt = 0; nt < 4; ++nt) {
                const float2 b = g_mwp[3 * 8192 + (ks * 16 + ng * 4 + nt) * 32 + lane];
                mma8(acc[nt], a, __float_as_uint(b.x), __float_as_uint(b.y));
            }
        }
#pragma unroll 4
        for (int ks = 0; ks < 16; ++ks) {
            u32 a[4];
            ldA_raw<SXL>(s_ag + (mrow + frow) * SXL + ks * 8 + fcol, a);
#pragma unroll
            for (int nt = 0; nt < 4; ++nt) {
                const float2 b = g_mwp[4 * 8192 + (ks * 16 + ng * 4 + nt) * 32 + lane];
                mma8(acc[nt], a, __float_as_uint(b.x), __float_as_uint(b.y));
            }
        }
        __syncthreads();
        const int rA = mrow + frow;
#pragma unroll
        for (int nt = 0; nt < 4; ++nt) {
            const int gc = ng * 32 + nt * 8 + 2 * fcol;
            *(float2*)(s_uh + rA * SXL + gc) =
                make_float2(f2tff(gelu_f(acc[nt].x)), f2tff(gelu_f(acc[nt].y)));
            *(float2*)(s_uh + (rA + 8) * SXL + gc) =
                make_float2(f2tff(gelu_f(acc[nt].z)), f2tff(gelu_f(acc[nt].w)));
        }
    }
    __syncthreads();

    // P5: pre-LN = hmsg + UH @ uw2 + ub2 -> s_pl (fp32; alias s_hs)
    {
        float4 acc[4];
#pragma unroll
        for (int nt = 0; nt < 4; ++nt) {
            const int gc = ng * 32 + nt * 8 + 2 * fcol;
            acc[nt] = make_float4(ub2[gc], ub2[gc + 1], ub2[gc], ub2[gc + 1]);
        }
#pragma unroll 4
        for (int ks = 0; ks < 16; ++ks) {
            u32 a[4];
            ldA_raw<SXL>(s_uh + (mrow + frow) * SXL + ks * 8 + fcol, a);
#pragma unroll
            for (int nt = 0; nt < 4; ++nt) {
                const float2 b = g_mwp[5 * 8192 + (ks * 16 + ng * 4 + nt) * 32 + lane];
                mma8(acc[nt], a, __float_as_uint(b.x), __float_as_uint(b.y));
            }
        }
        __syncthreads();
        const int rA = mrow + frow;
#pragma unroll
        for (int nt = 0; nt < 4; ++nt) {
            const int gc = ng * 32 + nt * 8 + 2 * fcol;
            const float2 h0 = *(const float2*)(s_hmt + (4 + rA) * SXL + gc);
            const float2 h1 = *(const float2*)(s_hmt + (12 + rA) * SXL + gc);
            *(float2*)(s_pl + rA * SXL + gc) =
                make_float2(h0.x + acc[nt].x, h0.y + acc[nt].y);
            *(float2*)(s_pl + (rA + 8) * SXL + gc) =
                make_float2(h1.x + acc[nt].z, h1.y + acc[nt].w);
        }
    }
    __syncthreads();

    // P6: LN per row (4 rows/warp). Non-final: -> hout. Final: tf32 -> s_hmt[4+r]
#pragma unroll
    for (int rr = 0; rr < 4; ++rr) {
        const int r = wid * 4 + rr;
        const float4 v0 = *(const float4*)(s_pl + r * SXL + lane * 4);
        const float4 v = ln_f4(v0, lg, lb, lane);
        if (!last) {
            *(float4*)(hout + (r0 + r) * Dm + lane * 4) = v;
        } else {
            float* dst = s_hmt + (4 + r) * SXL + lane * 4;
            dst[0] = f2tff(v.x); dst[1] = f2tff(v.y);
            dst[2] = f2tff(v.z); dst[3] = f2tff(v.w);
        }
    }

    // P7 (final round only): bc = hmsg_final @ bc_w + bc_b -> g_bcb
    if (last) {
        __syncthreads();
        float4 acc[4];
#pragma unroll
        for (int nt = 0; nt < 4; ++nt) {
            const int gc = ng * 32 + nt * 8 + 2 * fcol;
            acc[nt] = make_float4(bcb[gc], bcb[gc + 1], bcb[gc], bcb[gc + 1]);
        }
#pragma unroll 4
        for (int ks = 0; ks < 16; ++ks) {
            u32 a[4];
            ldA_raw<SXL>(s_hmt + (4 + mrow + frow) * SXL + ks * 8 + fcol, a);
#pragma unroll
            for (int nt = 0; nt < 4; ++nt) {
                const float2 b = g_mwp[6 * 8192 + (ks * 16 + ng * 4 + nt) * 32 + lane];
                mma8(acc[nt], a, __float_as_uint(b.x), __float_as_uint(b.y));
            }
        }
        const int rA = r0 + mrow + frow;
#pragma unroll
        for (int nt = 0; nt < 4; ++nt) {
            const int gc = ng * 32 + nt * 8 + 2 * fcol;
            *(float2*)(g_bcb + rA * Dm + gc)       = make_float2(acc[nt].x, acc[nt].y);
            *(float2*)(g_bcb + (rA + 8) * Dm + gc) = make_float2(acc[nt].z, acc[nt].w);
        }
    }
}

// ============================================================
// K5: logits = LN(local + bc) @ head_w (tensor), 64 tok/block
// ============================================================
__global__ __launch_bounds__(256) void k_head(
    const float* __restrict__ lg, const float* __restrict__ lb,
    float* __restrict__ out)
{
    __shared__ float s_x[64 * SXL];
    const int tid = threadIdx.x, wid = tid >> 5, lane = tid & 31;
    const int gt0 = blockIdx.x * 64;
    const int frow = lane >> 2, fcol = lane & 3;

#pragma unroll
    for (int tt = 0; tt < 8; ++tt) {
        const int tl = wid * 8 + tt, gt = gt0 + tl;
        const float4 lv = *(const float4*)(g_local + gt * Dm + lane * 4);
        const float4 bv = *(const float4*)(g_bcb + (gt >> 3) * Dm + lane * 4);
        const float4 h = make_float4(lv.x + bv.x, lv.y + bv.y, lv.z + bv.z, lv.w + bv.w);
        const float4 v = ln_f4(h, lg, lb, lane);
        float* dst = s_x + tl * SXL + lane * 4;
        dst[0] = f2tff(v.x); dst[1] = f2tff(v.y); dst[2] = f2tff(v.z); dst[3] = f2tff(v.w);
    }
    __syncthreads();

    const int mg = (wid >> 2) * 32;
    const int ng = (wid & 3);
    float4 acc[2][8];
#pragma unroll
    for (int mt = 0; mt < 2; ++mt)
#pragma unroll
        for (int nt = 0; nt < 8; ++nt) acc[mt][nt] = make_float4(0.f, 0.f, 0.f, 0.f);

#pragma unroll 4
    for (int ks = 0; ks < 16; ++ks) {
        u32 a[2][4];
#pragma unroll
        for (int mt = 0; mt < 2; ++mt)
            ldA_raw<SXL>(s_x + (mg + mt * 16 + frow) * SXL + ks * 8 + fcol, a[mt]);
#pragma unroll
        for (int nt = 0; nt < 8; ++nt) {
            const float2 b = g_hwp[(ks * 32 + ng * 8 + nt) * 32 + lane];
#pragma unroll
            for (int mt = 0; mt < 2; ++mt)
                mma8(acc[mt][nt], a[mt], __float_as_uint(b.x), __float_as_uint(b.y));
        }
    }

#pragma unroll
    for (int mt = 0; mt < 2; ++mt) {
        const int rg = gt0 + mg + mt * 16 + frow;
#pragma unroll
        for (int nt = 0; nt < 8; ++nt) {
            const int gc = ng * 64 + nt * 8 + 2 * fcol;
            *(float2*)(out + rg * Hm + gc)       = make_float2(acc[mt][nt].x, acc[mt][nt].y);
            *(float2*)(out + (rg + 8) * Hm + gc) = make_float2(acc[mt][nt].z, acc[mt][nt].w);
        }
    }
}

// ============================================================
extern "C" void kernel_launch(void* const* d_in, const int* in_sizes, int n_in,
                              void* d_out, int out_size) {
    const int*   x      = (const int*)  d_in[0];
    const float* emb    = (const float*)d_in[1];
    const float* pos    = (const float*)d_in[2];
    const float* lw1    = (const float*)d_in[3];
    const float* lb1    = (const float*)d_in[4];
    const float* lw2    = (const float*)d_in[5];
    const float* lb2    = (const float*)d_in[6];
    const float* lln_g  = (const float*)d_in[7];
    const float* lln_b  = (const float*)d_in[8];
    const float* pool_w = (const float*)d_in[9];
    const float* pool_b = (const float*)d_in[10];
    const float* msg_w1 = (const float*)d_in[11];
    const float* msg_b1 = (const float*)d_in[12];
    const float* msg_w2 = (const float*)d_in[13];
    const float* msg_b2 = (const float*)d_in[14];
    const float* upd_w1 = (const float*)d_in[15];
    const float* upd_b1 = (const float*)d_in[16];
    const float* upd_w2 = (const float*)d_in[17];
    const float* upd_b2 = (const float*)d_in[18];
    const float* mln_g  = (const float*)d_in[19];
    const float* mln_b  = (const float*)d_in[20];
    const float* bc_w   = (const float*)d_in[21];
    const float* bc_b   = (const float*)d_in[22];
    const float* fln_g  = (const float*)d_in[23];
    const float* fln_b  = (const float*)d_in[24];
    const float* head_w = (const float*)d_in[25];
    float* out = (float*)d_out;

    const int SMEM_LOCAL = (128 * SXL) * 4;   // 67584 B
    const int SMEM_MSG   = (160 * SXL) * 4;   // 84480 B
    cudaFuncSetAttribute(k_local, cudaFuncAttributeMaxDynamicSharedMemorySize, SMEM_LOCAL);
    cudaFuncSetAttribute(k_msgf,  cudaFuncAttributeMaxDynamicSharedMemorySize, SMEM_MSG);

    k_pack_all<<<416, 256>>>(lw1, lw2, head_w, msg_w1, msg_w2, upd_w1, upd_w2, bc_w);

    k_local<<<NTOK / 64, 256, SMEM_LOCAL>>>(x, emb, pos, lb1, lb2,
                                            lln_g, lln_b, pool_w, pool_b);

    // rounds: A->B, B->A, A->(bc)  (last round writes g_bcb, skips hout)
    for (int r = 0; r < 3; ++r) {
        const int useA = (r % 2 == 0) ? 1 : 0;
        const int last = (r == 2) ? 1 : 0;
        k_msgf<<<ROWS / 32, 256, SMEM_MSG>>>(useA, last, msg_b1, msg_b2,
                                             upd_b1, upd_b2, mln_g, mln_b, bc_b);
    }

    k_head<<<NTOK / 64, 256>>>(fln_g, fln_b, out);
}

// round 11
// speedup vs baseline: 1.0629x; 1.0421x over previous
#include <cuda_runtime.h>

#define Dm 128
#define Hm 256
#define ROWS 16384   /* 16 * 1024 chunks */
#define NTOK 131072  /* 16 * 8192 tokens */
#define EPSf 1e-5f

typedef unsigned long long u64;
typedef unsigned int u32;

// ---- scratch (device globals; no allocation) ----
__device__ float g_local[NTOK * Dm];   // 64 MB
__device__ float g_hA[ROWS * Dm];      // 8 MB
__device__ float g_hB[ROWS * Dm];      // 8 MB
__device__ float g_bcb[ROWS * Dm];     // 8 MB
// packed tf32 weight fragments
__device__ float2 g_w1p[16 * 32 * 32]; // lw1 128x256
__device__ float2 g_w2p[32 * 16 * 32]; // lw2 256x128
__device__ float2 g_hwp[16 * 32 * 32]; // head_w 128x256
// 128x128 mats: [0]=w1self [1]=w1nbr [2]=mw2 [3]=uw1a [4]=uw1b [5]=uw2 [6]=bc_w
__device__ float2 g_mwp[7 * 8192];

// ---- packed f32x2 helpers (scalar path) ----
__device__ __forceinline__ u64 pk2(float x, float y) {
    u64 r; asm("mov.b64 %0, {%1, %2};" : "=l"(r) : "f"(x), "f"(y)); return r;
}
__device__ __forceinline__ u64 dup_f(float a) {
    u64 r; asm("mov.b64 %0, {%1, %1};" : "=l"(r) : "f"(a)); return r;
}
__device__ __forceinline__ void fma2(u64& d, u64 a, u64 b) {
    asm("fma.rn.f32x2 %0, %1, %2, %0;" : "+l"(d) : "l"(a), "l"(b));
}
__device__ __forceinline__ float2 u2f(u64 v) {
    float2 r; asm("mov.b64 {%0, %1}, %2;" : "=f"(r.x), "=f"(r.y) : "l"(v)); return r;
}

// ---- tf32 helpers ----
__device__ __forceinline__ u32 f2tf(float f) {
    u32 r; asm("cvt.rna.tf32.f32 %0, %1;" : "=r"(r) : "f"(f)); return r;
}
__device__ __forceinline__ float f2tff(float f) { return __uint_as_float(f2tf(f)); }

// mma.sync m16n8k8 tf32
__device__ __forceinline__ void mma8(float4& c, const u32 a[4], u32 b0, u32 b1) {
    asm volatile(
        "mma.sync.aligned.m16n8k8.row.col.f32.tf32.tf32.f32 "
        "{%0,%1,%2,%3}, {%4,%5,%6,%7}, {%8,%9}, {%0,%1,%2,%3};"
        : "+f"(c.x), "+f"(c.y), "+f"(c.z), "+f"(c.w)
        : "r"(a[0]), "r"(a[1]), "r"(a[2]), "r"(a[3]), "r"(b0), "r"(b1));
}

template<int STRIDE>
__device__ __forceinline__ void ldA_raw(const float* ap, u32 a[4]) {
    a[0] = __float_as_uint(ap[0]);
    a[1] = __float_as_uint(ap[8 * STRIDE]);
    a[2] = __float_as_uint(ap[4]);
    a[3] = __float_as_uint(ap[8 * STRIDE + 4]);
}

__device__ __forceinline__ float wsum(float v) {
#pragma unroll
    for (int o = 16; o; o >>= 1) v += __shfl_xor_sync(0xffffffffu, v, o);
    return v;
}
__device__ __forceinline__ float gelu_f(float x) {
    return 0.5f * x * (1.0f + erff(x * 0.70710678118f));
}

__device__ __forceinline__ float4 ln_f4(float4 h, const float* __restrict__ g,
                                        const float* __restrict__ b, int lane) {
    const float mu = wsum(h.x + h.y + h.z + h.w) * (1.0f / 128.0f);
    const float a0 = h.x - mu, a1 = h.y - mu, a2 = h.z - mu, a3 = h.w - mu;
    const float var = wsum(a0 * a0 + a1 * a1 + a2 * a2 + a3 * a3) * (1.0f / 128.0f);
    const float rs = rsqrtf(var + EPSf);
    const int dd = lane * 4;
    const float4 gg = *(const float4*)(g + dd);
    const float4 bb = *(const float4*)(b + dd);
    return make_float4(a0 * rs * gg.x + bb.x, a1 * rs * gg.y + bb.y,
                       a2 * rs * gg.z + bb.z, a3 * rs * gg.w + bb.w);
}

// ---- scalar register-tiled GEMM accumulate (pool only) ----
template<int KDIM, int RPT, int NCP>
__device__ __forceinline__ void mm_acc(const float* __restrict__ s,
                                       const float* __restrict__ W, const int ldw,
                                       u64 acc[RPT][NCP]) {
#pragma unroll 2
    for (int d = 0; d < KDIM; d += 2) {
        u64 w0[NCP], w1[NCP];
        if constexpr (NCP >= 2) {
#pragma unroll
            for (int c = 0; c < NCP; c += 2) {
                const ulonglong2 t0 = *(const ulonglong2*)(W + d * ldw + c * 2);
                const ulonglong2 t1 = *(const ulonglong2*)(W + (d + 1) * ldw + c * 2);
                w0[c] = t0.x; w0[c + 1] = t0.y;
                w1[c] = t1.x; w1[c + 1] = t1.y;
            }
        } else {
            w0[0] = *(const u64*)(W + d * ldw);
            w1[0] = *(const u64*)(W + (d + 1) * ldw);
        }
#pragma unroll
        for (int r = 0; r < RPT; ++r) {
            const float2 a = *(const float2*)(s + r * KDIM + d);
            const u64 a0 = dup_f(a.x), a1 = dup_f(a.y);
#pragma unroll
            for (int c = 0; c < NCP; ++c) {
                fma2(acc[r][c], a0, w0[c]);
                fma2(acc[r][c], a1, w1[c]);
            }
        }
    }
}

// ============================================================
// K0: fused pack of all weights into tf32 B-fragment order
// ============================================================
__device__ __forceinline__ void pack_one(const float* __restrict__ W,
                                         float2* __restrict__ P,
                                         int N, int idx) {
    const int lane = idx & 31;
    const int t = idx >> 5;
    const int nt = t % (N / 8);
    const int ks = t / (N / 8);
    const int k = ks * 8 + (lane & 3);
    const int n = nt * 8 + (lane >> 2);
    P[idx] = make_float2(f2tff(W[k * N + n]), f2tff(W[(k + 4) * N + n]));
}

__global__ __launch_bounds__(256) void k_pack_all(
    const float* __restrict__ lw1, const float* __restrict__ lw2,
    const float* __restrict__ hw,  const float* __restrict__ mw1,
    const float* __restrict__ mw2, const float* __restrict__ uw1,
    const float* __restrict__ uw2, const float* __restrict__ bcw)
{
    const int b = blockIdx.x, tid = threadIdx.x;
    if      (b < 64)  pack_one(lw1, g_w1p, 256, b * 256 + tid);
    else if (b < 128) pack_one(lw2, g_w2p, 128, (b - 64) * 256 + tid);
    else if (b < 192) pack_one(hw,  g_hwp, 256, (b - 128) * 256 + tid);
    else if (b < 224) pack_one(mw1,           g_mwp + 0 * 8192, 128, (b - 192) * 256 + tid);
    else if (b < 256) pack_one(mw1 + 16384,   g_mwp + 1 * 8192, 128, (b - 224) * 256 + tid);
    else if (b < 288) pack_one(mw2,           g_mwp + 2 * 8192, 128, (b - 256) * 256 + tid);
    else if (b < 320) pack_one(uw1,           g_mwp + 3 * 8192, 128, (b - 288) * 256 + tid);
    else if (b < 352) pack_one(uw1 + 16384,   g_mwp + 4 * 8192, 128, (b - 320) * 256 + tid);
    else if (b < 384) pack_one(uw2,           g_mwp + 5 * 8192, 128, (b - 352) * 256 + tid);
    else              pack_one(bcw,           g_mwp + 6 * 8192, 128, (b - 384) * 256 + tid);
}

// ============================================================
// K1: local = h + MLP2(LN(h)) + fused pool/summ (tensor-core)
// R8 geometry: 64 tokens/block, 256 threads, ~98KB dyn smem
// ============================================================
#define SXL 132
#define SHL 260
__global__ __launch_bounds__(256, 2) void k_local(
    const int* __restrict__ x, const float* __restrict__ emb, const float* __restrict__ pos,
    const float* __restrict__ lb1, const float* __restrict__ lb2,
    const float* __restrict__ lng, const float* __restrict__ lnb,
    const float* __restrict__ pw, const float* __restrict__ pb)
{
    extern __shared__ float sm[];
    float* s_x = sm;                // 64 x 132
    float* s_h = sm + 64 * SXL;     // 64 x 260
    const int tid = threadIdx.x, wid = tid >> 5, lane = tid & 31;
    const int gt0 = blockIdx.x * 64;
    const int frow = lane >> 2, fcol = lane & 3;

    // phase 1: LN per token -> tf32 in s_x
#pragma unroll
    for (int tt = 0; tt < 8; ++tt) {
        const int tl = wid * 8 + tt, gt = gt0 + tl;
        const int xt = __ldg(x + gt);
        const float4 e = *(const float4*)(emb + xt * Dm + lane * 4);
        const float4 p = *(const float4*)(pos + (gt & 7) * Dm + lane * 4);
        const float4 h = make_float4(e.x + p.x, e.y + p.y, e.z + p.z, e.w + p.w);
        const float4 v = ln_f4(h, lng, lnb, lane);
        float* dst = s_x + tl * SXL + lane * 4;
        dst[0] = f2tff(v.x); dst[1] = f2tff(v.y); dst[2] = f2tff(v.z); dst[3] = f2tff(v.w);
    }
    __syncthreads();

    const int mg = (wid >> 2) * 32;   // 2 m-groups of 32 rows
    const int ng = (wid & 3);         // 4 n-groups

    // phase 2: hid = gelu(xln @ lw1 + b1) -> tf32 in s_h (cols ng*64..+63)
    {
        float4 acc[2][8];
#pragma unroll
        for (int nt = 0; nt < 8; ++nt) {
            const int gc = ng * 64 + nt * 8 + 2 * fcol;
            const float b0 = lb1[gc], b1v = lb1[gc + 1];
#pragma unroll
            for (int mt = 0; mt < 2; ++mt) acc[mt][nt] = make_float4(b0, b1v, b0, b1v);
        }
#pragma unroll 4
        for (int ks = 0; ks < 16; ++ks) {
            u32 a[2][4];
#pragma unroll
            for (int mt = 0; mt < 2; ++mt)
                ldA_raw<SXL>(s_x + (mg + mt * 16 + frow) * SXL + ks * 8 + fcol, a[mt]);
#pragma unroll
            for (int nt = 0; nt < 8; ++nt) {
                const float2 b = g_w1p[(ks * 32 + ng * 8 + nt) * 32 + lane];
#pragma unroll
                for (int mt = 0; mt < 2; ++mt)
                    mma8(acc[mt][nt], a[mt], __float_as_uint(b.x), __float_as_uint(b.y));
            }
        }
#pragma unroll
        for (int mt = 0; mt < 2; ++mt) {
            const int rg = mg + mt * 16 + frow;
#pragma unroll
            for (int nt = 0; nt < 8; ++nt) {
                const int gc = ng * 64 + nt * 8 + 2 * fcol;
                *(float2*)(s_h + rg * SHL + gc) =
                    make_float2(f2tff(gelu_f(acc[mt][nt].x)), f2tff(gelu_f(acc[mt][nt].y)));
                *(float2*)(s_h + (rg + 8) * SHL + gc) =
                    make_float2(f2tff(gelu_f(acc[mt][nt].z)), f2tff(gelu_f(acc[mt][nt].w)));
            }
        }
    }
    __syncthreads();

    // phase 3: local = h + hid @ lw2 + b2 -> g_local and s_x (fp32)
    {
        float4 acc[2][4];
#pragma unroll
        for (int nt = 0; nt < 4; ++nt) {
            const int gc = ng * 32 + nt * 8 + 2 * fcol;
            const float b0 = lb2[gc], b1v = lb2[gc + 1];
#pragma unroll
            for (int mt = 0; mt < 2; ++mt) acc[mt][nt] = make_float4(b0, b1v, b0, b1v);
        }
#pragma unroll 4
        for (int ks = 0; ks < 32; ++ks) {
            u32 a[2][4];
#pragma unroll
            for (int mt = 0; mt < 2; ++mt)
                ldA_raw<SHL>(s_h + (mg + mt * 16 + frow) * SHL + ks * 8 + fcol, a[mt]);
#pragma unroll
            for (int nt = 0; nt < 4; ++nt) {
                const float2 b = g_w2p[(ks * 16 + ng * 4 + nt) * 32 + lane];
#pragma unroll
                for (int mt = 0; mt < 2; ++mt)
                    mma8(acc[mt][nt], a[mt], __float_as_uint(b.x), __float_as_uint(b.y));
            }
        }
#pragma unroll
        for (int mt = 0; mt < 2; ++mt) {
#pragma unroll
            for (int rr = 0; rr < 2; ++rr) {
                const int tl = mg + mt * 16 + frow + rr * 8;
                const int gt = gt0 + tl;
                const int xt = __ldg(x + gt);
#pragma unroll
                for (int nt = 0; nt < 4; ++nt) {
                    const int gc = ng * 32 + nt * 8 + 2 * fcol;
                    const float2 e = *(const float2*)(emb + xt * Dm + gc);
                    const float2 p = *(const float2*)(pos + (gt & 7) * Dm + gc);
                    const float cx = rr ? acc[mt][nt].z : acc[mt][nt].x;
                    const float cy = rr ? acc[mt][nt].w : acc[mt][nt].y;
                    const float2 o = make_float2(e.x + p.x + cx, e.y + p.y + cy);
                    *(float2*)(g_local + gt * Dm + gc) = o;
                    *(float2*)(s_x + tl * SXL + gc) = o;
                }
            }
        }
    }
    __syncthreads();

    // phase 4: chunk means (8 chunks) -> s_h[0:1024]
#pragma unroll
    for (int it = 0; it < 4; ++it) {
        const int idx = tid + it * 256;
        const int c = idx >> 7, dd = idx & 127;
        float s = 0.f;
#pragma unroll
        for (int t = 0; t < 8; ++t) s += s_x[(c * 8 + t) * SXL + dd];
        s_h[c * 128 + dd] = s * 0.125f;
    }
    __syncthreads();

    // phase 5: summ = mean @ pool_w + pool_b -> g_hA (warp per chunk)
    {
        const int j0 = lane * 4;
        u64 acc1[1][2];
        acc1[0][0] = pk2(pb[j0], pb[j0 + 1]);
        acc1[0][1] = pk2(pb[j0 + 2], pb[j0 + 3]);
        mm_acc<128, 1, 2>(s_h + wid * 128, pw + j0, 128, acc1);
        const float2 v0 = u2f(acc1[0][0]), v1 = u2f(acc1[0][1]);
        *(float4*)(g_hA + (blockIdx.x * 8 + wid) * Dm + j0) =
            make_float4(v0.x, v0.y, v1.x, v1.y);
    }
}

// ============================================================
// K2: FUSED msg round, 256 threads / 8 warps, 32 rows (+4 halo)
// smem 84.5KB -> 2 CTAs/SM. grid 512. 5 block barriers.
// ============================================================
__global__ __launch_bounds__(256) void k_msgf(
    int useA, int last,
    const float* __restrict__ mb1, const float* __restrict__ mb2,
    const float* __restrict__ ub1, const float* __restrict__ ub2,
    const float* __restrict__ lg, const float* __restrict__ lb,
    const float* __restrict__ bcb)
{
    const float* __restrict__ hin = useA ? g_hA : g_hB;
    float* __restrict__ hout = useA ? g_hB : g_hA;
    extern __shared__ float sm[];
    float* s_hmt = sm;             // 48 rows tf32 hmsg (v = row-(r0-4))
    float* s_pn  = sm + 48 * SXL;  // 48 rows nbr-proj; rows 0..31 alias agg
    float* s_ps  = sm + 96 * SXL;  // 32 rows self-proj; alias uh
    float* s_hs  = sm + 128 * SXL; // 32 rows gelu-sum; alias pre-LN fp32
    float* s_ag  = s_pn;
    float* s_uh  = s_ps;
    float* s_pl  = s_hs;
    const int tid = threadIdx.x, wid = tid >> 5, lane = tid & 31;
    const int r0 = blockIdx.x * 32;
    const int frow = lane >> 2, fcol = lane & 3;
    const int ng = wid & 3;            // 4 n-groups of 32 cols
    const int mgrp = wid >> 2;         // 2 m-groups of 16 rows (phases P3+)
    const int mrow = mgrp * 16;

    // P0: load 48 halo rows of hmsg as tf32 (clamped)
#pragma unroll
    for (int it = 0; it < 24; ++it) {
        const int idx = tid + it * 256;
        const int v = idx >> 7, j = idx & 127;
        int row = r0 - 4 + v;
        row = row < 0 ? 0 : (row > ROWS - 1 ? ROWS - 1 : row);
        s_hmt[v * SXL + j] = f2tff(hin[row * Dm + j]);
    }
    __syncthreads();

    // P1: warps 0-3: self-proj (2 m-tiles, v=4..35); warps 4-7: nbr-proj (3 m-tiles, v=0..47)
    if (mgrp == 0) {
        float4 acc[2][4];
#pragma unroll
        for (int mt = 0; mt < 2; ++mt)
#pragma unroll
            for (int nt = 0; nt < 4; ++nt) acc[mt][nt] = make_float4(0.f, 0.f, 0.f, 0.f);
#pragma unroll 4
        for (int ks = 0; ks < 16; ++ks) {
            u32 a[2][4];
#pragma unroll
            for (int mt = 0; mt < 2; ++mt)
                ldA_raw<SXL>(s_hmt + (4 + mt * 16 + frow) * SXL + ks * 8 + fcol, a[mt]);
#pragma unroll
            for (int nt = 0; nt < 4; ++nt) {
                const float2 b = g_mwp[0 * 8192 + (ks * 16 + ng * 4 + nt) * 32 + lane];
#pragma unroll
                for (int mt = 0; mt < 2; ++mt)
                    mma8(acc[mt][nt], a[mt], __float_as_uint(b.x), __float_as_uint(b.y));
            }
        }
#pragma unroll
        for (int mt = 0; mt < 2; ++mt) {
            const int r = mt * 16 + frow;
#pragma unroll
            for (int nt = 0; nt < 4; ++nt) {
                const int gc = ng * 32 + nt * 8 + 2 * fcol;
                *(float2*)(s_ps + r * SXL + gc)       = make_float2(acc[mt][nt].x, acc[mt][nt].y);
                *(float2*)(s_ps + (r + 8) * SXL + gc) = make_float2(acc[mt][nt].z, acc[mt][nt].w);
            }
        }
    } else {
        float4 acc[3][4];
#pragma unroll
        for (int mt = 0; mt < 3; ++mt)
#pragma unroll
            for (int nt = 0; nt < 4; ++nt) acc[mt][nt] = make_float4(0.f, 0.f, 0.f, 0.f);
#pragma unroll 4
        for (int ks = 0; ks < 16; ++ks) {
            u32 a[3][4];
#pragma unroll
            for (int mt = 0; mt < 3; ++mt)
                ldA_raw<SXL>(s_hmt + (mt * 16 + frow) * SXL + ks * 8 + fcol, a[mt]);
#pragma unroll
            for (int nt = 0; nt < 4; ++nt) {
                const float2 b = g_mwp[1 * 8192 + (ks * 16 + ng * 4 + nt) * 32 + lane];
#pragma unroll
                for (int mt = 0; mt < 3; ++mt)
                    mma8(acc[mt][nt], a[mt], __float_as_uint(b.x), __float_as_uint(b.y));
            }
        }
#pragma unroll
        for (int mt = 0; mt < 3; ++mt) {
            const int v = mt * 16 + frow;
#pragma unroll
            for (int nt = 0; nt < 4; ++nt) {
                const int gc = ng * 32 + nt * 8 + 2 * fcol;
                *(float2*)(s_pn + v * SXL + gc)       = make_float2(acc[mt][nt].x, acc[mt][nt].y);
                *(float2*)(s_pn + (v + 8) * SXL + gc) = make_float2(acc[mt][nt].z, acc[mt][nt].w);
            }
        }
    }
    __syncthreads();

    // P2: gelu-sum -> s_hs (tf32)
#pragma unroll
    for (int it = 0; it < 16; ++it) {
        const int idx = tid + it * 256;
        const int r = idx >> 7, j = idx & 127;
        const int i = (r0 + r) & 1023;
        const float ps_b = s_ps[r * SXL + j] + mb1[j];
        float a = 0.f;
#pragma unroll
        for (int dd = 0; dd < 5; ++dd) {
            if (i >= dd) a += gelu_f(ps_b + s_pn[(r + 4 - dd) * SXL + j]);
        }
        s_hs[r * SXL + j] = f2tff(a);
    }
    __syncthreads();

    // P3: agg = (HS @ mw2)/count + b2 -> s_ag (tf32; alias s_pn rows 0..31)
    // (no interior barrier: s_pn last read in P2, already synced; MMA reads s_hs only)
    {
        float4 acc[4];
#pragma unroll
        for (int nt = 0; nt < 4; ++nt) acc[nt] = make_float4(0.f, 0.f, 0.f, 0.f);
#pragma unroll 4
        for (int ks = 0; ks < 16; ++ks) {
            u32 a[4];
            ldA_raw<SXL>(s_hs + (mrow + frow) * SXL + ks * 8 + fcol, a);
#pragma unroll
            for (int nt = 0; nt < 4; ++nt) {
                const float2 b = g_mwp[2 * 8192 + (ks * 16 + ng * 4 + nt) * 32 + lane];
                mma8(acc[nt], a, __float_as_uint(b.x), __float_as_uint(b.y));
            }
        }
        const int rA = mrow + frow;
        const int iA = (r0 + rA) & 1023, iB = (r0 + rA + 8) & 1023;
        const float invA = 1.0f / ((iA + 1) < 5 ? (float)(iA + 1) : 5.0f);
        const float invB = 1.0f / ((iB + 1) < 5 ? (float)(iB + 1) : 5.0f);
#pragma unroll
        for (int nt = 0; nt < 4; ++nt) {
            const int gc = ng * 32 + nt * 8 + 2 * fcol;
            const float b20 = mb2[gc], b21 = mb2[gc + 1];
            *(float2*)(s_ag + rA * SXL + gc) =
                make_float2(f2tff(acc[nt].x * invA + b20), f2tff(acc[nt].y * invA + b21));
            *(float2*)(s_ag + (rA + 8) * SXL + gc) =
                make_float2(f2tff(acc[nt].z * invB + b20), f2tff(acc[nt].w * invB + b21));
        }
    }
    __syncthreads();

    // P4: uh = gelu(HMT @ uw1a + AG @ uw1b + ub1) -> s_uh (tf32; alias s_ps)
    // (no interior barrier: s_ps last read in P2)
    {
        float4 acc[4];
#pragma unroll
        for (int nt = 0; nt < 4; ++nt) {
            const int gc = ng * 32 + nt * 8 + 2 * fcol;
            acc[nt] = make_float4(ub1[gc], ub1[gc + 1], ub1[gc], ub1[gc + 1]);
        }
#pragma unroll 4
        for (int ks = 0; ks < 16; ++ks) {
            u32 a[4];
            ldA_raw<SXL>(s_hmt + (4 + mrow + frow) * SXL + ks * 8 + fcol, a);
#pragma unroll
            for (int nt = 0; nt < 4; ++nt) {
                const float2 b = g_mwp[3 * 8192 + (ks * 16 + ng * 4 + nt) * 32 + lane];
                mma8(acc[nt], a, __float_as_uint(b.x), __float_as_uint(b.y));
            }
        }
#pragma unroll 4
        for (int ks = 0; ks < 16; ++ks) {
            u32 a[4];
            ldA_raw<SXL>(s_ag + (mrow + frow) * SXL + ks * 8 + fcol, a);
#pragma unroll
            for (int nt = 0; nt < 4; ++nt) {
                const float2 b = g_mwp[4 * 8192 + (ks * 16 + ng * 4 + nt) * 32 + lane];
                mma8(acc[nt], a, __float_as_uint(b.x), __float_as_uint(b.y));
            }
        }
        const int rA = mrow + frow;
#pragma unroll
        for (int nt = 0; nt < 4; ++nt) {
            const int gc = ng * 32 + nt * 8 + 2 * fcol;
            *(float2*)(s_uh + rA * SXL + gc) =
                make_float2(f2tff(gelu_f(acc[nt].x)), f2tff(gelu_f(acc[nt].y)));
            *(float2*)(s_uh + (rA + 8) * SXL + gc) =
                make_float2(f2tff(gelu_f(acc[nt].z)), f2tff(gelu_f(acc[nt].w)));
        }
    }
    __syncthreads();

    // P5: pre-LN = hmsg + UH @ uw2 + ub2 -> s_pl (fp32; alias s_hs)
    // (no interior barrier: s_hs last read in P3, synced since)
    {
        float4 acc[4];
#pragma unroll
        for (int nt = 0; nt < 4; ++nt) {
            const int gc = ng * 32 + nt * 8 + 2 * fcol;
            acc[nt] = make_float4(ub2[gc], ub2[gc + 1], ub2[gc], ub2[gc + 1]);
        }
#pragma unroll 4
        for (int ks = 0; ks < 16; ++ks) {
            u32 a[4];
            ldA_raw<SXL>(s_uh + (mrow + frow) * SXL + ks * 8 + fcol, a);
#pragma unroll
            for (int nt = 0; nt < 4; ++nt) {
                const float2 b = g_mwp[5 * 8192 + (ks * 16 + ng * 4 + nt) * 32 + lane];
                mma8(acc[nt], a, __float_as_uint(b.x), __float_as_uint(b.y));
            }
        }
        const int rA = mrow + frow;
#pragma unroll
        for (int nt = 0; nt < 4; ++nt) {
            const int gc = ng * 32 + nt * 8 + 2 * fcol;
            const float2 h0 = *(const float2*)(s_hmt + (4 + rA) * SXL + gc);
            const float2 h1 = *(const float2*)(s_hmt + (12 + rA) * SXL + gc);
            *(float2*)(s_pl + rA * SXL + gc) =
                make_float2(h0.x + acc[nt].x, h0.y + acc[nt].y);
            *(float2*)(s_pl + (rA + 8) * SXL + gc) =
                make_float2(h1.x + acc[nt].z, h1.y + acc[nt].w);
        }
    }
    __syncthreads();

    // P6: LN per row (4 rows/warp). Non-final: -> hout. Final: tf32 -> s_hmt[4+r]
#pragma unroll
    for (int rr = 0; rr < 4; ++rr) {
        const int r = wid * 4 + rr;
        const float4 v0 = *(const float4*)(s_pl + r * SXL + lane * 4);
        const float4 v = ln_f4(v0, lg, lb, lane);
        if (!last) {
            *(float4*)(hout + (r0 + r) * Dm + lane * 4) = v;
        } else {
            float* dst = s_hmt + (4 + r) * SXL + lane * 4;
            dst[0] = f2tff(v.x); dst[1] = f2tff(v.y);
            dst[2] = f2tff(v.z); dst[3] = f2tff(v.w);
        }
    }

    // P7 (final round only): bc = hmsg_final @ bc_w + bc_b -> g_bcb
    if (last) {
        __syncthreads();
        float4 acc[4];
#pragma unroll
        for (int nt = 0; nt < 4; ++nt) {
            const int gc = ng * 32 + nt * 8 + 2 * fcol;
            acc[nt] = make_float4(bcb[gc], bcb[gc + 1], bcb[gc], bcb[gc + 1]);
        }
#pragma unroll 4
        for (int ks = 0; ks < 16; ++ks) {
            u32 a[4];
            ldA_raw<SXL>(s_hmt + (4 + mrow + frow) * SXL + ks * 8 + fcol, a);
#pragma unroll
            for (int nt = 0; nt < 4; ++nt) {
                const float2 b = g_mwp[6 * 8192 + (ks * 16 + ng * 4 + nt) * 32 + lane];
                mma8(acc[nt], a, __float_as_uint(b.x), __float_as_uint(b.y));
            }
        }
        const int rA = r0 + mrow + frow;
#pragma unroll
        for (int nt = 0; nt < 4; ++nt) {
            const int gc = ng * 32 + nt * 8 + 2 * fcol;
            *(float2*)(g_bcb + rA * Dm + gc)       = make_float2(acc[nt].x, acc[nt].y);
            *(float2*)(g_bcb + (rA + 8) * Dm + gc) = make_float2(acc[nt].z, acc[nt].w);
        }
    }
}

// ============================================================
// K5: logits = LN(local + bc) @ head_w (tensor), 64 tok/block
// ============================================================
__global__ __launch_bounds__(256) void k_head(
    const float* __restrict__ lg, const float* __restrict__ lb,
    float* __restrict__ out)
{
    __shared__ float s_x[64 * SXL];
    const int tid = threadIdx.x, wid = tid >> 5, lane = tid & 31;
    const int gt0 = blockIdx.x * 64;
    const int frow = lane >> 2, fcol = lane & 3;

#pragma unroll
    for (int tt = 0; tt < 8; ++tt) {
        const int tl = wid * 8 + tt, gt = gt0 + tl;
        const float4 lv = *(const float4*)(g_local + gt * Dm + lane * 4);
        const float4 bv = *(const float4*)(g_bcb + (gt >> 3) * Dm + lane * 4);
        const float4 h = make_float4(lv.x + bv.x, lv.y + bv.y, lv.z + bv.z, lv.w + bv.w);
        const float4 v = ln_f4(h, lg, lb, lane);
        float* dst = s_x + tl * SXL + lane * 4;
        dst[0] = f2tff(v.x); dst[1] = f2tff(v.y); dst[2] = f2tff(v.z); dst[3] = f2tff(v.w);
    }
    __syncthreads();

    const int mg = (wid >> 2) * 32;
    const int ng = (wid & 3);
    float4 acc[2][8];
#pragma unroll
    for (int mt = 0; mt < 2; ++mt)
#pragma unroll
        for (int nt = 0; nt < 8; ++nt) acc[mt][nt] = make_float4(0.f, 0.f, 0.f, 0.f);

#pragma unroll 4
    for (int ks = 0; ks < 16; ++ks) {
        u32 a[2][4];
#pragma unroll
        for (int mt = 0; mt < 2; ++mt)
            ldA_raw<SXL>(s_x + (mg + mt * 16 + frow) * SXL + ks * 8 + fcol, a[mt]);
#pragma unroll
        for (int nt = 0; nt < 8; ++nt) {
            const float2 b = g_hwp[(ks * 32 + ng * 8 + nt) * 32 + lane];
#pragma unroll
            for (int mt = 0; mt < 2; ++mt)
                mma8(acc[mt][nt], a[mt], __float_as_uint(b.x), __float_as_uint(b.y));
        }
    }

#pragma unroll
    for (int mt = 0; mt < 2; ++mt) {
        const int rg = gt0 + mg + mt * 16 + frow;
#pragma unroll
        for (int nt = 0; nt < 8; ++nt) {
            const int gc = ng * 64 + nt * 8 + 2 * fcol;
            *(float2*)(out + rg * Hm + gc)       = make_float2(acc[mt][nt].x, acc[mt][nt].y);
            *(float2*)(out + (rg + 8) * Hm + gc) = make_float2(acc[mt][nt].z, acc[mt][nt].w);
        }
    }
}

// ============================================================
extern "C" void kernel_launch(void* const* d_in, const int* in_sizes, int n_in,
                              void* d_out, int out_size) {
    const int*   x      = (const int*)  d_in[0];
    const float* emb    = (const float*)d_in[1];
    const float* pos    = (const float*)d_in[2];
    const float* lw1    = (const float*)d_in[3];
    const float* lb1    = (const float*)d_in[4];
    const float* lw2    = (const float*)d_in[5];
    const float* lb2    = (const float*)d_in[6];
    const float* lln_g  = (const float*)d_in[7];
    const float* lln_b  = (const float*)d_in[8];
    const float* pool_w = (const float*)d_in[9];
    const float* pool_b = (const float*)d_in[10];
    const float* msg_w1 = (const float*)d_in[11];
    const float* msg_b1 = (const float*)d_in[12];
    const float* msg_w2 = (const float*)d_in[13];
    const float* msg_b2 = (const float*)d_in[14];
    const float* upd_w1 = (const float*)d_in[15];
    const float* upd_b1 = (const float*)d_in[16];
    const float* upd_w2 = (const float*)d_in[17];
    const float* upd_b2 = (const float*)d_in[18];
    const float* mln_g  = (const float*)d_in[19];
    const float* mln_b  = (const float*)d_in[20];
    const float* bc_w   = (const float*)d_in[21];
    const float* bc_b   = (const float*)d_in[22];
    const float* fln_g  = (const float*)d_in[23];
    const float* fln_b  = (const float*)d_in[24];
    const float* head_w = (const float*)d_in[25];
    float* out = (float*)d_out;

    const int SMEM_LOCAL = (64 * SXL + 64 * SHL) * 4;   // 100352 B
    const int SMEM_MSG   = (160 * SXL) * 4;             // 84480 B
    cudaFuncSetAttribute(k_local, cudaFuncAttributeMaxDynamicSharedMemorySize, SMEM_LOCAL);
    cudaFuncSetAttribute(k_msgf,  cudaFuncAttributeMaxDynamicSharedMemorySize, SMEM_MSG);

    k_pack_all<<<416, 256>>>(lw1, lw2, head_w, msg_w1, msg_w2, upd_w1, upd_w2, bc_w);

    k_local<<<NTOK / 64, 256, SMEM_LOCAL>>>(x, emb, pos, lb1, lb2,
                                            lln_g, lln_b, pool_w, pool_b);

    // rounds: A->B, B->A, A->(bc)  (last round writes g_bcb, skips hout)
    for (int r = 0; r < 3; ++r) {
        const int useA = (r % 2 == 0) ? 1 : 0;
        const int last = (r == 2) ? 1 : 0;
        k_msgf<<<ROWS / 32, 256, SMEM_MSG>>>(useA, last, msg_b1, msg_b2,
                                             upd_b1, upd_b2, mln_g, mln_b, bc_b);
    }

    k_head<<<NTOK / 64, 256>>>(fln_g, fln_b, out);
}

// round 12
// speedup vs baseline: 1.0638x; 1.0009x over previous
#include <cuda_runtime.h>

#define Dm 128
#define Hm 256
#define ROWS 16384   /* 16 * 1024 chunks */
#define NTOK 131072  /* 16 * 8192 tokens */
#define EPSf 1e-5f

typedef unsigned long long u64;
typedef unsigned int u32;

// ---- scratch (device globals; no allocation) ----
__device__ float g_local[NTOK * Dm];   // 64 MB
__device__ float g_hA[ROWS * Dm];      // 8 MB
__device__ float g_hB[ROWS * Dm];      // 8 MB
__device__ float g_bcb[ROWS * Dm];     // 8 MB
// packed tf32 weight fragments
__device__ float2 g_w1p[16 * 32 * 32]; // lw1 128x256
__device__ float2 g_w2p[32 * 16 * 32]; // lw2 256x128
__device__ float2 g_hwp[16 * 32 * 32]; // head_w 128x256
// 128x128 mats: [0]=w1self [1]=w1nbr [2]=mw2 [3]=uw1a [4]=uw1b [5]=uw2 [6]=bc_w
__device__ float2 g_mwp[7 * 8192];

// ---- packed f32x2 helpers (scalar path) ----
__device__ __forceinline__ u64 pk2(float x, float y) {
    u64 r; asm("mov.b64 %0, {%1, %2};" : "=l"(r) : "f"(x), "f"(y)); return r;
}
__device__ __forceinline__ u64 dup_f(float a) {
    u64 r; asm("mov.b64 %0, {%1, %1};" : "=l"(r) : "f"(a)); return r;
}
__device__ __forceinline__ void fma2(u64& d, u64 a, u64 b) {
    asm("fma.rn.f32x2 %0, %1, %2, %0;" : "+l"(d) : "l"(a), "l"(b));
}
__device__ __forceinline__ float2 u2f(u64 v) {
    float2 r; asm("mov.b64 {%0, %1}, %2;" : "=f"(r.x), "=f"(r.y) : "l"(v)); return r;
}

// ---- tf32 helpers ----
__device__ __forceinline__ u32 f2tf(float f) {
    u32 r; asm("cvt.rna.tf32.f32 %0, %1;" : "=r"(r) : "f"(f)); return r;
}
__device__ __forceinline__ float f2tff(float f) { return __uint_as_float(f2tf(f)); }

// mma.sync m16n8k8 tf32
__device__ __forceinline__ void mma8(float4& c, const u32 a[4], u32 b0, u32 b1) {
    asm volatile(
        "mma.sync.aligned.m16n8k8.row.col.f32.tf32.tf32.f32 "
        "{%0,%1,%2,%3}, {%4,%5,%6,%7}, {%8,%9}, {%0,%1,%2,%3};"
        : "+f"(c.x), "+f"(c.y), "+f"(c.z), "+f"(c.w)
        : "r"(a[0]), "r"(a[1]), "r"(a[2]), "r"(a[3]), "r"(b0), "r"(b1));
}

template<int STRIDE>
__device__ __forceinline__ void ldA_raw(const float* ap, u32 a[4]) {
    a[0] = __float_as_uint(ap[0]);
    a[1] = __float_as_uint(ap[8 * STRIDE]);
    a[2] = __float_as_uint(ap[4]);
    a[3] = __float_as_uint(ap[8 * STRIDE + 4]);
}

__device__ __forceinline__ float wsum(float v) {
#pragma unroll
    for (int o = 16; o; o >>= 1) v += __shfl_xor_sync(0xffffffffu, v, o);
    return v;
}
__device__ __forceinline__ float gelu_f(float x) {
    return 0.5f * x * (1.0f + erff(x * 0.70710678118f));
}

__device__ __forceinline__ float4 ln_f4(float4 h, const float* __restrict__ g,
                                        const float* __restrict__ b, int lane) {
    const float mu = wsum(h.x + h.y + h.z + h.w) * (1.0f / 128.0f);
    const float a0 = h.x - mu, a1 = h.y - mu, a2 = h.z - mu, a3 = h.w - mu;
    const float var = wsum(a0 * a0 + a1 * a1 + a2 * a2 + a3 * a3) * (1.0f / 128.0f);
    const float rs = rsqrtf(var + EPSf);
    const int dd = lane * 4;
    const float4 gg = *(const float4*)(g + dd);
    const float4 bb = *(const float4*)(b + dd);
    return make_float4(a0 * rs * gg.x + bb.x, a1 * rs * gg.y + bb.y,
                       a2 * rs * gg.z + bb.z, a3 * rs * gg.w + bb.w);
}

// ---- scalar register-tiled GEMM accumulate (pool only) ----
template<int KDIM, int RPT, int NCP>
__device__ __forceinline__ void mm_acc(const float* __restrict__ s,
                                       const float* __restrict__ W, const int ldw,
                                       u64 acc[RPT][NCP]) {
#pragma unroll 2
    for (int d = 0; d < KDIM; d += 2) {
        u64 w0[NCP], w1[NCP];
        if constexpr (NCP >= 2) {
#pragma unroll
            for (int c = 0; c < NCP; c += 2) {
                const ulonglong2 t0 = *(const ulonglong2*)(W + d * ldw + c * 2);
                const ulonglong2 t1 = *(const ulonglong2*)(W + (d + 1) * ldw + c * 2);
                w0[c] = t0.x; w0[c + 1] = t0.y;
                w1[c] = t1.x; w1[c + 1] = t1.y;
            }
        } else {
            w0[0] = *(const u64*)(W + d * ldw);
            w1[0] = *(const u64*)(W + (d + 1) * ldw);
        }
#pragma unroll
        for (int r = 0; r < RPT; ++r) {
            const float2 a = *(const float2*)(s + r * KDIM + d);
            const u64 a0 = dup_f(a.x), a1 = dup_f(a.y);
#pragma unroll
            for (int c = 0; c < NCP; ++c) {
                fma2(acc[r][c], a0, w0[c]);
                fma2(acc[r][c], a1, w1[c]);
            }
        }
    }
}

// ============================================================
// K0: fused pack of all weights into tf32 B-fragment order
// ============================================================
__device__ __forceinline__ void pack_one(const float* __restrict__ W,
                                         float2* __restrict__ P,
                                         int N, int idx) {
    const int lane = idx & 31;
    const int t = idx >> 5;
    const int nt = t % (N / 8);
    const int ks = t / (N / 8);
    const int k = ks * 8 + (lane & 3);
    const int n = nt * 8 + (lane >> 2);
    P[idx] = make_float2(f2tff(W[k * N + n]), f2tff(W[(k + 4) * N + n]));
}

__global__ __launch_bounds__(256) void k_pack_all(
    const float* __restrict__ lw1, const float* __restrict__ lw2,
    const float* __restrict__ hw,  const float* __restrict__ mw1,
    const float* __restrict__ mw2, const float* __restrict__ uw1,
    const float* __restrict__ uw2, const float* __restrict__ bcw)
{
    const int b = blockIdx.x, tid = threadIdx.x;
    if      (b < 64)  pack_one(lw1, g_w1p, 256, b * 256 + tid);
    else if (b < 128) pack_one(lw2, g_w2p, 128, (b - 64) * 256 + tid);
    else if (b < 192) pack_one(hw,  g_hwp, 256, (b - 128) * 256 + tid);
    else if (b < 224) pack_one(mw1,           g_mwp + 0 * 8192, 128, (b - 192) * 256 + tid);
    else if (b < 256) pack_one(mw1 + 16384,   g_mwp + 1 * 8192, 128, (b - 224) * 256 + tid);
    else if (b < 288) pack_one(mw2,           g_mwp + 2 * 8192, 128, (b - 256) * 256 + tid);
    else if (b < 320) pack_one(uw1,           g_mwp + 3 * 8192, 128, (b - 288) * 256 + tid);
    else if (b < 352) pack_one(uw1 + 16384,   g_mwp + 4 * 8192, 128, (b - 320) * 256 + tid);
    else if (b < 384) pack_one(uw2,           g_mwp + 5 * 8192, 128, (b - 352) * 256 + tid);
    else              pack_one(bcw,           g_mwp + 6 * 8192, 128, (b - 384) * 256 + tid);
}

// ============================================================
// K1: local = h + MLP2(LN(h)) + fused pool/summ (tensor-core)
// R8 geometry: 64 tokens/block, 256 threads, ~98KB dyn smem
// ============================================================
#define SXL 132
#define SHL 260
__global__ __launch_bounds__(256, 2) void k_local(
    const int* __restrict__ x, const float* __restrict__ emb, const float* __restrict__ pos,
    const float* __restrict__ lb1, const float* __restrict__ lb2,
    const float* __restrict__ lng, const float* __restrict__ lnb,
    const float* __restrict__ pw, const float* __restrict__ pb)
{
    extern __shared__ float sm[];
    float* s_x = sm;                // 64 x 132
    float* s_h = sm + 64 * SXL;     // 64 x 260
    const int tid = threadIdx.x, wid = tid >> 5, lane = tid & 31;
    const int gt0 = blockIdx.x * 64;
    const int frow = lane >> 2, fcol = lane & 3;

    // phase 1: LN per token -> tf32 in s_x
#pragma unroll
    for (int tt = 0; tt < 8; ++tt) {
        const int tl = wid * 8 + tt, gt = gt0 + tl;
        const int xt = __ldg(x + gt);
        const float4 e = *(const float4*)(emb + xt * Dm + lane * 4);
        const float4 p = *(const float4*)(pos + (gt & 7) * Dm + lane * 4);
        const float4 h = make_float4(e.x + p.x, e.y + p.y, e.z + p.z, e.w + p.w);
        const float4 v = ln_f4(h, lng, lnb, lane);
        float* dst = s_x + tl * SXL + lane * 4;
        dst[0] = f2tff(v.x); dst[1] = f2tff(v.y); dst[2] = f2tff(v.z); dst[3] = f2tff(v.w);
    }
    __syncthreads();

    const int mg = (wid >> 2) * 32;   // 2 m-groups of 32 rows
    const int ng = (wid & 3);         // 4 n-groups

    // phase 2: hid = gelu(xln @ lw1 + b1) -> tf32 in s_h (cols ng*64..+63)
    {
        float4 acc[2][8];
#pragma unroll
        for (int nt = 0; nt < 8; ++nt) {
            const int gc = ng * 64 + nt * 8 + 2 * fcol;
            const float b0 = lb1[gc], b1v = lb1[gc + 1];
#pragma unroll
            for (int mt = 0; mt < 2; ++mt) acc[mt][nt] = make_float4(b0, b1v, b0, b1v);
        }
#pragma unroll 4
        for (int ks = 0; ks < 16; ++ks) {
            u32 a[2][4];
#pragma unroll
            for (int mt = 0; mt < 2; ++mt)
                ldA_raw<SXL>(s_x + (mg + mt * 16 + frow) * SXL + ks * 8 + fcol, a[mt]);
#pragma unroll
            for (int nt = 0; nt < 8; ++nt) {
                const float2 b = g_w1p[(ks * 32 + ng * 8 + nt) * 32 + lane];
#pragma unroll
                for (int mt = 0; mt < 2; ++mt)
                    mma8(acc[mt][nt], a[mt], __float_as_uint(b.x), __float_as_uint(b.y));
            }
        }
#pragma unroll
        for (int mt = 0; mt < 2; ++mt) {
            const int rg = mg + mt * 16 + frow;
#pragma unroll
            for (int nt = 0; nt < 8; ++nt) {
                const int gc = ng * 64 + nt * 8 + 2 * fcol;
                *(float2*)(s_h + rg * SHL + gc) =
                    make_float2(f2tff(gelu_f(acc[mt][nt].x)), f2tff(gelu_f(acc[mt][nt].y)));
                *(float2*)(s_h + (rg + 8) * SHL + gc) =
                    make_float2(f2tff(gelu_f(acc[mt][nt].z)), f2tff(gelu_f(acc[mt][nt].w)));
            }
        }
    }
    __syncthreads();

    // phase 3: local = h + hid @ lw2 + b2 -> g_local and s_x (fp32)
    {
        float4 acc[2][4];
#pragma unroll
        for (int nt = 0; nt < 4; ++nt) {
            const int gc = ng * 32 + nt * 8 + 2 * fcol;
            const float b0 = lb2[gc], b1v = lb2[gc + 1];
#pragma unroll
            for (int mt = 0; mt < 2; ++mt) acc[mt][nt] = make_float4(b0, b1v, b0, b1v);
        }
#pragma unroll 4
        for (int ks = 0; ks < 32; ++ks) {
            u32 a[2][4];
#pragma unroll
            for (int mt = 0; mt < 2; ++mt)
                ldA_raw<SHL>(s_h + (mg + mt * 16 + frow) * SHL + ks * 8 + fcol, a[mt]);
#pragma unroll
            for (int nt = 0; nt < 4; ++nt) {
                const float2 b = g_w2p[(ks * 16 + ng * 4 + nt) * 32 + lane];
#pragma unroll
                for (int mt = 0; mt < 2; ++mt)
                    mma8(acc[mt][nt], a[mt], __float_as_uint(b.x), __float_as_uint(b.y));
            }
        }
#pragma unroll
        for (int mt = 0; mt < 2; ++mt) {
#pragma unroll
            for (int rr = 0; rr < 2; ++rr) {
                const int tl = mg + mt * 16 + frow + rr * 8;
                const int gt = gt0 + tl;
                const int xt = __ldg(x + gt);
#pragma unroll
                for (int nt = 0; nt < 4; ++nt) {
                    const int gc = ng * 32 + nt * 8 + 2 * fcol;
                    const float2 e = *(const float2*)(emb + xt * Dm + gc);
                    const float2 p = *(const float2*)(pos + (gt & 7) * Dm + gc);
                    const float cx = rr ? acc[mt][nt].z : acc[mt][nt].x;
                    const float cy = rr ? acc[mt][nt].w : acc[mt][nt].y;
                    const float2 o = make_float2(e.x + p.x + cx, e.y + p.y + cy);
                    *(float2*)(g_local + gt * Dm + gc) = o;
                    *(float2*)(s_x + tl * SXL + gc) = o;
                }
            }
        }
    }
    __syncthreads();

    // phase 4: chunk means (8 chunks) -> s_h[0:1024]
#pragma unroll
    for (int it = 0; it < 4; ++it) {
        const int idx = tid + it * 256;
        const int c = idx >> 7, dd = idx & 127;
        float s = 0.f;
#pragma unroll
        for (int t = 0; t < 8; ++t) s += s_x[(c * 8 + t) * SXL + dd];
        s_h[c * 128 + dd] = s * 0.125f;
    }
    __syncthreads();

    // phase 5: summ = mean @ pool_w + pool_b -> g_hA (warp per chunk)
    {
        const int j0 = lane * 4;
        u64 acc1[1][2];
        acc1[0][0] = pk2(pb[j0], pb[j0 + 1]);
        acc1[0][1] = pk2(pb[j0 + 2], pb[j0 + 3]);
        mm_acc<128, 1, 2>(s_h + wid * 128, pw + j0, 128, acc1);
        const float2 v0 = u2f(acc1[0][0]), v1 = u2f(acc1[0][1]);
        *(float4*)(g_hA + (blockIdx.x * 8 + wid) * Dm + j0) =
            make_float4(v0.x, v0.y, v1.x, v1.y);
    }
}

// ============================================================
// K2: FUSED msg round, 256 threads / 8 warps, 32 rows (+4 halo)
// Trimmed buffers: 136 rows x SXL = 70.1KB -> 3 CTAs/SM.
//   s_hmt 36 rows tf32 hmsg  (v = row-(r0-4), v=0..35)
//   s_pn  36 rows nbr-proj (v=0..35); rows 0..31 alias agg
//   s_ps  32 rows self-proj; alias uh
//   s_hs  32 rows gelu-sum; alias pre-LN fp32
// nbr-proj m-tiles at v = {0,16,20} (third overlaps, identical values)
// ============================================================
__global__ __launch_bounds__(256, 3) void k_msgf(
    int useA, int last,
    const float* __restrict__ mb1, const float* __restrict__ mb2,
    const float* __restrict__ ub1, const float* __restrict__ ub2,
    const float* __restrict__ lg, const float* __restrict__ lb,
    const float* __restrict__ bcb)
{
    const float* __restrict__ hin = useA ? g_hA : g_hB;
    float* __restrict__ hout = useA ? g_hB : g_hA;
    extern __shared__ float sm[];
    float* s_hmt = sm;              // 36 rows
    float* s_pn  = sm + 36 * SXL;   // 36 rows
    float* s_ps  = sm + 72 * SXL;   // 32 rows
    float* s_hs  = sm + 104 * SXL;  // 32 rows
    float* s_ag  = s_pn;
    float* s_uh  = s_ps;
    float* s_pl  = s_hs;
    const int tid = threadIdx.x, wid = tid >> 5, lane = tid & 31;
    const int r0 = blockIdx.x * 32;
    const int frow = lane >> 2, fcol = lane & 3;
    const int ng = wid & 3;            // 4 n-groups of 32 cols
    const int mgrp = wid >> 2;         // 2 m-groups of 16 rows (phases P3+)
    const int mrow = mgrp * 16;

    // P0: load 36 halo rows of hmsg as tf32 (clamped): 36*128 = 4608
#pragma unroll
    for (int it = 0; it < 18; ++it) {
        const int idx = tid + it * 256;
        const int v = idx >> 7, j = idx & 127;
        int row = r0 - 4 + v;
        row = row < 0 ? 0 : (row > ROWS - 1 ? ROWS - 1 : row);
        s_hmt[v * SXL + j] = f2tff(hin[row * Dm + j]);
    }
    __syncthreads();

    // P1: warps 0-3: self-proj (m-tiles at v=4,20); warps 4-7: nbr-proj (v=0,16,20)
    if (mgrp == 0) {
        float4 acc[2][4];
#pragma unroll
        for (int mt = 0; mt < 2; ++mt)
#pragma unroll
            for (int nt = 0; nt < 4; ++nt) acc[mt][nt] = make_float4(0.f, 0.f, 0.f, 0.f);
#pragma unroll 4
        for (int ks = 0; ks < 16; ++ks) {
            u32 a[2][4];
#pragma unroll
            for (int mt = 0; mt < 2; ++mt)
                ldA_raw<SXL>(s_hmt + (4 + mt * 16 + frow) * SXL + ks * 8 + fcol, a[mt]);
#pragma unroll
            for (int nt = 0; nt < 4; ++nt) {
                const float2 b = g_mwp[0 * 8192 + (ks * 16 + ng * 4 + nt) * 32 + lane];
#pragma unroll
                for (int mt = 0; mt < 2; ++mt)
                    mma8(acc[mt][nt], a[mt], __float_as_uint(b.x), __float_as_uint(b.y));
            }
        }
#pragma unroll
        for (int mt = 0; mt < 2; ++mt) {
            const int r = mt * 16 + frow;
#pragma unroll
            for (int nt = 0; nt < 4; ++nt) {
                const int gc = ng * 32 + nt * 8 + 2 * fcol;
                *(float2*)(s_ps + r * SXL + gc)       = make_float2(acc[mt][nt].x, acc[mt][nt].y);
                *(float2*)(s_ps + (r + 8) * SXL + gc) = make_float2(acc[mt][nt].z, acc[mt][nt].w);
            }
        }
    } else {
        const int nbase0 = 0, nbase1 = 16, nbase2 = 20;
        float4 acc[3][4];
#pragma unroll
        for (int mt = 0; mt < 3; ++mt)
#pragma unroll
            for (int nt = 0; nt < 4; ++nt) acc[mt][nt] = make_float4(0.f, 0.f, 0.f, 0.f);
#pragma unroll 4
        for (int ks = 0; ks < 16; ++ks) {
            u32 a[3][4];
            ldA_raw<SXL>(s_hmt + (nbase0 + frow) * SXL + ks * 8 + fcol, a[0]);
            ldA_raw<SXL>(s_hmt + (nbase1 + frow) * SXL + ks * 8 + fcol, a[1]);
            ldA_raw<SXL>(s_hmt + (nbase2 + frow) * SXL + ks * 8 + fcol, a[2]);
#pragma unroll
            for (int nt = 0; nt < 4; ++nt) {
                const float2 b = g_mwp[1 * 8192 + (ks * 16 + ng * 4 + nt) * 32 + lane];
#pragma unroll
                for (int mt = 0; mt < 3; ++mt)
                    mma8(acc[mt][nt], a[mt], __float_as_uint(b.x), __float_as_uint(b.y));
            }
        }
        const int vb[3] = {nbase0, nbase1, nbase2};
#pragma unroll
        for (int mt = 0; mt < 3; ++mt) {
            const int v = vb[mt] + frow;
#pragma unroll
            for (int nt = 0; nt < 4; ++nt) {
                const int gc = ng * 32 + nt * 8 + 2 * fcol;
                *(float2*)(s_pn + v * SXL + gc)       = make_float2(acc[mt][nt].x, acc[mt][nt].y);
                *(float2*)(s_pn + (v + 8) * SXL + gc) = make_float2(acc[mt][nt].z, acc[mt][nt].w);
            }
        }
    }
    __syncthreads();

    // P2: gelu-sum -> s_hs (tf32)
#pragma unroll
    for (int it = 0; it < 16; ++it) {
        const int idx = tid + it * 256;
        const int r = idx >> 7, j = idx & 127;
        const int i = (r0 + r) & 1023;
        const float ps_b = s_ps[r * SXL + j] + mb1[j];
        float a = 0.f;
#pragma unroll
        for (int dd = 0; dd < 5; ++dd) {
            if (i >= dd) a += gelu_f(ps_b + s_pn[(r + 4 - dd) * SXL + j]);
        }
        s_hs[r * SXL + j] = f2tff(a);
    }
    __syncthreads();

    // P3: agg = (HS @ mw2)/count + b2 -> s_ag (tf32; alias s_pn rows 0..31)
    {
        float4 acc[4];
#pragma unroll
        for (int nt = 0; nt < 4; ++nt) acc[nt] = make_float4(0.f, 0.f, 0.f, 0.f);
#pragma unroll 4
        for (int ks = 0; ks < 16; ++ks) {
            u32 a[4];
            ldA_raw<SXL>(s_hs + (mrow + frow) * SXL + ks * 8 + fcol, a);
#pragma unroll
            for (int nt = 0; nt < 4; ++nt) {
                const float2 b = g_mwp[2 * 8192 + (ks * 16 + ng * 4 + nt) * 32 + lane];
                mma8(acc[nt], a, __float_as_uint(b.x), __float_as_uint(b.y));
            }
        }
        const int rA = mrow + frow;
        const int iA = (r0 + rA) & 1023, iB = (r0 + rA + 8) & 1023;
        const float invA = 1.0f / ((iA + 1) < 5 ? (float)(iA + 1) : 5.0f);
        const float invB = 1.0f / ((iB + 1) < 5 ? (float)(iB + 1) : 5.0f);
#pragma unroll
        for (int nt = 0; nt < 4; ++nt) {
            const int gc = ng * 32 + nt * 8 + 2 * fcol;
            const float b20 = mb2[gc], b21 = mb2[gc + 1];
            *(float2*)(s_ag + rA * SXL + gc) =
                make_float2(f2tff(acc[nt].x * invA + b20), f2tff(acc[nt].y * invA + b21));
            *(float2*)(s_ag + (rA + 8) * SXL + gc) =
                make_float2(f2tff(acc[nt].z * invB + b20), f2tff(acc[nt].w * invB + b21));
        }
    }
    __syncthreads();

    // P4: uh = gelu(HMT @ uw1a + AG @ uw1b + ub1) -> s_uh (tf32; alias s_ps)
    {
        float4 acc[4];
#pragma unroll
        for (int nt = 0; nt < 4; ++nt) {
            const int gc = ng * 32 + nt * 8 + 2 * fcol;
            acc[nt] = make_float4(ub1[gc], ub1[gc + 1], ub1[gc], ub1[gc + 1]);
        }
#pragma unroll 4
        for (int ks = 0; ks < 16; ++ks) {
            u32 a[4];
            ldA_raw<SXL>(s_hmt + (4 + mrow + frow) * SXL + ks * 8 + fcol, a);
#pragma unroll
            for (int nt = 0; nt < 4; ++nt) {
                const float2 b = g_mwp[3 * 8192 + (ks * 16 + ng * 4 + nt) * 32 + lane];
                mma8(acc[nt], a, __float_as_uint(b.x), __float_as_uint(b.y));
            }
        }
#pragma unroll 4
        for (int ks = 0; ks < 16; ++ks) {
            u32 a[4];
            ldA_raw<SXL>(s_ag + (mrow + frow) * SXL + ks * 8 + fcol, a);
#pragma unroll
            for (int nt = 0; nt < 4; ++nt) {
                const float2 b = g_mwp[4 * 8192 + (ks * 16 + ng * 4 + nt) * 32 + lane];
                mma8(acc[nt], a, __float_as_uint(b.x), __float_as_uint(b.y));
            }
        }
        const int rA = mrow + frow;
#pragma unroll
        for (int nt = 0; nt < 4; ++nt) {
            const int gc = ng * 32 + nt * 8 + 2 * fcol;
            *(float2*)(s_uh + rA * SXL + gc) =
                make_float2(f2tff(gelu_f(acc[nt].x)), f2tff(gelu_f(acc[nt].y)));
            *(float2*)(s_uh + (rA + 8) * SXL + gc) =
                make_float2(f2tff(gelu_f(acc[nt].z)), f2tff(gelu_f(acc[nt].w)));
        }
    }
    __syncthreads();

    // P5: pre-LN = hmsg + UH @ uw2 + ub2 -> s_pl (fp32; alias s_hs)
    {
        float4 acc[4];
#pragma unroll
        for (int nt = 0; nt < 4; ++nt) {
            const int gc = ng * 32 + nt * 8 + 2 * fcol;
            acc[nt] = make_float4(ub2[gc], ub2[gc + 1], ub2[gc], ub2[gc + 1]);
        }
#pragma unroll 4
        for (int ks = 0; ks < 16; ++ks) {
            u32 a[4];
            ldA_raw<SXL>(s_uh + (mrow + frow) * SXL + ks * 8 + fcol, a);
#pragma unroll
            for (int nt = 0; nt < 4; ++nt) {
                const float2 b = g_mwp[5 * 8192 + (ks * 16 + ng * 4 + nt) * 32 + lane];
                mma8(acc[nt], a, __float_as_uint(b.x), __float_as_uint(b.y));
            }
        }
        const int rA = mrow + frow;
#pragma unroll
        for (int nt = 0; nt < 4; ++nt) {
            const int gc = ng * 32 + nt * 8 + 2 * fcol;
            const float2 h0 = *(const float2*)(s_hmt + (4 + rA) * SXL + gc);
            const float2 h1 = *(const float2*)(s_hmt + (12 + rA) * SXL + gc);
            *(float2*)(s_pl + rA * SXL + gc) =
                make_float2(h0.x + acc[nt].x, h0.y + acc[nt].y);
            *(float2*)(s_pl + (rA + 8) * SXL + gc) =
                make_float2(h1.x + acc[nt].z, h1.y + acc[nt].w);
        }
    }
    __syncthreads();

    // P6: LN per row (4 rows/warp). Non-final: -> hout. Final: tf32 -> s_hmt[4+r]
#pragma unroll
    for (int rr = 0; rr < 4; ++rr) {
        const int r = wid * 4 + rr;
        const float4 v0 = *(const float4*)(s_pl + r * SXL + lane * 4);
        const float4 v = ln_f4(v0, lg, lb, lane);
        if (!last) {
            *(float4*)(hout + (r0 + r) * Dm + lane * 4) = v;
        } else {
            float* dst = s_hmt + (4 + r) * SXL + lane * 4;
            dst[0] = f2tff(v.x); dst[1] = f2tff(v.y);
            dst[2] = f2tff(v.z); dst[3] = f2tff(v.w);
        }
    }

    // P7 (final round only): bc = hmsg_final @ bc_w + bc_b -> g_bcb
    if (last) {
        __syncthreads();
        float4 acc[4];
#pragma unroll
        for (int nt = 0; nt < 4; ++nt) {
            const int gc = ng * 32 + nt * 8 + 2 * fcol;
            acc[nt] = make_float4(bcb[gc], bcb[gc + 1], bcb[gc], bcb[gc + 1]);
        }
#pragma unroll 4
        for (int ks = 0; ks < 16; ++ks) {
            u32 a[4];
            ldA_raw<SXL>(s_hmt + (4 + mrow + frow) * SXL + ks * 8 + fcol, a);
#pragma unroll
            for (int nt = 0; nt < 4; ++nt) {
                const float2 b = g_mwp[6 * 8192 + (ks * 16 + ng * 4 + nt) * 32 + lane];
                mma8(acc[nt], a, __float_as_uint(b.x), __float_as_uint(b.y));
            }
        }
        const int rA = r0 + mrow + frow;
#pragma unroll
        for (int nt = 0; nt < 4; ++nt) {
            const int gc = ng * 32 + nt * 8 + 2 * fcol;
            *(float2*)(g_bcb + rA * Dm + gc)       = make_float2(acc[nt].x, acc[nt].y);
            *(float2*)(g_bcb + (rA + 8) * Dm + gc) = make_float2(acc[nt].z, acc[nt].w);
        }
    }
}

// ============================================================
// K5: logits = LN(local + bc) @ head_w (tensor), 64 tok/block
// ============================================================
__global__ __launch_bounds__(256) void k_head(
    const float* __restrict__ lg, const float* __restrict__ lb,
    float* __restrict__ out)
{
    __shared__ float s_x[64 * SXL];
    const int tid = threadIdx.x, wid = tid >> 5, lane = tid & 31;
    const int gt0 = blockIdx.x * 64;
    const int frow = lane >> 2, fcol = lane & 3;

#pragma unroll
    for (int tt = 0; tt < 8; ++tt) {
        const int tl = wid * 8 + tt, gt = gt0 + tl;
        const float4 lv = *(const float4*)(g_local + gt * Dm + lane * 4);
        const float4 bv = *(const float4*)(g_bcb + (gt >> 3) * Dm + lane * 4);
        const float4 h = make_float4(lv.x + bv.x, lv.y + bv.y, lv.z + bv.z, lv.w + bv.w);
        const float4 v = ln_f4(h, lg, lb, lane);
        float* dst = s_x + tl * SXL + lane * 4;
        dst[0] = f2tff(v.x); dst[1] = f2tff(v.y); dst[2] = f2tff(v.z); dst[3] = f2tff(v.w);
    }
    __syncthreads();

    const int mg = (wid >> 2) * 32;
    const int ng = (wid & 3);
    float4 acc[2][8];
#pragma unroll
    for (int mt = 0; mt < 2; ++mt)
#pragma unroll
        for (int nt = 0; nt < 8; ++nt) acc[mt][nt] = make_float4(0.f, 0.f, 0.f, 0.f);

#pragma unroll 4
    for (int ks = 0; ks < 16; ++ks) {
        u32 a[2][4];
#pragma unroll
        for (int mt = 0; mt < 2; ++mt)
            ldA_raw<SXL>(s_x + (mg + mt * 16 + frow) * SXL + ks * 8 + fcol, a[mt]);
#pragma unroll
        for (int nt = 0; nt < 8; ++nt) {
            const float2 b = g_hwp[(ks * 32 + ng * 8 + nt) * 32 + lane];
#pragma unroll
            for (int mt = 0; mt < 2; ++mt)
                mma8(acc[mt][nt], a[mt], __float_as_uint(b.x), __float_as_uint(b.y));
        }
    }

#pragma unroll
    for (int mt = 0; mt < 2; ++mt) {
        const int rg = gt0 + mg + mt * 16 + frow;
#pragma unroll
        for (int nt = 0; nt < 8; ++nt) {
            const int gc = ng * 64 + nt * 8 + 2 * fcol;
            *(float2*)(out + rg * Hm + gc)       = make_float2(acc[mt][nt].x, acc[mt][nt].y);
            *(float2*)(out + (rg + 8) * Hm + gc) = make_float2(acc[mt][nt].z, acc[mt][nt].w);
        }
    }
}

// ============================================================
extern "C" void kernel_launch(void* const* d_in, const int* in_sizes, int n_in,
                              void* d_out, int out_size) {
    const int*   x      = (const int*)  d_in[0];
    const float* emb    = (const float*)d_in[1];
    const float* pos    = (const float*)d_in[2];
    const float* lw1    = (const float*)d_in[3];
    const float* lb1    = (const float*)d_in[4];
    const float* lw2    = (const float*)d_in[5];
    const float* lb2    = (const float*)d_in[6];
    const float* lln_g  = (const float*)d_in[7];
    const float* lln_b  = (const float*)d_in[8];
    const float* pool_w = (const float*)d_in[9];
    const float* pool_b = (const float*)d_in[10];
    const float* msg_w1 = (const float*)d_in[11];
    const float* msg_b1 = (const float*)d_in[12];
    const float* msg_w2 = (const float*)d_in[13];
    const float* msg_b2 = (const float*)d_in[14];
    const float* upd_w1 = (const float*)d_in[15];
    const float* upd_b1 = (const float*)d_in[16];
    const float* upd_w2 = (const float*)d_in[17];
    const float* upd_b2 = (const float*)d_in[18];
    const float* mln_g  = (const float*)d_in[19];
    const float* mln_b  = (const float*)d_in[20];
    const float* bc_w   = (const float*)d_in[21];
    const float* bc_b   = (const float*)d_in[22];
    const float* fln_g  = (const float*)d_in[23];
    const float* fln_b  = (const float*)d_in[24];
    const float* head_w = (const float*)d_in[25];
    float* out = (float*)d_out;

    const int SMEM_LOCAL = (64 * SXL + 64 * SHL) * 4;   // 100352 B
    const int SMEM_MSG   = (136 * SXL) * 4;             // 71808 B
    cudaFuncSetAttribute(k_local, cudaFuncAttributeMaxDynamicSharedMemorySize, SMEM_LOCAL);
    cudaFuncSetAttribute(k_msgf,  cudaFuncAttributeMaxDynamicSharedMemorySize, SMEM_MSG);

    k_pack_all<<<416, 256>>>(lw1, lw2, head_w, msg_w1, msg_w2, upd_w1, upd_w2, bc_w);

    k_local<<<NTOK / 64, 256, SMEM_LOCAL>>>(x, emb, pos, lb1, lb2,
                                            lln_g, lln_b, pool_w, pool_b);

    // rounds: A->B, B->A, A->(bc)  (last round writes g_bcb, skips hout)
    for (int r = 0; r < 3; ++r) {
        const int useA = (r % 2 == 0) ? 1 : 0;
        const int last = (r == 2) ? 1 : 0;
        k_msgf<<<ROWS / 32, 256, SMEM_MSG>>>(useA, last, msg_b1, msg_b2,
                                             upd_b1, upd_b2, mln_g, mln_b, bc_b);
    }

    k_head<<<NTOK / 64, 256>>>(fln_g, fln_b, out);
}

// round 14
// speedup vs baseline: 1.2635x; 1.1877x over previous
#include <cuda_runtime.h>
#include <cuda_fp16.h>

#define Dm 128
#define Hm 256
#define ROWS 16384   /* 16 * 1024 chunks */
#define NTOK 131072  /* 16 * 8192 tokens */
#define EPSf 1e-5f

typedef unsigned long long u64;
typedef unsigned int u32;

// ---- scratch (device globals; no allocation) ----
__device__ float g_local[NTOK * Dm];   // 64 MB
__device__ float g_hA[ROWS * Dm];      // 8 MB
__device__ float g_hB[ROWS * Dm];      // 8 MB
__device__ float g_bcb[ROWS * Dm];     // 8 MB
// fp16 weight fragments (m16n8k16 B layout)
__device__ uint2 g_w1h[8 * 32 * 32];   // lw1 128x256
__device__ uint2 g_w2h[16 * 16 * 32];  // lw2 256x128
__device__ uint2 g_hwh[8 * 32 * 32];   // head_w 128x256
// tf32 128x128 msg mats: [0]=w1self [1]=w1nbr [2]=mw2 [3]=uw1a [4]=uw1b [5]=uw2 [6]=bc_w
__device__ float2 g_mwp[7 * 8192];

// ---- packed f32x2 helpers (scalar path) ----
__device__ __forceinline__ u64 pk2(float x, float y) {
    u64 r; asm("mov.b64 %0, {%1, %2};" : "=l"(r) : "f"(x), "f"(y)); return r;
}
__device__ __forceinline__ u64 dup_f(float a) {
    u64 r; asm("mov.b64 %0, {%1, %1};" : "=l"(r) : "f"(a)); return r;
}
__device__ __forceinline__ void fma2(u64& d, u64 a, u64 b) {
    asm("fma.rn.f32x2 %0, %1, %2, %0;" : "+l"(d) : "l"(a), "l"(b));
}
__device__ __forceinline__ float2 u2f(u64 v) {
    float2 r; asm("mov.b64 {%0, %1}, %2;" : "=f"(r.x), "=f"(r.y) : "l"(v)); return r;
}

// ---- tf32 helpers ----
__device__ __forceinline__ u32 f2tf(float f) {
    u32 r; asm("cvt.rna.tf32.f32 %0, %1;" : "=r"(r) : "f"(f)); return r;
}
__device__ __forceinline__ float f2tff(float f) { return __uint_as_float(f2tf(f)); }

// ---- fp16 helpers ----
__device__ __forceinline__ u32 h2u(float x, float y) {
    __half2 h = __floats2half2_rn(x, y);
    return *(u32*)&h;
}

// mma.sync m16n8k8 tf32
__device__ __forceinline__ void mma8(float4& c, const u32 a[4], u32 b0, u32 b1) {
    asm volatile(
        "mma.sync.aligned.m16n8k8.row.col.f32.tf32.tf32.f32 "
        "{%0,%1,%2,%3}, {%4,%5,%6,%7}, {%8,%9}, {%0,%1,%2,%3};"
        : "+f"(c.x), "+f"(c.y), "+f"(c.z), "+f"(c.w)
        : "r"(a[0]), "r"(a[1]), "r"(a[2]), "r"(a[3]), "r"(b0), "r"(b1));
}
// mma.sync m16n8k16 f16 (fp32 accum)
__device__ __forceinline__ void mma16(float4& c, const u32 a[4], u32 b0, u32 b1) {
    asm volatile(
        "mma.sync.aligned.m16n8k16.row.col.f32.f16.f16.f32 "
        "{%0,%1,%2,%3}, {%4,%5,%6,%7}, {%8,%9}, {%0,%1,%2,%3};"
        : "+f"(c.x), "+f"(c.y), "+f"(c.z), "+f"(c.w)
        : "r"(a[0]), "r"(a[1]), "r"(a[2]), "r"(a[3]), "r"(b0), "r"(b1));
}

template<int STRIDE>
__device__ __forceinline__ void ldA_raw(const float* ap, u32 a[4]) {
    a[0] = __float_as_uint(ap[0]);
    a[1] = __float_as_uint(ap[8 * STRIDE]);
    a[2] = __float_as_uint(ap[4]);
    a[3] = __float_as_uint(ap[8 * STRIDE + 4]);
}
// fp16 A fragment: ap pre-offset to (row, ks*16 + 2*fcol), stride in halves
template<int STRIDE>
__device__ __forceinline__ void ldA_h(const __half* ap, u32 a[4]) {
    a[0] = *(const u32*)(ap);
    a[1] = *(const u32*)(ap + 8 * STRIDE);
    a[2] = *(const u32*)(ap + 8);
    a[3] = *(const u32*)(ap + 8 * STRIDE + 8);
}

__device__ __forceinline__ float wsum(float v) {
#pragma unroll
    for (int o = 16; o; o >>= 1) v += __shfl_xor_sync(0xffffffffu, v, o);
    return v;
}
__device__ __forceinline__ float gelu_f(float x) {
    return 0.5f * x * (1.0f + erff(x * 0.70710678118f));
}

__device__ __forceinline__ float4 ln_f4(float4 h, const float* __restrict__ g,
                                        const float* __restrict__ b, int lane) {
    const float mu = wsum(h.x + h.y + h.z + h.w) * (1.0f / 128.0f);
    const float a0 = h.x - mu, a1 = h.y - mu, a2 = h.z - mu, a3 = h.w - mu;
    const float var = wsum(a0 * a0 + a1 * a1 + a2 * a2 + a3 * a3) * (1.0f / 128.0f);
    const float rs = rsqrtf(var + EPSf);
    const int dd = lane * 4;
    const float4 gg = *(const float4*)(g + dd);
    const float4 bb = *(const float4*)(b + dd);
    return make_float4(a0 * rs * gg.x + bb.x, a1 * rs * gg.y + bb.y,
                       a2 * rs * gg.z + bb.z, a3 * rs * gg.w + bb.w);
}

// ---- scalar register-tiled GEMM accumulate (pool only) ----
template<int KDIM, int RPT, int NCP>
__device__ __forceinline__ void mm_acc(const float* __restrict__ s,
                                       const float* __restrict__ W, const int ldw,
                                       u64 acc[RPT][NCP]) {
#pragma unroll 2
    for (int d = 0; d < KDIM; d += 2) {
        u64 w0[NCP], w1[NCP];
        if constexpr (NCP >= 2) {
#pragma unroll
            for (int c = 0; c < NCP; c += 2) {
                const ulonglong2 t0 = *(const ulonglong2*)(W + d * ldw + c * 2);
                const ulonglong2 t1 = *(const ulonglong2*)(W + (d + 1) * ldw + c * 2);
                w0[c] = t0.x; w0[c + 1] = t0.y;
                w1[c] = t1.x; w1[c + 1] = t1.y;
            }
        } else {
            w0[0] = *(const u64*)(W + d * ldw);
            w1[0] = *(const u64*)(W + (d + 1) * ldw);
        }
#pragma unroll
        for (int r = 0; r < RPT; ++r) {
            const float2 a = *(const float2*)(s + r * KDIM + d);
            const u64 a0 = dup_f(a.x), a1 = dup_f(a.y);
#pragma unroll
            for (int c = 0; c < NCP; ++c) {
                fma2(acc[r][c], a0, w0[c]);
                fma2(acc[r][c], a1, w1[c]);
            }
        }
    }
}

// ============================================================
// K0: fused pack. fp16 frags for lw1/lw2/head_w; tf32 for msg mats
// ============================================================
__device__ __forceinline__ void pack_one_t(const float* __restrict__ W,
                                           float2* __restrict__ P,
                                           int N, int idx) {
    const int lane = idx & 31;
    const int t = idx >> 5;
    const int nt = t % (N / 8);
    const int ks = t / (N / 8);
    const int k = ks * 8 + (lane & 3);
    const int n = nt * 8 + (lane >> 2);
    P[idx] = make_float2(f2tff(W[k * N + n]), f2tff(W[(k + 4) * N + n]));
}
__device__ __forceinline__ void pack_one_h(const float* __restrict__ W,
                                           uint2* __restrict__ P,
                                           int N, int idx) {
    const int lane = idx & 31;
    const int t = idx >> 5;
    const int nt = t % (N / 8);
    const int ks = t / (N / 8);
    const int k0 = ks * 16 + 2 * (lane & 3);
    const int n = nt * 8 + (lane >> 2);
    uint2 r;
    r.x = h2u(W[k0 * N + n],       W[(k0 + 1) * N + n]);
    r.y = h2u(W[(k0 + 8) * N + n], W[(k0 + 9) * N + n]);
    P[idx] = r;
}

__global__ __launch_bounds__(256) void k_pack_all(
    const float* __restrict__ lw1, const float* __restrict__ lw2,
    const float* __restrict__ hw,  const float* __restrict__ mw1,
    const float* __restrict__ mw2, const float* __restrict__ uw1,
    const float* __restrict__ uw2, const float* __restrict__ bcw)
{
    const int b = blockIdx.x, tid = threadIdx.x;
    if      (b < 32)  pack_one_h(lw1, g_w1h, 256, b * 256 + tid);
    else if (b < 64)  pack_one_h(lw2, g_w2h, 128, (b - 32) * 256 + tid);
    else if (b < 96)  pack_one_h(hw,  g_hwh, 256, (b - 64) * 256 + tid);
    else if (b < 128) pack_one_t(mw1,           g_mwp + 0 * 8192, 128, (b - 96)  * 256 + tid);
    else if (b < 160) pack_one_t(mw1 + 16384,   g_mwp + 1 * 8192, 128, (b - 128) * 256 + tid);
    else if (b < 192) pack_one_t(mw2,           g_mwp + 2 * 8192, 128, (b - 160) * 256 + tid);
    else if (b < 224) pack_one_t(uw1,           g_mwp + 3 * 8192, 128, (b - 192) * 256 + tid);
    else if (b < 256) pack_one_t(uw1 + 16384,   g_mwp + 4 * 8192, 128, (b - 224) * 256 + tid);
    else if (b < 288) pack_one_t(uw2,           g_mwp + 5 * 8192, 128, (b - 256) * 256 + tid);
    else              pack_one_t(bcw,           g_mwp + 6 * 8192, 128, (b - 288) * 256 + tid);
}

// ============================================================
// K1: local = h + MLP2(LN(h)) + fused pool/summ  (fp16 MMA)
// 64 tokens/block, 256 threads, ~50KB smem, 3 CTAs/SM
// ============================================================
#define SXL 132   /* float stride (msg kernel) */
#define SXH 136   /* half stride, 64x136 halves */
#define SHH 264   /* half stride for hidden 256+pad */
__global__ __launch_bounds__(256, 3) void k_local(
    const int* __restrict__ x, const float* __restrict__ emb, const float* __restrict__ pos,
    const float* __restrict__ lb1, const float* __restrict__ lb2,
    const float* __restrict__ lng, const float* __restrict__ lnb,
    const float* __restrict__ pw, const float* __restrict__ pb)
{
    extern __shared__ char smc[];
    __half* s_x = (__half*)smc;                    // 64 x 136 halves (17408 B)
    __half* s_h = (__half*)(smc + 64 * SXH * 2);   // 64 x 264 halves (33792 B)
    const int tid = threadIdx.x, wid = tid >> 5, lane = tid & 31;
    const int gt0 = blockIdx.x * 64;
    const int frow = lane >> 2, fcol = lane & 3;

    // phase 1: LN per token -> fp16 in s_x
#pragma unroll
    for (int tt = 0; tt < 8; ++tt) {
        const int tl = wid * 8 + tt, gt = gt0 + tl;
        const int xt = __ldg(x + gt);
        const float4 e = *(const float4*)(emb + xt * Dm + lane * 4);
        const float4 p = *(const float4*)(pos + (gt & 7) * Dm + lane * 4);
        const float4 h = make_float4(e.x + p.x, e.y + p.y, e.z + p.z, e.w + p.w);
        const float4 v = ln_f4(h, lng, lnb, lane);
        u32* dst = (u32*)(s_x + tl * SXH) + lane * 2;
        dst[0] = h2u(v.x, v.y);
        dst[1] = h2u(v.z, v.w);
    }
    __syncthreads();

    const int mg = (wid >> 2) * 32;   // 2 m-groups of 32 rows
    const int ng = (wid & 3);         // 4 n-groups

    // phase 2: hid = gelu(xln @ lw1 + b1) -> fp16 in s_h (cols ng*64..+63), 8 k16-steps
    {
        float4 acc[2][8];
#pragma unroll
        for (int nt = 0; nt < 8; ++nt) {
            const int gc = ng * 64 + nt * 8 + 2 * fcol;
            const float b0 = lb1[gc], b1v = lb1[gc + 1];
#pragma unroll
            for (int mt = 0; mt < 2; ++mt) acc[mt][nt] = make_float4(b0, b1v, b0, b1v);
        }
#pragma unroll
        for (int ks = 0; ks < 8; ++ks) {
            u32 a[2][4];
#pragma unroll
            for (int mt = 0; mt < 2; ++mt)
                ldA_h<SXH>(s_x + (mg + mt * 16 + frow) * SXH + ks * 16 + 2 * fcol, a[mt]);
#pragma unroll
            for (int nt = 0; nt < 8; ++nt) {
                const uint2 b = g_w1h[(ks * 32 + ng * 8 + nt) * 32 + lane];
#pragma unroll
                for (int mt = 0; mt < 2; ++mt)
                    mma16(acc[mt][nt], a[mt], b.x, b.y);
            }
        }
#pragma unroll
        for (int mt = 0; mt < 2; ++mt) {
            const int rg = mg + mt * 16 + frow;
#pragma unroll
            for (int nt = 0; nt < 8; ++nt) {
                const int gc = ng * 64 + nt * 8 + 2 * fcol;
                *(u32*)(s_h + rg * SHH + gc) =
                    h2u(gelu_f(acc[mt][nt].x), gelu_f(acc[mt][nt].y));
                *(u32*)(s_h + (rg + 8) * SHH + gc) =
                    h2u(gelu_f(acc[mt][nt].z), gelu_f(acc[mt][nt].w));
            }
        }
    }
    __syncthreads();

    // phase 3: local = h + hid @ lw2 + b2 -> g_local (fp32) and s_x (fp16), 16 k16-steps
    {
        float4 acc[2][4];
#pragma unroll
        for (int nt = 0; nt < 4; ++nt) {
            const int gc = ng * 32 + nt * 8 + 2 * fcol;
            const float b0 = lb2[gc], b1v = lb2[gc + 1];
#pragma unroll
            for (int mt = 0; mt < 2; ++mt) acc[mt][nt] = make_float4(b0, b1v, b0, b1v);
        }
#pragma unroll 4
        for (int ks = 0; ks < 16; ++ks) {
            u32 a[2][4];
#pragma unroll
            for (int mt = 0; mt < 2; ++mt)
                ldA_h<SHH>(s_h + (mg + mt * 16 + frow) * SHH + ks * 16 + 2 * fcol, a[mt]);
#pragma unroll
            for (int nt = 0; nt < 4; ++nt) {
                const uint2 b = g_w2h[(ks * 16 + ng * 4 + nt) * 32 + lane];
#pragma unroll
                for (int mt = 0; mt < 2; ++mt)
                    mma16(acc[mt][nt], a[mt], b.x, b.y);
            }
        }
#pragma unroll
        for (int mt = 0; mt < 2; ++mt) {
#pragma unroll
            for (int rr = 0; rr < 2; ++rr) {
                const int tl = mg + mt * 16 + frow + rr * 8;
                const int gt = gt0 + tl;
                const int xt = __ldg(x + gt);
#pragma unroll
                for (int nt = 0; nt < 4; ++nt) {
                    const int gc = ng * 32 + nt * 8 + 2 * fcol;
                    const float2 e = *(const float2*)(emb + xt * Dm + gc);
                    const float2 p = *(const float2*)(pos + (gt & 7) * Dm + gc);
                    const float cx = rr ? acc[mt][nt].z : acc[mt][nt].x;
                    const float cy = rr ? acc[mt][nt].w : acc[mt][nt].y;
                    const float2 o = make_float2(e.x + p.x + cx, e.y + p.y + cy);
                    *(float2*)(g_local + gt * Dm + gc) = o;
                    *(u32*)(s_x + tl * SXH + gc) = h2u(o.x, o.y);
                }
            }
        }
    }
    __syncthreads();

    // phase 4: chunk means (8 chunks) -> (float*)s_h[0:1024]
    float* s_m = (float*)s_h;
#pragma unroll
    for (int it = 0; it < 4; ++it) {
        const int idx = tid + it * 256;
        const int c = idx >> 7, dd = idx & 127;
        float s = 0.f;
#pragma unroll
        for (int t = 0; t < 8; ++t) s += __half2float(s_x[(c * 8 + t) * SXH + dd]);
        s_m[c * 128 + dd] = s * 0.125f;
    }
    __syncthreads();

    // phase 5: summ = mean @ pool_w + pool_b -> g_hA (warp per chunk)
    {
        const int j0 = lane * 4;
        u64 acc1[1][2];
        acc1[0][0] = pk2(pb[j0], pb[j0 + 1]);
        acc1[0][1] = pk2(pb[j0 + 2], pb[j0 + 3]);
        mm_acc<128, 1, 2>(s_m + wid * 128, pw + j0, 128, acc1);
        const float2 v0 = u2f(acc1[0][0]), v1 = u2f(acc1[0][1]);
        *(float4*)(g_hA + (blockIdx.x * 8 + wid) * Dm + j0) =
            make_float4(v0.x, v0.y, v1.x, v1.y);
    }
}

// ============================================================
// K2: FUSED msg round (unchanged from best: tf32, 36-row bufs)
// ============================================================
__global__ __launch_bounds__(256, 3) void k_msgf(
    int useA, int last,
    const float* __restrict__ mb1, const float* __restrict__ mb2,
    const float* __restrict__ ub1, const float* __restrict__ ub2,
    const float* __restrict__ lg, const float* __restrict__ lb,
    const float* __restrict__ bcb)
{
    const float* __restrict__ hin = useA ? g_hA : g_hB;
    float* __restrict__ hout = useA ? g_hB : g_hA;
    extern __shared__ float sm[];
    float* s_hmt = sm;              // 36 rows
    float* s_pn  = sm + 36 * SXL;   // 36 rows
    float* s_ps  = sm + 72 * SXL;   // 32 rows
    float* s_hs  = sm + 104 * SXL;  // 32 rows
    float* s_ag  = s_pn;
    float* s_uh  = s_ps;
    float* s_pl  = s_hs;
    const int tid = threadIdx.x, wid = tid >> 5, lane = tid & 31;
    const int r0 = blockIdx.x * 32;
    const int frow = lane >> 2, fcol = lane & 3;
    const int ng = wid & 3;
    const int mgrp = wid >> 2;
    const int mrow = mgrp * 16;

    // P0
#pragma unroll
    for (int it = 0; it < 18; ++it) {
        const int idx = tid + it * 256;
        const int v = idx >> 7, j = idx & 127;
        int row = r0 - 4 + v;
        row = row < 0 ? 0 : (row > ROWS - 1 ? ROWS - 1 : row);
        s_hmt[v * SXL + j] = f2tff(hin[row * Dm + j]);
    }
    __syncthreads();

    // P1
    if (mgrp == 0) {
        float4 acc[2][4];
#pragma unroll
        for (int mt = 0; mt < 2; ++mt)
#pragma unroll
            for (int nt = 0; nt < 4; ++nt) acc[mt][nt] = make_float4(0.f, 0.f, 0.f, 0.f);
#pragma unroll 4
        for (int ks = 0; ks < 16; ++ks) {
            u32 a[2][4];
#pragma unroll
            for (int mt = 0; mt < 2; ++mt)
                ldA_raw<SXL>(s_hmt + (4 + mt * 16 + frow) * SXL + ks * 8 + fcol, a[mt]);
#pragma unroll
            for (int nt = 0; nt < 4; ++nt) {
                const float2 b = g_mwp[0 * 8192 + (ks * 16 + ng * 4 + nt) * 32 + lane];
#pragma unroll
                for (int mt = 0; mt < 2; ++mt)
                    mma8(acc[mt][nt], a[mt], __float_as_uint(b.x), __float_as_uint(b.y));
            }
        }
#pragma unroll
        for (int mt = 0; mt < 2; ++mt) {
            const int r = mt * 16 + frow;
#pragma unroll
            for (int nt = 0; nt < 4; ++nt) {
                const int gc = ng * 32 + nt * 8 + 2 * fcol;
                *(float2*)(s_ps + r * SXL + gc)       = make_float2(acc[mt][nt].x, acc[mt][nt].y);
                *(float2*)(s_ps + (r + 8) * SXL + gc) = make_float2(acc[mt][nt].z, acc[mt][nt].w);
            }
        }
    } else {
        const int nbase0 = 0, nbase1 = 16, nbase2 = 20;
        float4 acc[3][4];
#pragma unroll
        for (int mt = 0; mt < 3; ++mt)
#pragma unroll
            for (int nt = 0; nt < 4; ++nt) acc[mt][nt] = make_float4(0.f, 0.f, 0.f, 0.f);
#pragma unroll 4
        for (int ks = 0; ks < 16; ++ks) {
            u32 a[3][4];
            ldA_raw<SXL>(s_hmt + (nbase0 + frow) * SXL + ks * 8 + fcol, a[0]);
            ldA_raw<SXL>(s_hmt + (nbase1 + frow) * SXL + ks * 8 + fcol, a[1]);
            ldA_raw<SXL>(s_hmt + (nbase2 + frow) * SXL + ks * 8 + fcol, a[2]);
#pragma unroll
            for (int nt = 0; nt < 4; ++nt) {
                const float2 b = g_mwp[1 * 8192 + (ks * 16 + ng * 4 + nt) * 32 + lane];
#pragma unroll
                for (int mt = 0; mt < 3; ++mt)
                    mma8(acc[mt][nt], a[mt], __float_as_uint(b.x), __float_as_uint(b.y));
            }
        }
        const int vb[3] = {nbase0, nbase1, nbase2};
#pragma unroll
        for (int mt = 0; mt < 3; ++mt) {
            const int v = vb[mt] + frow;
#pragma unroll
            for (int nt = 0; nt < 4; ++nt) {
                const int gc = ng * 32 + nt * 8 + 2 * fcol;
                *(float2*)(s_pn + v * SXL + gc)       = make_float2(acc[mt][nt].x, acc[mt][nt].y);
                *(float2*)(s_pn + (v + 8) * SXL + gc) = make_float2(acc[mt][nt].z, acc[mt][nt].w);
            }
        }
    }
    __syncthreads();

    // P2: gelu-sum
#pragma unroll
    for (int it = 0; it < 16; ++it) {
        const int idx = tid + it * 256;
        const int r = idx >> 7, j = idx & 127;
        const int i = (r0 + r) & 1023;
        const float ps_b = s_ps[r * SXL + j] + mb1[j];
        float a = 0.f;
#pragma unroll
        for (int dd = 0; dd < 5; ++dd) {
            if (i >= dd) a += gelu_f(ps_b + s_pn[(r + 4 - dd) * SXL + j]);
        }
        s_hs[r * SXL + j] = f2tff(a);
    }
    __syncthreads();

    // P3: agg
    {
        float4 acc[4];
#pragma unroll
        for (int nt = 0; nt < 4; ++nt) acc[nt] = make_float4(0.f, 0.f, 0.f, 0.f);
#pragma unroll 4
        for (int ks = 0; ks < 16; ++ks) {
            u32 a[4];
            ldA_raw<SXL>(s_hs + (mrow + frow) * SXL + ks * 8 + fcol, a);
#pragma unroll
            for (int nt = 0; nt < 4; ++nt) {
                const float2 b = g_mwp[2 * 8192 + (ks * 16 + ng * 4 + nt) * 32 + lane];
                mma8(acc[nt], a, __float_as_uint(b.x), __float_as_uint(b.y));
            }
        }
        const int rA = mrow + frow;
        const int iA = (r0 + rA) & 1023, iB = (r0 + rA + 8) & 1023;
        const float invA = 1.0f / ((iA + 1) < 5 ? (float)(iA + 1) : 5.0f);
        const float invB = 1.0f / ((iB + 1) < 5 ? (float)(iB + 1) : 5.0f);
#pragma unroll
        for (int nt = 0; nt < 4; ++nt) {
            const int gc = ng * 32 + nt * 8 + 2 * fcol;
            const float b20 = mb2[gc], b21 = mb2[gc + 1];
            *(float2*)(s_ag + rA * SXL + gc) =
                make_float2(f2tff(acc[nt].x * invA + b20), f2tff(acc[nt].y * invA + b21));
            *(float2*)(s_ag + (rA + 8) * SXL + gc) =
                make_float2(f2tff(acc[nt].z * invB + b20), f2tff(acc[nt].w * invB + b21));
        }
    }
    __syncthreads();

    // P4: uh
    {
        float4 acc[4];
#pragma unroll
        for (int nt = 0; nt < 4; ++nt) {
            const int gc = ng * 32 + nt * 8 + 2 * fcol;
            acc[nt] = make_float4(ub1[gc], ub1[gc + 1], ub1[gc], ub1[gc + 1]);
        }
#pragma unroll 4
        for (int ks = 0; ks < 16; ++ks) {
            u32 a[4];
            ldA_raw<SXL>(s_hmt + (4 + mrow + frow) * SXL + ks * 8 + fcol, a);
#pragma unroll
            for (int nt = 0; nt < 4; ++nt) {
                const float2 b = g_mwp[3 * 8192 + (ks * 16 + ng * 4 + nt) * 32 + lane];
                mma8(acc[nt], a, __float_as_uint(b.x), __float_as_uint(b.y));
            }
        }
#pragma unroll 4
        for (int ks = 0; ks < 16; ++ks) {
            u32 a[4];
            ldA_raw<SXL>(s_ag + (mrow + frow) * SXL + ks * 8 + fcol, a);
#pragma unroll
            for (int nt = 0; nt < 4; ++nt) {
                const float2 b = g_mwp[4 * 8192 + (ks * 16 + ng * 4 + nt) * 32 + lane];
                mma8(acc[nt], a, __float_as_uint(b.x), __float_as_uint(b.y));
            }
        }
        const int rA = mrow + frow;
#pragma unroll
        for (int nt = 0; nt < 4; ++nt) {
            const int gc = ng * 32 + nt * 8 + 2 * fcol;
            *(float2*)(s_uh + rA * SXL + gc) =
                make_float2(f2tff(gelu_f(acc[nt].x)), f2tff(gelu_f(acc[nt].y)));
            *(float2*)(s_uh + (rA + 8) * SXL + gc) =
                make_float2(f2tff(gelu_f(acc[nt].z)), f2tff(gelu_f(acc[nt].w)));
        }
    }
    __syncthreads();

    // P5: pre-LN
    {
        float4 acc[4];
#pragma unroll
        for (int nt = 0; nt < 4; ++nt) {
            const int gc = ng * 32 + nt * 8 + 2 * fcol;
            acc[nt] = make_float4(ub2[gc], ub2[gc + 1], ub2[gc], ub2[gc + 1]);
        }
#pragma unroll 4
        for (int ks = 0; ks < 16; ++ks) {
            u32 a[4];
            ldA_raw<SXL>(s_uh + (mrow + frow) * SXL + ks * 8 + fcol, a);
#pragma unroll
            for (int nt = 0; nt < 4; ++nt) {
                const float2 b = g_mwp[5 * 8192 + (ks * 16 + ng * 4 + nt) * 32 + lane];
                mma8(acc[nt], a, __float_as_uint(b.x), __float_as_uint(b.y));
            }
        }
        const int rA = mrow + frow;
#pragma unroll
        for (int nt = 0; nt < 4; ++nt) {
            const int gc = ng * 32 + nt * 8 + 2 * fcol;
            const float2 h0 = *(const float2*)(s_hmt + (4 + rA) * SXL + gc);
            const float2 h1 = *(const float2*)(s_hmt + (12 + rA) * SXL + gc);
            *(float2*)(s_pl + rA * SXL + gc) =
                make_float2(h0.x + acc[nt].x, h0.y + acc[nt].y);
            *(float2*)(s_pl + (rA + 8) * SXL + gc) =
                make_float2(h1.x + acc[nt].z, h1.y + acc[nt].w);
        }
    }
    __syncthreads();

    // P6: LN
#pragma unroll
    for (int rr = 0; rr < 4; ++rr) {
        const int r = wid * 4 + rr;
        const float4 v0 = *(const float4*)(s_pl + r * SXL + lane * 4);
        const float4 v = ln_f4(v0, lg, lb, lane);
        if (!last) {
            *(float4*)(hout + (r0 + r) * Dm + lane * 4) = v;
        } else {
            float* dst = s_hmt + (4 + r) * SXL + lane * 4;
            dst[0] = f2tff(v.x); dst[1] = f2tff(v.y);
            dst[2] = f2tff(v.z); dst[3] = f2tff(v.w);
        }
    }

    // P7: bc (last round)
    if (last) {
        __syncthreads();
        float4 acc[4];
#pragma unroll
        for (int nt = 0; nt < 4; ++nt) {
            const int gc = ng * 32 + nt * 8 + 2 * fcol;
            acc[nt] = make_float4(bcb[gc], bcb[gc + 1], bcb[gc], bcb[gc + 1]);
        }
#pragma unroll 4
        for (int ks = 0; ks < 16; ++ks) {
            u32 a[4];
            ldA_raw<SXL>(s_hmt + (4 + mrow + frow) * SXL + ks * 8 + fcol, a);
#pragma unroll
            for (int nt = 0; nt < 4; ++nt) {
                const float2 b = g_mwp[6 * 8192 + (ks * 16 + ng * 4 + nt) * 32 + lane];
                mma8(acc[nt], a, __float_as_uint(b.x), __float_as_uint(b.y));
            }
        }
        const int rA = r0 + mrow + frow;
#pragma unroll
        for (int nt = 0; nt < 4; ++nt) {
            const int gc = ng * 32 + nt * 8 + 2 * fcol;
            *(float2*)(g_bcb + rA * Dm + gc)       = make_float2(acc[nt].x, acc[nt].y);
            *(float2*)(g_bcb + (rA + 8) * Dm + gc) = make_float2(acc[nt].z, acc[nt].w);
        }
    }
}

// ============================================================
// K5: logits = LN(local + bc) @ head_w (fp16 MMA), 64 tok/block
// ============================================================
__global__ __launch_bounds__(256) void k_head(
    const float* __restrict__ lg, const float* __restrict__ lb,
    float* __restrict__ out)
{
    __shared__ __half s_x[64 * SXH];
    const int tid = threadIdx.x, wid = tid >> 5, lane = tid & 31;
    const int gt0 = blockIdx.x * 64;
    const int frow = lane >> 2, fcol = lane & 3;

#pragma unroll
    for (int tt = 0; tt < 8; ++tt) {
        const int tl = wid * 8 + tt, gt = gt0 + tl;
        const float4 lv = *(const float4*)(g_local + gt * Dm + lane * 4);
        const float4 bv = *(const float4*)(g_bcb + (gt >> 3) * Dm + lane * 4);
        const float4 h = make_float4(lv.x + bv.x, lv.y + bv.y, lv.z + bv.z, lv.w + bv.w);
        const float4 v = ln_f4(h, lg, lb, lane);
        u32* dst = (u32*)(s_x + tl * SXH) + lane * 2;
        dst[0] = h2u(v.x, v.y);
        dst[1] = h2u(v.z, v.w);
    }
    __syncthreads();

    const int mg = (wid >> 2) * 32;
    const int ng = (wid & 3);
    float4 acc[2][8];
#pragma unroll
    for (int mt = 0; mt < 2; ++mt)
#pragma unroll
        for (int nt = 0; nt < 8; ++nt) acc[mt][nt] = make_float4(0.f, 0.f, 0.f, 0.f);

#pragma unroll
    for (int ks = 0; ks < 8; ++ks) {
        u32 a[2][4];
#pragma unroll
        for (int mt = 0; mt < 2; ++mt)
            ldA_h<SXH>(s_x + (mg + mt * 16 + frow) * SXH + ks * 16 + 2 * fcol, a[mt]);
#pragma unroll
        for (int nt = 0; nt < 8; ++nt) {
            const uint2 b = g_hwh[(ks * 32 + ng * 8 + nt) * 32 + lane];
#pragma unroll
            for (int mt = 0; mt < 2; ++mt)
                mma16(acc[mt][nt], a[mt], b.x, b.y);
        }
    }

#pragma unroll
    for (int mt = 0; mt < 2; ++mt) {
        const int rg = gt0 + mg + mt * 16 + frow;
#pragma unroll
        for (int nt = 0; nt < 8; ++nt) {
            const int gc = ng * 64 + nt * 8 + 2 * fcol;
            *(float2*)(out + rg * Hm + gc)       = make_float2(acc[mt][nt].x, acc[mt][nt].y);
            *(float2*)(out + (rg + 8) * Hm + gc) = make_float2(acc[mt][nt].z, acc[mt][nt].w);
        }
    }
}

// ============================================================
extern "C" void kernel_launch(void* const* d_in, const int* in_sizes, int n_in,
                              void* d_out, int out_size) {
    const int*   x      = (const int*)  d_in[0];
    const float* emb    = (const float*)d_in[1];
    const float* pos    = (const float*)d_in[2];
    const float* lw1    = (const float*)d_in[3];
    const float* lb1    = (const float*)d_in[4];
    const float* lw2    = (const float*)d_in[5];
    const float* lb2    = (const float*)d_in[6];
    const float* lln_g  = (const float*)d_in[7];
    const float* lln_b  = (const float*)d_in[8];
    const float* pool_w = (const float*)d_in[9];
    const float* pool_b = (const float*)d_in[10];
    const float* msg_w1 = (const float*)d_in[11];
    const float* msg_b1 = (const float*)d_in[12];
    const float* msg_w2 = (const float*)d_in[13];
    const float* msg_b2 = (const float*)d_in[14];
    const float* upd_w1 = (const float*)d_in[15];
    const float* upd_b1 = (const float*)d_in[16];
    const float* upd_w2 = (const float*)d_in[17];
    const float* upd_b2 = (const float*)d_in[18];
    const float* mln_g  = (const float*)d_in[19];
    const float* mln_b  = (const float*)d_in[20];
    const float* bc_w   = (const float*)d_in[21];
    const float* bc_b   = (const float*)d_in[22];
    const float* fln_g  = (const float*)d_in[23];
    const float* fln_b  = (const float*)d_in[24];
    const float* head_w = (const float*)d_in[25];
    float* out = (float*)d_out;

    const int SMEM_LOCAL = (64 * SXH + 64 * SHH) * 2;   // 51200 B
    const int SMEM_MSG   = (136 * SXL) * 4;             // 71808 B
    cudaFuncSetAttribute(k_local, cudaFuncAttributeMaxDynamicSharedMemorySize, SMEM_LOCAL);
    cudaFuncSetAttribute(k_msgf,  cudaFuncAttributeMaxDynamicSharedMemorySize, SMEM_MSG);

    k_pack_all<<<320, 256>>>(lw1, lw2, head_w, msg_w1, msg_w2, upd_w1, upd_w2, bc_w);

    k_local<<<NTOK / 64, 256, SMEM_LOCAL>>>(x, emb, pos, lb1, lb2,
                                            lln_g, lln_b, pool_w, pool_b);

    // rounds: A->B, B->A, A->(bc)  (last round writes g_bcb, skips hout)
    for (int r = 0; r < 3; ++r) {
        const int useA = (r % 2 == 0) ? 1 : 0;
        const int last = (r == 2) ? 1 : 0;
        k_msgf<<<ROWS / 32, 256, SMEM_MSG>>>(useA, last, msg_b1, msg_b2,
                                             upd_b1, upd_b2, mln_g, mln_b, bc_b);
    }

    k_head<<<NTOK / 64, 256>>>(fln_g, fln_b, out);
}

// round 15
// speedup vs baseline: 1.4111x; 1.1168x over previous
#include <cuda_runtime.h>
#include <cuda_fp16.h>

#define Dm 128
#define Hm 256
#define ROWS 16384   /* 16 * 1024 chunks */
#define NTOK 131072  /* 16 * 8192 tokens */
#define EPSf 1e-5f

typedef unsigned long long u64;
typedef unsigned int u32;

// ---- scratch (device globals; no allocation) ----
__device__ float g_local[NTOK * Dm];   // 64 MB
__device__ float g_hA[ROWS * Dm];      // 8 MB
__device__ float g_hB[ROWS * Dm];      // 8 MB
__device__ float g_bcb[ROWS * Dm];     // 8 MB
// fp16 weight fragments (m16n8k16 B layout)
__device__ uint2 g_w1h[8 * 32 * 32];   // lw1 128x256
__device__ uint2 g_w2h[16 * 16 * 32];  // lw2 256x128
__device__ uint2 g_hwh[8 * 32 * 32];   // head_w 128x256
// fp16 128x128 msg mats: [0]=w1self [1]=w1nbr [2]=mw2 [3]=uw1a [4]=uw1b [5]=uw2 [6]=bc_w
__device__ uint2 g_mwh[7 * 4096];

// ---- packed f32x2 helpers (pool path) ----
__device__ __forceinline__ u64 pk2(float x, float y) {
    u64 r; asm("mov.b64 %0, {%1, %2};" : "=l"(r) : "f"(x), "f"(y)); return r;
}
__device__ __forceinline__ u64 dup_f(float a) {
    u64 r; asm("mov.b64 %0, {%1, %1};" : "=l"(r) : "f"(a)); return r;
}
__device__ __forceinline__ void fma2(u64& d, u64 a, u64 b) {
    asm("fma.rn.f32x2 %0, %1, %2, %0;" : "+l"(d) : "l"(a), "l"(b));
}
__device__ __forceinline__ float2 u2f(u64 v) {
    float2 r; asm("mov.b64 {%0, %1}, %2;" : "=f"(r.x), "=f"(r.y) : "l"(v)); return r;
}

// ---- fp16 helpers ----
__device__ __forceinline__ u32 h2u(float x, float y) {
    __half2 h = __floats2half2_rn(x, y);
    return *(u32*)&h;
}
__device__ __forceinline__ float2 uh2f(u32 v) {
    return __half22float2(*(__half2*)&v);
}

// mma.sync m16n8k16 f16 (fp32 accum)
__device__ __forceinline__ void mma16(float4& c, const u32 a[4], u32 b0, u32 b1) {
    asm volatile(
        "mma.sync.aligned.m16n8k16.row.col.f32.f16.f16.f32 "
        "{%0,%1,%2,%3}, {%4,%5,%6,%7}, {%8,%9}, {%0,%1,%2,%3};"
        : "+f"(c.x), "+f"(c.y), "+f"(c.z), "+f"(c.w)
        : "r"(a[0]), "r"(a[1]), "r"(a[2]), "r"(a[3]), "r"(b0), "r"(b1));
}

// fp16 A fragment: ap pre-offset to (row, ks*16 + 2*fcol), stride in halves
template<int STRIDE>
__device__ __forceinline__ void ldA_h(const __half* ap, u32 a[4]) {
    a[0] = *(const u32*)(ap);
    a[1] = *(const u32*)(ap + 8 * STRIDE);
    a[2] = *(const u32*)(ap + 8);
    a[3] = *(const u32*)(ap + 8 * STRIDE + 8);
}

__device__ __forceinline__ float wsum(float v) {
#pragma unroll
    for (int o = 16; o; o >>= 1) v += __shfl_xor_sync(0xffffffffu, v, o);
    return v;
}
__device__ __forceinline__ float gelu_f(float x) {
    return 0.5f * x * (1.0f + erff(x * 0.70710678118f));
}

__device__ __forceinline__ float4 ln_f4(float4 h, const float* __restrict__ g,
                                        const float* __restrict__ b, int lane) {
    const float mu = wsum(h.x + h.y + h.z + h.w) * (1.0f / 128.0f);
    const float a0 = h.x - mu, a1 = h.y - mu, a2 = h.z - mu, a3 = h.w - mu;
    const float var = wsum(a0 * a0 + a1 * a1 + a2 * a2 + a3 * a3) * (1.0f / 128.0f);
    const float rs = rsqrtf(var + EPSf);
    const int dd = lane * 4;
    const float4 gg = *(const float4*)(g + dd);
    const float4 bb = *(const float4*)(b + dd);
    return make_float4(a0 * rs * gg.x + bb.x, a1 * rs * gg.y + bb.y,
                       a2 * rs * gg.z + bb.z, a3 * rs * gg.w + bb.w);
}

// ---- scalar register-tiled GEMM accumulate (pool only) ----
template<int KDIM, int RPT, int NCP>
__device__ __forceinline__ void mm_acc(const float* __restrict__ s,
                                       const float* __restrict__ W, const int ldw,
                                       u64 acc[RPT][NCP]) {
#pragma unroll 2
    for (int d = 0; d < KDIM; d += 2) {
        u64 w0[NCP], w1[NCP];
        if constexpr (NCP >= 2) {
#pragma unroll
            for (int c = 0; c < NCP; c += 2) {
                const ulonglong2 t0 = *(const ulonglong2*)(W + d * ldw + c * 2);
                const ulonglong2 t1 = *(const ulonglong2*)(W + (d + 1) * ldw + c * 2);
                w0[c] = t0.x; w0[c + 1] = t0.y;
                w1[c] = t1.x; w1[c + 1] = t1.y;
            }
        } else {
            w0[0] = *(const u64*)(W + d * ldw);
            w1[0] = *(const u64*)(W + (d + 1) * ldw);
        }
#pragma unroll
        for (int r = 0; r < RPT; ++r) {
            const float2 a = *(const float2*)(s + r * KDIM + d);
            const u64 a0 = dup_f(a.x), a1 = dup_f(a.y);
#pragma unroll
            for (int c = 0; c < NCP; ++c) {
                fma2(acc[r][c], a0, w0[c]);
                fma2(acc[r][c], a1, w1[c]);
            }
        }
    }
}

// ============================================================
// K0: fused pack — everything to fp16 m16n8k16 B-fragments
// ============================================================
__device__ __forceinline__ void pack_one_h(const float* __restrict__ W,
                                           uint2* __restrict__ P,
                                           int N, int idx) {
    const int lane = idx & 31;
    const int t = idx >> 5;
    const int nt = t % (N / 8);
    const int ks = t / (N / 8);
    const int k0 = ks * 16 + 2 * (lane & 3);
    const int n = nt * 8 + (lane >> 2);
    uint2 r;
    r.x = h2u(W[k0 * N + n],       W[(k0 + 1) * N + n]);
    r.y = h2u(W[(k0 + 8) * N + n], W[(k0 + 9) * N + n]);
    P[idx] = r;
}

__global__ __launch_bounds__(256) void k_pack_all(
    const float* __restrict__ lw1, const float* __restrict__ lw2,
    const float* __restrict__ hw,  const float* __restrict__ mw1,
    const float* __restrict__ mw2, const float* __restrict__ uw1,
    const float* __restrict__ uw2, const float* __restrict__ bcw)
{
    const int b = blockIdx.x, tid = threadIdx.x;
    if      (b < 32)  pack_one_h(lw1, g_w1h, 256, b * 256 + tid);
    else if (b < 64)  pack_one_h(lw2, g_w2h, 128, (b - 32) * 256 + tid);
    else if (b < 96)  pack_one_h(hw,  g_hwh, 256, (b - 64) * 256 + tid);
    else if (b < 112) pack_one_h(mw1,           g_mwh + 0 * 4096, 128, (b - 96)  * 256 + tid);
    else if (b < 128) pack_one_h(mw1 + 16384,   g_mwh + 1 * 4096, 128, (b - 112) * 256 + tid);
    else if (b < 144) pack_one_h(mw2,           g_mwh + 2 * 4096, 128, (b - 128) * 256 + tid);
    else if (b < 160) pack_one_h(uw1,           g_mwh + 3 * 4096, 128, (b - 144) * 256 + tid);
    else if (b < 176) pack_one_h(uw1 + 16384,   g_mwh + 4 * 4096, 128, (b - 160) * 256 + tid);
    else if (b < 192) pack_one_h(uw2,           g_mwh + 5 * 4096, 128, (b - 176) * 256 + tid);
    else              pack_one_h(bcw,           g_mwh + 6 * 4096, 128, (b - 192) * 256 + tid);
}

// ============================================================
// K1: local = h + MLP2(LN(h)) + fused pool/summ  (fp16 MMA)
// 64 tokens/block, 256 threads, ~50KB smem, 3 CTAs/SM
// ============================================================
#define SXL 132   /* float stride */
#define SXH 136   /* half stride */
#define SHH 264   /* half stride for hidden */
__global__ __launch_bounds__(256, 3) void k_local(
    const int* __restrict__ x, const float* __restrict__ emb, const float* __restrict__ pos,
    const float* __restrict__ lb1, const float* __restrict__ lb2,
    const float* __restrict__ lng, const float* __restrict__ lnb,
    const float* __restrict__ pw, const float* __restrict__ pb)
{
    extern __shared__ char smc[];
    __half* s_x = (__half*)smc;                    // 64 x 136 halves
    __half* s_h = (__half*)(smc + 64 * SXH * 2);   // 64 x 264 halves
    const int tid = threadIdx.x, wid = tid >> 5, lane = tid & 31;
    const int gt0 = blockIdx.x * 64;
    const int frow = lane >> 2, fcol = lane & 3;

    // phase 1: LN per token -> fp16
#pragma unroll
    for (int tt = 0; tt < 8; ++tt) {
        const int tl = wid * 8 + tt, gt = gt0 + tl;
        const int xt = __ldg(x + gt);
        const float4 e = *(const float4*)(emb + xt * Dm + lane * 4);
        const float4 p = *(const float4*)(pos + (gt & 7) * Dm + lane * 4);
        const float4 h = make_float4(e.x + p.x, e.y + p.y, e.z + p.z, e.w + p.w);
        const float4 v = ln_f4(h, lng, lnb, lane);
        u32* dst = (u32*)(s_x + tl * SXH) + lane * 2;
        dst[0] = h2u(v.x, v.y);
        dst[1] = h2u(v.z, v.w);
    }
    __syncthreads();

    const int mg = (wid >> 2) * 32;
    const int ng = (wid & 3);

    // phase 2: hid = gelu(xln @ lw1 + b1)
    {
        float4 acc[2][8];
#pragma unroll
        for (int nt = 0; nt < 8; ++nt) {
            const int gc = ng * 64 + nt * 8 + 2 * fcol;
            const float b0 = lb1[gc], b1v = lb1[gc + 1];
#pragma unroll
            for (int mt = 0; mt < 2; ++mt) acc[mt][nt] = make_float4(b0, b1v, b0, b1v);
        }
#pragma unroll
        for (int ks = 0; ks < 8; ++ks) {
            u32 a[2][4];
#pragma unroll
            for (int mt = 0; mt < 2; ++mt)
                ldA_h<SXH>(s_x + (mg + mt * 16 + frow) * SXH + ks * 16 + 2 * fcol, a[mt]);
#pragma unroll
            for (int nt = 0; nt < 8; ++nt) {
                const uint2 b = g_w1h[(ks * 32 + ng * 8 + nt) * 32 + lane];
#pragma unroll
                for (int mt = 0; mt < 2; ++mt)
                    mma16(acc[mt][nt], a[mt], b.x, b.y);
            }
        }
#pragma unroll
        for (int mt = 0; mt < 2; ++mt) {
            const int rg = mg + mt * 16 + frow;
#pragma unroll
            for (int nt = 0; nt < 8; ++nt) {
                const int gc = ng * 64 + nt * 8 + 2 * fcol;
                *(u32*)(s_h + rg * SHH + gc) =
                    h2u(gelu_f(acc[mt][nt].x), gelu_f(acc[mt][nt].y));
                *(u32*)(s_h + (rg + 8) * SHH + gc) =
                    h2u(gelu_f(acc[mt][nt].z), gelu_f(acc[mt][nt].w));
            }
        }
    }
    __syncthreads();

    // phase 3: local = h + hid @ lw2 + b2
    {
        float4 acc[2][4];
#pragma unroll
        for (int nt = 0; nt < 4; ++nt) {
            const int gc = ng * 32 + nt * 8 + 2 * fcol;
            const float b0 = lb2[gc], b1v = lb2[gc + 1];
#pragma unroll
            for (int mt = 0; mt < 2; ++mt) acc[mt][nt] = make_float4(b0, b1v, b0, b1v);
        }
#pragma unroll 4
        for (int ks = 0; ks < 16; ++ks) {
            u32 a[2][4];
#pragma unroll
            for (int mt = 0; mt < 2; ++mt)
                ldA_h<SHH>(s_h + (mg + mt * 16 + frow) * SHH + ks * 16 + 2 * fcol, a[mt]);
#pragma unroll
            for (int nt = 0; nt < 4; ++nt) {
                const uint2 b = g_w2h[(ks * 16 + ng * 4 + nt) * 32 + lane];
#pragma unroll
                for (int mt = 0; mt < 2; ++mt)
                    mma16(acc[mt][nt], a[mt], b.x, b.y);
            }
        }
#pragma unroll
        for (int mt = 0; mt < 2; ++mt) {
#pragma unroll
            for (int rr = 0; rr < 2; ++rr) {
                const int tl = mg + mt * 16 + frow + rr * 8;
                const int gt = gt0 + tl;
                const int xt = __ldg(x + gt);
#pragma unroll
                for (int nt = 0; nt < 4; ++nt) {
                    const int gc = ng * 32 + nt * 8 + 2 * fcol;
                    const float2 e = *(const float2*)(emb + xt * Dm + gc);
                    const float2 p = *(const float2*)(pos + (gt & 7) * Dm + gc);
                    const float cx = rr ? acc[mt][nt].z : acc[mt][nt].x;
                    const float cy = rr ? acc[mt][nt].w : acc[mt][nt].y;
                    const float2 o = make_float2(e.x + p.x + cx, e.y + p.y + cy);
                    *(float2*)(g_local + gt * Dm + gc) = o;
                    *(u32*)(s_x + tl * SXH + gc) = h2u(o.x, o.y);
                }
            }
        }
    }
    __syncthreads();

    // phase 4: chunk means -> (float*)s_h[0:1024]
    float* s_m = (float*)s_h;
#pragma unroll
    for (int it = 0; it < 4; ++it) {
        const int idx = tid + it * 256;
        const int c = idx >> 7, dd = idx & 127;
        float s = 0.f;
#pragma unroll
        for (int t = 0; t < 8; ++t) s += __half2float(s_x[(c * 8 + t) * SXH + dd]);
        s_m[c * 128 + dd] = s * 0.125f;
    }
    __syncthreads();

    // phase 5: summ = mean @ pool_w + pool_b -> g_hA
    {
        const int j0 = lane * 4;
        u64 acc1[1][2];
        acc1[0][0] = pk2(pb[j0], pb[j0 + 1]);
        acc1[0][1] = pk2(pb[j0 + 2], pb[j0 + 3]);
        mm_acc<128, 1, 2>(s_m + wid * 128, pw + j0, 128, acc1);
        const float2 v0 = u2f(acc1[0][0]), v1 = u2f(acc1[0][1]);
        *(float4*)(g_hA + (blockIdx.x * 8 + wid) * Dm + j0) =
            make_float4(v0.x, v0.y, v1.x, v1.y);
    }
}

// ============================================================
// K2: FUSED msg round — fp16 MMA everywhere, fp32 residual from gmem
// 32 rows/block (+4 halo), 256 threads, 52.6KB smem
//   s_hmtH 36 rows fp16 hmsg (v = row-(r0-4))
//   s_pnH  36 rows nbr-proj fp16; rows 0..31 alias agg
//   s_psH  32 rows self-proj fp16; alias uh
//   s_hsH  32 rows gelu-sum fp16
//   s_pl   32 rows fp32 pre-LN
// ============================================================
__global__ __launch_bounds__(256, 3) void k_msgf(
    int useA, int last,
    const float* __restrict__ mb1, const float* __restrict__ mb2,
    const float* __restrict__ ub1, const float* __restrict__ ub2,
    const float* __restrict__ lg, const float* __restrict__ lb,
    const float* __restrict__ bcb)
{
    const float* __restrict__ hin = useA ? g_hA : g_hB;
    float* __restrict__ hout = useA ? g_hB : g_hA;
    extern __shared__ char smc[];
    __half* s_hmtH = (__half*)smc;            // 36 rows
    __half* s_pnH  = s_hmtH + 36 * SXH;       // 36 rows
    __half* s_psH  = s_hmtH + 72 * SXH;       // 32 rows
    __half* s_hsH  = s_hmtH + 104 * SXH;      // 32 rows
    float*  s_pl   = (float*)(smc + 136 * SXH * 2);  // 32 x SXL fp32
    __half* s_agH  = s_pnH;
    __half* s_uhH  = s_psH;
    const int tid = threadIdx.x, wid = tid >> 5, lane = tid & 31;
    const int r0 = blockIdx.x * 32;
    const int frow = lane >> 2, fcol = lane & 3;
    const int ng = wid & 3;            // 4 n-groups of 32 cols
    const int mgrp = wid >> 2;         // 2 m-groups of 16 rows (P3+)
    const int mrow = mgrp * 16;

    // P0: load 36 halo rows of hmsg as fp16 (clamped): 36*64 = 2304 pairs
#pragma unroll
    for (int it = 0; it < 9; ++it) {
        const int idx = tid + it * 256;
        const int v = idx >> 6, jp = idx & 63;
        int row = r0 - 4 + v;
        row = row < 0 ? 0 : (row > ROWS - 1 ? ROWS - 1 : row);
        const float2 hv = *(const float2*)(hin + row * Dm + jp * 2);
        *((u32*)(s_hmtH + v * SXH) + jp) = h2u(hv.x, hv.y);
    }
    __syncthreads();

    // P1: warps 0-3 self-proj (m-tiles v=4,20); warps 4-7 nbr-proj (v=0,16,20)
    if (mgrp == 0) {
        float4 acc[2][4];
#pragma unroll
        for (int mt = 0; mt < 2; ++mt)
#pragma unroll
            for (int nt = 0; nt < 4; ++nt) acc[mt][nt] = make_float4(0.f, 0.f, 0.f, 0.f);
#pragma unroll
        for (int ks = 0; ks < 8; ++ks) {
            u32 a[2][4];
#pragma unroll
            for (int mt = 0; mt < 2; ++mt)
                ldA_h<SXH>(s_hmtH + (4 + mt * 16 + frow) * SXH + ks * 16 + 2 * fcol, a[mt]);
#pragma unroll
            for (int nt = 0; nt < 4; ++nt) {
                const uint2 b = g_mwh[0 * 4096 + (ks * 16 + ng * 4 + nt) * 32 + lane];
#pragma unroll
                for (int mt = 0; mt < 2; ++mt)
                    mma16(acc[mt][nt], a[mt], b.x, b.y);
            }
        }
#pragma unroll
        for (int mt = 0; mt < 2; ++mt) {
            const int r = mt * 16 + frow;
#pragma unroll
            for (int nt = 0; nt < 4; ++nt) {
                const int gc = ng * 32 + nt * 8 + 2 * fcol;
                *(u32*)(s_psH + r * SXH + gc)       = h2u(acc[mt][nt].x, acc[mt][nt].y);
                *(u32*)(s_psH + (r + 8) * SXH + gc) = h2u(acc[mt][nt].z, acc[mt][nt].w);
            }
        }
    } else {
        float4 acc[3][4];
#pragma unroll
        for (int mt = 0; mt < 3; ++mt)
#pragma unroll
            for (int nt = 0; nt < 4; ++nt) acc[mt][nt] = make_float4(0.f, 0.f, 0.f, 0.f);
        const int vb[3] = {0, 16, 20};
#pragma unroll
        for (int ks = 0; ks < 8; ++ks) {
            u32 a[3][4];
#pragma unroll
            for (int mt = 0; mt < 3; ++mt)
                ldA_h<SXH>(s_hmtH + (vb[mt] + frow) * SXH + ks * 16 + 2 * fcol, a[mt]);
#pragma unroll
            for (int nt = 0; nt < 4; ++nt) {
                const uint2 b = g_mwh[1 * 4096 + (ks * 16 + ng * 4 + nt) * 32 + lane];
#pragma unroll
                for (int mt = 0; mt < 3; ++mt)
                    mma16(acc[mt][nt], a[mt], b.x, b.y);
            }
        }
#pragma unroll
        for (int mt = 0; mt < 3; ++mt) {
            const int v = vb[mt] + frow;
#pragma unroll
            for (int nt = 0; nt < 4; ++nt) {
                const int gc = ng * 32 + nt * 8 + 2 * fcol;
                *(u32*)(s_pnH + v * SXH + gc)       = h2u(acc[mt][nt].x, acc[mt][nt].y);
                *(u32*)(s_pnH + (v + 8) * SXH + gc) = h2u(acc[mt][nt].z, acc[mt][nt].w);
            }
        }
    }
    __syncthreads();

    // P2: gelu-sum -> s_hsH (half2 granularity: 32 rows x 64 pairs)
#pragma unroll
    for (int it = 0; it < 8; ++it) {
        const int idx = tid + it * 256;
        const int r = idx >> 6, jp = idx & 63;
        const int i = (r0 + r) & 1023;
        const float2 b1v = *(const float2*)(mb1 + jp * 2);
        float2 ps = uh2f(*((const u32*)(s_psH + r * SXH) + jp));
        ps.x += b1v.x; ps.y += b1v.y;
        float a0 = 0.f, a1 = 0.f;
#pragma unroll
        for (int dd = 0; dd < 5; ++dd) {
            if (i >= dd) {
                const float2 pn = uh2f(*((const u32*)(s_pnH + (r + 4 - dd) * SXH) + jp));
                a0 += gelu_f(ps.x + pn.x);
                a1 += gelu_f(ps.y + pn.y);
            }
        }
        *((u32*)(s_hsH + r * SXH) + jp) = h2u(a0, a1);
    }
    __syncthreads();

    // P3: agg = (HS @ mw2)/count + b2 -> s_agH (alias s_pnH rows 0..31)
    {
        float4 acc[4];
#pragma unroll
        for (int nt = 0; nt < 4; ++nt) acc[nt] = make_float4(0.f, 0.f, 0.f, 0.f);
#pragma unroll
        for (int ks = 0; ks < 8; ++ks) {
            u32 a[4];
            ldA_h<SXH>(s_hsH + (mrow + frow) * SXH + ks * 16 + 2 * fcol, a);
#pragma unroll
            for (int nt = 0; nt < 4; ++nt) {
                const uint2 b = g_mwh[2 * 4096 + (ks * 16 + ng * 4 + nt) * 32 + lane];
                mma16(acc[nt], a, b.x, b.y);
            }
        }
        const int rA = mrow + frow;
        const int iA = (r0 + rA) & 1023, iB = (r0 + rA + 8) & 1023;
        const float invA = 1.0f / ((iA + 1) < 5 ? (float)(iA + 1) : 5.0f);
        const float invB = 1.0f / ((iB + 1) < 5 ? (float)(iB + 1) : 5.0f);
#pragma unroll
        for (int nt = 0; nt < 4; ++nt) {
            const int gc = ng * 32 + nt * 8 + 2 * fcol;
            const float b20 = mb2[gc], b21 = mb2[gc + 1];
            *(u32*)(s_agH + rA * SXH + gc) =
                h2u(acc[nt].x * invA + b20, acc[nt].y * invA + b21);
            *(u32*)(s_agH + (rA + 8) * SXH + gc) =
                h2u(acc[nt].z * invB + b20, acc[nt].w * invB + b21);
        }
    }
    __syncthreads();

    // P4: uh = gelu(HMT @ uw1a + AG @ uw1b + ub1) -> s_uhH (alias s_psH)
    {
        float4 acc[4];
#pragma unroll
        for (int nt = 0; nt < 4; ++nt) {
            const int gc = ng * 32 + nt * 8 + 2 * fcol;
            acc[nt] = make_float4(ub1[gc], ub1[gc + 1], ub1[gc], ub1[gc + 1]);
        }
#pragma unroll
        for (int ks = 0; ks < 8; ++ks) {
            u32 a[4];
            ldA_h<SXH>(s_hmtH + (4 + mrow + frow) * SXH + ks * 16 + 2 * fcol, a);
#pragma unroll
            for (int nt = 0; nt < 4; ++nt) {
                const uint2 b = g_mwh[3 * 4096 + (ks * 16 + ng * 4 + nt) * 32 + lane];
                mma16(acc[nt], a, b.x, b.y);
            }
        }
#pragma unroll
        for (int ks = 0; ks < 8; ++ks) {
            u32 a[4];
            ldA_h<SXH>(s_agH + (mrow + frow) * SXH + ks * 16 + 2 * fcol, a);
#pragma unroll
            for (int nt = 0; nt < 4; ++nt) {
                const uint2 b = g_mwh[4 * 4096 + (ks * 16 + ng * 4 + nt) * 32 + lane];
                mma16(acc[nt], a, b.x, b.y);
            }
        }
        __syncthreads();   // s_psH alias: all P2 reads long done; order writes after P3
        const int rA = mrow + frow;
#pragma unroll
        for (int nt = 0; nt < 4; ++nt) {
            const int gc = ng * 32 + nt * 8 + 2 * fcol;
            *(u32*)(s_uhH + rA * SXH + gc) =
                h2u(gelu_f(acc[nt].x), gelu_f(acc[nt].y));
            *(u32*)(s_uhH + (rA + 8) * SXH + gc) =
                h2u(gelu_f(acc[nt].z), gelu_f(acc[nt].w));
        }
    }
    __syncthreads();

    // P5: pre-LN = hmsg(fp32, from gmem) + UH @ uw2 + ub2 -> s_pl
    {
        float4 acc[4];
#pragma unroll
        for (int nt = 0; nt < 4; ++nt) {
            const int gc = ng * 32 + nt * 8 + 2 * fcol;
            acc[nt] = make_float4(ub2[gc], ub2[gc + 1], ub2[gc], ub2[gc + 1]);
        }
#pragma unroll
        for (int ks = 0; ks < 8; ++ks) {
            u32 a[4];
            ldA_h<SXH>(s_uhH + (mrow + frow) * SXH + ks * 16 + 2 * fcol, a);
#pragma unroll
            for (int nt = 0; nt < 4; ++nt) {
                const uint2 b = g_mwh[5 * 4096 + (ks * 16 + ng * 4 + nt) * 32 + lane];
                mma16(acc[nt], a, b.x, b.y);
            }
        }
        const int rA = mrow + frow;
#pragma unroll
        for (int nt = 0; nt < 4; ++nt) {
            const int gc = ng * 32 + nt * 8 + 2 * fcol;
            const float2 h0 = *(const float2*)(hin + (r0 + rA) * Dm + gc);
            const float2 h1 = *(const float2*)(hin + (r0 + rA + 8) * Dm + gc);
            *(float2*)(s_pl + rA * SXL + gc) =
                make_float2(h0.x + acc[nt].x, h0.y + acc[nt].y);
            *(float2*)(s_pl + (rA + 8) * SXL + gc) =
                make_float2(h1.x + acc[nt].z, h1.y + acc[nt].w);
        }
    }
    __syncthreads();

    // P6: LN per row (4 rows/warp). Non-final: -> hout. Final: fp16 -> s_hmtH[4+r]
#pragma unroll
    for (int rr = 0; rr < 4; ++rr) {
        const int r = wid * 4 + rr;
        const float4 v0 = *(const float4*)(s_pl + r * SXL + lane * 4);
        const float4 v = ln_f4(v0, lg, lb, lane);
        if (!last) {
            *(float4*)(hout + (r0 + r) * Dm + lane * 4) = v;
        } else {
            u32* dst = (u32*)(s_hmtH + (4 + r) * SXH) + lane * 2;
            dst[0] = h2u(v.x, v.y);
            dst[1] = h2u(v.z, v.w);
        }
    }

    // P7 (final round only): bc = hmsg_final @ bc_w + bc_b -> g_bcb
    if (last) {
        __syncthreads();
        float4 acc[4];
#pragma unroll
        for (int nt = 0; nt < 4; ++nt) {
            const int gc = ng * 32 + nt * 8 + 2 * fcol;
            acc[nt] = make_float4(bcb[gc], bcb[gc + 1], bcb[gc], bcb[gc + 1]);
        }
#pragma unroll
        for (int ks = 0; ks < 8; ++ks) {
            u32 a[4];
            ldA_h<SXH>(s_hmtH + (4 + mrow + frow) * SXH + ks * 16 + 2 * fcol, a);
#pragma unroll
            for (int nt = 0; nt < 4; ++nt) {
                const uint2 b = g_mwh[6 * 4096 + (ks * 16 + ng * 4 + nt) * 32 + lane];
                mma16(acc[nt], a, b.x, b.y);
            }
        }
        const int rA = r0 + mrow + frow;
#pragma unroll
        for (int nt = 0; nt < 4; ++nt) {
            const int gc = ng * 32 + nt * 8 + 2 * fcol;
            *(float2*)(g_bcb + rA * Dm + gc)       = make_float2(acc[nt].x, acc[nt].y);
            *(float2*)(g_bcb + (rA + 8) * Dm + gc) = make_float2(acc[nt].z, acc[nt].w);
        }
    }
}

// ============================================================
// K5: logits = LN(local + bc) @ head_w (fp16 MMA), 64 tok/block
// ============================================================
__global__ __launch_bounds__(256) void k_head(
    const float* __restrict__ lg, const float* __restrict__ lb,
    float* __restrict__ out)
{
    __shared__ __half s_x[64 * SXH];
    const int tid = threadIdx.x, wid = tid >> 5, lane = tid & 31;
    const int gt0 = blockIdx.x * 64;
    const int frow = lane >> 2, fcol = lane & 3;

#pragma unroll
    for (int tt = 0; tt < 8; ++tt) {
        const int tl = wid * 8 + tt, gt = gt0 + tl;
        const float4 lv = *(const float4*)(g_local + gt * Dm + lane * 4);
        const float4 bv = *(const float4*)(g_bcb + (gt >> 3) * Dm + lane * 4);
        const float4 h = make_float4(lv.x + bv.x, lv.y + bv.y, lv.z + bv.z, lv.w + bv.w);
        const float4 v = ln_f4(h, lg, lb, lane);
        u32* dst = (u32*)(s_x + tl * SXH) + lane * 2;
        dst[0] = h2u(v.x, v.y);
        dst[1] = h2u(v.z, v.w);
    }
    __syncthreads();

    const int mg = (wid >> 2) * 32;
    const int ng = (wid & 3);
    float4 acc[2][8];
#pragma unroll
    for (int mt = 0; mt < 2; ++mt)
#pragma unroll
        for (int nt = 0; nt < 8; ++nt) acc[mt][nt] = make_float4(0.f, 0.f, 0.f, 0.f);

#pragma unroll
    for (int ks = 0; ks < 8; ++ks) {
        u32 a[2][4];
#pragma unroll
        for (int mt = 0; mt < 2; ++mt)
            ldA_h<SXH>(s_x + (mg + mt * 16 + frow) * SXH + ks * 16 + 2 * fcol, a[mt]);
#pragma unroll
        for (int nt = 0; nt < 8; ++nt) {
            const uint2 b = g_hwh[(ks * 32 + ng * 8 + nt) * 32 + lane];
#pragma unroll
            for (int mt = 0; mt < 2; ++mt)
                mma16(acc[mt][nt], a[mt], b.x, b.y);
        }
    }

#pragma unroll
    for (int mt = 0; mt < 2; ++mt) {
        const int rg = gt0 + mg + mt * 16 + frow;
#pragma unroll
        for (int nt = 0; nt < 8; ++nt) {
            const int gc = ng * 64 + nt * 8 + 2 * fcol;
            *(float2*)(out + rg * Hm + gc)       = make_float2(acc[mt][nt].x, acc[mt][nt].y);
            *(float2*)(out + (rg + 8) * Hm + gc) = make_float2(acc[mt][nt].z, acc[mt][nt].w);
        }
    }
}

// ============================================================
extern "C" void kernel_launch(void* const* d_in, const int* in_sizes, int n_in,
                              void* d_out, int out_size) {
    const int*   x      = (const int*)  d_in[0];
    const float* emb    = (const float*)d_in[1];
    const float* pos    = (const float*)d_in[2];
    const float* lw1    = (const float*)d_in[3];
    const float* lb1    = (const float*)d_in[4];
    const float* lw2    = (const float*)d_in[5];
    const float* lb2    = (const float*)d_in[6];
    const float* lln_g  = (const float*)d_in[7];
    const float* lln_b  = (const float*)d_in[8];
    const float* pool_w = (const float*)d_in[9];
    const float* pool_b = (const float*)d_in[10];
    const float* msg_w1 = (const float*)d_in[11];
    const float* msg_b1 = (const float*)d_in[12];
    const float* msg_w2 = (const float*)d_in[13];
    const float* msg_b2 = (const float*)d_in[14];
    const float* upd_w1 = (const float*)d_in[15];
    const float* upd_b1 = (const float*)d_in[16];
    const float* upd_w2 = (const float*)d_in[17];
    const float* upd_b2 = (const float*)d_in[18];
    const float* mln_g  = (const float*)d_in[19];
    const float* mln_b  = (const float*)d_in[20];
    const float* bc_w   = (const float*)d_in[21];
    const float* bc_b   = (const float*)d_in[22];
    const float* fln_g  = (const float*)d_in[23];
    const float* fln_b  = (const float*)d_in[24];
    const float* head_w = (const float*)d_in[25];
    float* out = (float*)d_out;

    const int SMEM_LOCAL = (64 * SXH + 64 * SHH) * 2;         // 51200 B
    const int SMEM_MSG   = 136 * SXH * 2 + 32 * SXL * 4;      // 53888 B
    cudaFuncSetAttribute(k_local, cudaFuncAttributeMaxDynamicSharedMemorySize, SMEM_LOCAL);
    cudaFuncSetAttribute(k_msgf,  cudaFuncAttributeMaxDynamicSharedMemorySize, SMEM_MSG);

    k_pack_all<<<208, 256>>>(lw1, lw2, head_w, msg_w1, msg_w2, upd_w1, upd_w2, bc_w);

    k_local<<<NTOK / 64, 256, SMEM_LOCAL>>>(x, emb, pos, lb1, lb2,
                                            lln_g, lln_b, pool_w, pool_b);

    // rounds: A->B, B->A, A->(bc)  (last round writes g_bcb, skips hout)
    for (int r = 0; r < 3; ++r) {
        const int useA = (r % 2 == 0) ? 1 : 0;
        const int last = (r == 2) ? 1 : 0;
        k_msgf<<<ROWS / 32, 256, SMEM_MSG>>>(useA, last, msg_b1, msg_b2,
                                             upd_b1, upd_b2, mln_g, mln_b, bc_b);
    }

    k_head<<<NTOK / 64, 256>>>(fln_g, fln_b, out);
}